// round 1
// baseline (speedup 1.0000x reference)
#include <cuda_runtime.h>
#include <math.h>

#define TOK   4096   // B*S tokens
#define DM    1024
#define HID   4096
#define SEQL  2048
#define NB    2
#define NH    16
#define DH    64

// ---------------- scratch (allocation-free: __device__ globals) ----------------
__device__ float g_xn[TOK * DM];      // layernorm output
__device__ float g_q[TOK * DM];
__device__ float g_k[TOK * DM];
__device__ float g_v[TOK * DM];
__device__ float g_attn[TOK * DM];
__device__ float g_x1[TOK * DM];      // residual after attention
__device__ float g_hid[TOK * HID];    // FFN hidden

// ---------------- LayerNorm: one block per token, 128 threads ----------------
__global__ void ln_kernel(const float* __restrict__ x,
                          const float* __restrict__ gamma,
                          const float* __restrict__ beta,
                          float* __restrict__ out)
{
    int t   = blockIdx.x;
    int tid = threadIdx.x;
    const float4* xr = (const float4*)(x + (size_t)t * DM);
    float4 v0 = xr[tid];
    float4 v1 = xr[tid + 128];
    float s  = v0.x + v0.y + v0.z + v0.w + v1.x + v1.y + v1.z + v1.w;
    float ss = v0.x*v0.x + v0.y*v0.y + v0.z*v0.z + v0.w*v0.w
             + v1.x*v1.x + v1.y*v1.y + v1.z*v1.z + v1.w*v1.w;
    #pragma unroll
    for (int o = 16; o; o >>= 1) {
        s  += __shfl_xor_sync(0xffffffffu, s,  o);
        ss += __shfl_xor_sync(0xffffffffu, ss, o);
    }
    __shared__ float sm_s[4], sm_ss[4];
    int w = tid >> 5, ln = tid & 31;
    if (ln == 0) { sm_s[w] = s; sm_ss[w] = ss; }
    __syncthreads();
    s  = sm_s[0] + sm_s[1] + sm_s[2] + sm_s[3];
    ss = sm_ss[0] + sm_ss[1] + sm_ss[2] + sm_ss[3];
    float mu   = s * (1.0f / DM);
    float var  = ss * (1.0f / DM) - mu * mu;
    float rstd = rsqrtf(var + 1e-5f);

    const float4* gr = (const float4*)gamma;
    const float4* br = (const float4*)beta;
    float4* o4 = (float4*)(out + (size_t)t * DM);
    #pragma unroll
    for (int u = 0; u < 2; u++) {
        int i = tid + u * 128;
        float4 xv = xr[i], gv = gr[i], bv = br[i];
        float4 r;
        r.x = (xv.x - mu) * rstd * gv.x + bv.x;
        r.y = (xv.y - mu) * rstd * gv.y + bv.y;
        r.z = (xv.z - mu) * rstd * gv.z + bv.z;
        r.w = (xv.w - mu) * rstd * gv.w + bv.w;
        o4[i] = r;
    }
}

// ---------------- SGEMM: C[M,N] = A[M,K] @ B[K,N] (+bias, +relu, +residual) ----
// 128x128x8 block tile, 256 threads, 8x8 per thread.
template<bool BIAS, bool RELU, bool RES>
__global__ void __launch_bounds__(256, 2) sgemm_kernel(
    const float* __restrict__ A, const float* __restrict__ Bw,
    const float* __restrict__ bias, const float* __restrict__ Res,
    float* __restrict__ C, int M, int N, int K)
{
    __shared__ float As[8][132];   // padded: conflict-free transposed stores
    __shared__ float Bs[8][128];

    int tid = threadIdx.x;
    int tx  = tid & 15, ty = tid >> 4;
    int m0  = blockIdx.y * 128, n0 = blockIdx.x * 128;

    float acc[8][8];
    #pragma unroll
    for (int i = 0; i < 8; i++)
        #pragma unroll
        for (int j = 0; j < 8; j++) acc[i][j] = 0.f;

    int arow = tid >> 1, ak = (tid & 1) * 4;
    int brow = tid >> 5, bcol = (tid & 31) * 4;
    const float* Aptr = A + (size_t)(m0 + arow) * K + ak;
    const float* Bptr = Bw + (size_t)brow * N + n0 + bcol;

    for (int kt = 0; kt < K; kt += 8) {
        float4 av = *(const float4*)(Aptr + kt);
        float4 bv = *(const float4*)(Bptr + (size_t)kt * N);
        As[ak + 0][arow] = av.x;
        As[ak + 1][arow] = av.y;
        As[ak + 2][arow] = av.z;
        As[ak + 3][arow] = av.w;
        *(float4*)&Bs[brow][bcol] = bv;
        __syncthreads();
        #pragma unroll
        for (int k = 0; k < 8; k++) {
            float4 a0 = *(const float4*)&As[k][ty * 4];
            float4 a1 = *(const float4*)&As[k][64 + ty * 4];
            float4 b0 = *(const float4*)&Bs[k][tx * 4];
            float4 b1 = *(const float4*)&Bs[k][64 + tx * 4];
            float a[8] = {a0.x, a0.y, a0.z, a0.w, a1.x, a1.y, a1.z, a1.w};
            float b[8] = {b0.x, b0.y, b0.z, b0.w, b1.x, b1.y, b1.z, b1.w};
            #pragma unroll
            for (int i = 0; i < 8; i++)
                #pragma unroll
                for (int j = 0; j < 8; j++)
                    acc[i][j] += a[i] * b[j];
        }
        __syncthreads();
    }

    #pragma unroll
    for (int i = 0; i < 8; i++) {
        int m = m0 + (i < 4 ? ty * 4 + i : 64 + ty * 4 + (i - 4));
        float* crow = C + (size_t)m * N;
        #pragma unroll
        for (int jh = 0; jh < 2; jh++) {
            int n = n0 + jh * 64 + tx * 4;
            float4 r;
            r.x = acc[i][jh * 4 + 0];
            r.y = acc[i][jh * 4 + 1];
            r.z = acc[i][jh * 4 + 2];
            r.w = acc[i][jh * 4 + 3];
            if (BIAS) {
                float4 bb = *(const float4*)(bias + n);
                r.x += bb.x; r.y += bb.y; r.z += bb.z; r.w += bb.w;
            }
            if (RELU) {
                r.x = fmaxf(r.x, 0.f); r.y = fmaxf(r.y, 0.f);
                r.z = fmaxf(r.z, 0.f); r.w = fmaxf(r.w, 0.f);
            }
            if (RES) {
                float4 rr = *(const float4*)(Res + (size_t)m * N + n);
                r.x += rr.x; r.y += rr.y; r.z += rr.z; r.w += rr.w;
            }
            *(float4*)(crow + n) = r;
        }
    }
}

// ---------------- Flash attention (fp32, causal, online softmax) ---------------
// Block = (q-tile of 64 rows) x (head) x (batch). 256 threads:
// thread t handles query row r = t/4, owning 16 of the 64 output dims (qtr = t%3..).
__global__ void __launch_bounds__(256, 2) attn_kernel(
    const float* __restrict__ Q, const float* __restrict__ K,
    const float* __restrict__ V, float* __restrict__ O)
{
    __shared__ float Qs[64][68];
    __shared__ float KVs[64][68];   // holds K during scores, V during accumulate

    int qt = blockIdx.x, h = blockIdx.y, b = blockIdx.z;
    int tid  = threadIdx.x;
    int r    = tid >> 2;      // query row within tile (0..63)
    int qtr  = tid & 3;       // which 16-dim quarter this thread owns
    int lane = tid & 31;

    // Load Q tile (each thread: 16 contiguous floats of one row)
    {
        const float* qbase = Q + (size_t)(b * SEQL + qt * 64 + r) * DM + h * DH + qtr * 16;
        #pragma unroll
        for (int u = 0; u < 4; u++)
            *(float4*)&Qs[r][qtr * 16 + u * 4] = *(const float4*)(qbase + u * 4);
    }

    float acc[16];
    #pragma unroll
    for (int u = 0; u < 16; u++) acc[u] = 0.f;
    float m_prev = -INFINITY, l = 0.f;
    int sq = qt * 64 + r;           // global query index within sequence
    int ntiles = qt + 1;            // causal: only key tiles <= query tile

    for (int t = 0; t < ntiles; t++) {
        __syncthreads();  // prev accumulate done reading KVs (also orders Qs on t=0)
        // Load K tile
        {
            const float* kbase = K + (size_t)(b * SEQL + t * 64 + r) * DM + h * DH + qtr * 16;
            #pragma unroll
            for (int u = 0; u < 4; u++)
                *(float4*)&KVs[r][qtr * 16 + u * 4] = *(const float4*)(kbase + u * 4);
        }
        __syncthreads();

        // Scores: this thread computes 16 of the 64 scores for its row
        float p[16];
        float mt = -INFINITY;
        #pragma unroll
        for (int jj = 0; jj < 16; jj++) {
            int j = qtr * 16 + jj;
            float s = 0.f;
            #pragma unroll
            for (int d4 = 0; d4 < 16; d4++) {
                float4 qv = *(const float4*)&Qs[r][d4 * 4];
                float4 kv = *(const float4*)&KVs[j][d4 * 4];
                s += qv.x * kv.x + qv.y * kv.y + qv.z * kv.z + qv.w * kv.w;
            }
            s *= 0.125f;                               // 1/sqrt(64)
            if (t * 64 + j > sq) s = -INFINITY;        // causal mask
            p[jj] = s;
            mt = fmaxf(mt, s);
        }
        // Row max / sum across the 4 lanes of this row
        mt = fmaxf(mt, __shfl_xor_sync(0xffffffffu, mt, 1));
        mt = fmaxf(mt, __shfl_xor_sync(0xffffffffu, mt, 2));
        float m_new = fmaxf(m_prev, mt);
        float scale = __expf(m_prev - m_new);
        float lt = 0.f;
        #pragma unroll
        for (int jj = 0; jj < 16; jj++) {
            p[jj] = __expf(p[jj] - m_new);
            lt += p[jj];
        }
        lt += __shfl_xor_sync(0xffffffffu, lt, 1);
        lt += __shfl_xor_sync(0xffffffffu, lt, 2);
        l = l * scale + lt;
        #pragma unroll
        for (int u = 0; u < 16; u++) acc[u] *= scale;
        m_prev = m_new;

        __syncthreads();  // score reads of K done
        // Load V tile into same buffer
        {
            const float* vbase = V + (size_t)(b * SEQL + t * 64 + r) * DM + h * DH + qtr * 16;
            #pragma unroll
            for (int u = 0; u < 4; u++)
                *(float4*)&KVs[r][qtr * 16 + u * 4] = *(const float4*)(vbase + u * 4);
        }
        __syncthreads();

        // Accumulate: p_j broadcast within the 4-lane row group via shfl
        #pragma unroll
        for (int j = 0; j < 64; j++) {
            float pj = __shfl_sync(0xffffffffu, p[j & 15], (lane & ~3) | (j >> 4));
            #pragma unroll
            for (int d4 = 0; d4 < 4; d4++) {
                float4 vv = *(const float4*)&KVs[j][qtr * 16 + d4 * 4];
                acc[d4 * 4 + 0] += pj * vv.x;
                acc[d4 * 4 + 1] += pj * vv.y;
                acc[d4 * 4 + 2] += pj * vv.z;
                acc[d4 * 4 + 3] += pj * vv.w;
            }
        }
    }

    float inv = 1.0f / l;
    float* ob = O + (size_t)(b * SEQL + sq) * DM + h * DH + qtr * 16;
    #pragma unroll
    for (int d4 = 0; d4 < 4; d4++) {
        float4 r4;
        r4.x = acc[d4 * 4 + 0] * inv;
        r4.y = acc[d4 * 4 + 1] * inv;
        r4.z = acc[d4 * 4 + 2] * inv;
        r4.w = acc[d4 * 4 + 3] * inv;
        *(float4*)(ob + d4 * 4) = r4;
    }
}

// ---------------- launch ----------------
extern "C" void kernel_launch(void* const* d_in, const int* in_sizes, int n_in,
                              void* d_out, int out_size)
{
    const float* x   = (const float*)d_in[0];
    const float* wq  = (const float*)d_in[1];
    const float* wk  = (const float*)d_in[2];
    const float* wv  = (const float*)d_in[3];
    const float* wo  = (const float*)d_in[4];
    const float* w1  = (const float*)d_in[5];
    const float* b1  = (const float*)d_in[6];
    const float* w2  = (const float*)d_in[7];
    const float* b2  = (const float*)d_in[8];
    const float* g1  = (const float*)d_in[9];
    const float* be1 = (const float*)d_in[10];
    const float* g2  = (const float*)d_in[11];
    const float* be2 = (const float*)d_in[12];
    float* out = (float*)d_out;

    float *xn, *q, *k, *v, *attn, *x1, *hid;
    cudaGetSymbolAddress((void**)&xn,   g_xn);
    cudaGetSymbolAddress((void**)&q,    g_q);
    cudaGetSymbolAddress((void**)&k,    g_k);
    cudaGetSymbolAddress((void**)&v,    g_v);
    cudaGetSymbolAddress((void**)&attn, g_attn);
    cudaGetSymbolAddress((void**)&x1,   g_x1);
    cudaGetSymbolAddress((void**)&hid,  g_hid);

    // LN1
    ln_kernel<<<TOK, 128>>>(x, g1, be1, xn);
    // QKV projections (M=4096, N=1024, K=1024)
    dim3 gqkv(DM / 128, TOK / 128);
    sgemm_kernel<false, false, false><<<gqkv, 256>>>(xn, wq, nullptr, nullptr, q, TOK, DM, DM);
    sgemm_kernel<false, false, false><<<gqkv, 256>>>(xn, wk, nullptr, nullptr, k, TOK, DM, DM);
    sgemm_kernel<false, false, false><<<gqkv, 256>>>(xn, wv, nullptr, nullptr, v, TOK, DM, DM);
    // Attention
    attn_kernel<<<dim3(SEQL / 64, NH, NB), 256>>>(q, k, v, attn);
    // O projection + residual(x) -> x1
    sgemm_kernel<false, false, true><<<gqkv, 256>>>(attn, wo, nullptr, x, x1, TOK, DM, DM);
    // LN2
    ln_kernel<<<TOK, 128>>>(x1, g2, be2, xn);
    // FFN1: relu(xn @ w1 + b1) -> hid  (M=4096, N=4096, K=1024)
    sgemm_kernel<true, true, false><<<dim3(HID / 128, TOK / 128), 256>>>(xn, w1, b1, nullptr, hid, TOK, HID, DM);
    // FFN2: hid @ w2 + b2 + x1 -> out  (M=4096, N=1024, K=4096)
    sgemm_kernel<true, false, true><<<gqkv, 256>>>(hid, w2, b2, x1, out, TOK, DM, HID);
}

// round 2
// speedup vs baseline: 2.9687x; 2.9687x over previous
#include <cuda_runtime.h>
#include <math.h>

#define TOK   4096   // B*S tokens
#define DM    1024
#define HID   4096
#define SEQL  2048
#define NB    2
#define NH    16
#define DH    64

// ---------------- scratch (allocation-free: __device__ globals) ----------------
__device__ float g_xn[TOK * DM];      // layernorm output
__device__ float g_q[TOK * DM];
__device__ float g_k[TOK * DM];
__device__ float g_v[TOK * DM];
__device__ float g_attn[TOK * DM];
__device__ float g_x1[TOK * DM];      // residual after attention
__device__ float g_hid[TOK * HID];    // FFN hidden

// ---------------- LayerNorm: one block per token, 128 threads ----------------
__global__ void ln_kernel(const float* __restrict__ x,
                          const float* __restrict__ gamma,
                          const float* __restrict__ beta,
                          float* __restrict__ out)
{
    int t   = blockIdx.x;
    int tid = threadIdx.x;
    const float4* xr = (const float4*)(x + (size_t)t * DM);
    float4 v0 = xr[tid];
    float4 v1 = xr[tid + 128];
    float s  = v0.x + v0.y + v0.z + v0.w + v1.x + v1.y + v1.z + v1.w;
    float ss = v0.x*v0.x + v0.y*v0.y + v0.z*v0.z + v0.w*v0.w
             + v1.x*v1.x + v1.y*v1.y + v1.z*v1.z + v1.w*v1.w;
    #pragma unroll
    for (int o = 16; o; o >>= 1) {
        s  += __shfl_xor_sync(0xffffffffu, s,  o);
        ss += __shfl_xor_sync(0xffffffffu, ss, o);
    }
    __shared__ float sm_s[4], sm_ss[4];
    int w = tid >> 5, ln = tid & 31;
    if (ln == 0) { sm_s[w] = s; sm_ss[w] = ss; }
    __syncthreads();
    s  = sm_s[0] + sm_s[1] + sm_s[2] + sm_s[3];
    ss = sm_ss[0] + sm_ss[1] + sm_ss[2] + sm_ss[3];
    float mu   = s * (1.0f / DM);
    float var  = ss * (1.0f / DM) - mu * mu;
    float rstd = rsqrtf(var + 1e-5f);

    const float4* gr = (const float4*)gamma;
    const float4* br = (const float4*)beta;
    float4* o4 = (float4*)(out + (size_t)t * DM);
    #pragma unroll
    for (int u = 0; u < 2; u++) {
        int i = tid + u * 128;
        float4 xv = xr[i], gv = gr[i], bv = br[i];
        float4 r;
        r.x = (xv.x - mu) * rstd * gv.x + bv.x;
        r.y = (xv.y - mu) * rstd * gv.y + bv.y;
        r.z = (xv.z - mu) * rstd * gv.z + bv.z;
        r.w = (xv.w - mu) * rstd * gv.w + bv.w;
        o4[i] = r;
    }
}

// ---------------- SGEMM: C[M,N] = A[M,K] @ B[K,N] (+bias, +relu, +residual) ----
// 128x128x16 block tile, 256 threads, 8x8 per thread, double-buffered smem.
template<bool BIAS, bool RELU, bool RES>
__global__ void __launch_bounds__(256, 2) sgemm_kernel(
    const float* __restrict__ A, const float* __restrict__ Bw,
    const float* __restrict__ bias, const float* __restrict__ Res,
    float* __restrict__ C, int M, int N, int K)
{
    __shared__ float As[2][16][132];   // transposed [k][m], padded
    __shared__ float Bs[2][16][128];

    int tid = threadIdx.x;
    int tx  = tid & 15, ty = tid >> 4;
    int m0  = blockIdx.y * 128, n0 = blockIdx.x * 128;

    float acc[8][8];
    #pragma unroll
    for (int i = 0; i < 8; i++)
        #pragma unroll
        for (int j = 0; j < 8; j++) acc[i][j] = 0.f;

    // A: thread loads 8 floats of row (m0+arow), cols acol..acol+7 of the slice
    int arow = tid & 127, acol = (tid >> 7) * 8;
    // B: thread loads 8 floats of slice row brow, cols bcol..bcol+7
    int brow = tid >> 4, bcol = (tid & 15) * 8;
    const float* Aptr = A + (size_t)(m0 + arow) * K + acol;
    const float* Bptr = Bw + (size_t)brow * N + n0 + bcol;

    int nk = K >> 4;
    float4 pa0, pa1, pb0, pb1;

    // prologue: slice 0
    pa0 = *(const float4*)(Aptr);
    pa1 = *(const float4*)(Aptr + 4);
    pb0 = *(const float4*)(Bptr);
    pb1 = *(const float4*)(Bptr + 4);
    As[0][acol + 0][arow] = pa0.x;
    As[0][acol + 1][arow] = pa0.y;
    As[0][acol + 2][arow] = pa0.z;
    As[0][acol + 3][arow] = pa0.w;
    As[0][acol + 4][arow] = pa1.x;
    As[0][acol + 5][arow] = pa1.y;
    As[0][acol + 6][arow] = pa1.z;
    As[0][acol + 7][arow] = pa1.w;
    *(float4*)&Bs[0][brow][bcol]     = pb0;
    *(float4*)&Bs[0][brow][bcol + 4] = pb1;
    __syncthreads();

    for (int kt = 0; kt < nk; kt++) {
        int cur = kt & 1;
        bool more = (kt + 1 < nk);
        if (more) {
            const float* ap = Aptr + (kt + 1) * 16;
            const float* bp = Bptr + (size_t)(kt + 1) * 16 * N;
            pa0 = *(const float4*)(ap);
            pa1 = *(const float4*)(ap + 4);
            pb0 = *(const float4*)(bp);
            pb1 = *(const float4*)(bp + 4);
        }
        #pragma unroll
        for (int k = 0; k < 16; k++) {
            float4 a0 = *(const float4*)&As[cur][k][ty * 4];
            float4 a1 = *(const float4*)&As[cur][k][64 + ty * 4];
            float4 b0 = *(const float4*)&Bs[cur][k][tx * 4];
            float4 b1 = *(const float4*)&Bs[cur][k][64 + tx * 4];
            float a[8] = {a0.x, a0.y, a0.z, a0.w, a1.x, a1.y, a1.z, a1.w};
            float b[8] = {b0.x, b0.y, b0.z, b0.w, b1.x, b1.y, b1.z, b1.w};
            #pragma unroll
            for (int i = 0; i < 8; i++)
                #pragma unroll
                for (int j = 0; j < 8; j++)
                    acc[i][j] += a[i] * b[j];
        }
        if (more) {
            int nxt = cur ^ 1;
            As[nxt][acol + 0][arow] = pa0.x;
            As[nxt][acol + 1][arow] = pa0.y;
            As[nxt][acol + 2][arow] = pa0.z;
            As[nxt][acol + 3][arow] = pa0.w;
            As[nxt][acol + 4][arow] = pa1.x;
            As[nxt][acol + 5][arow] = pa1.y;
            As[nxt][acol + 6][arow] = pa1.z;
            As[nxt][acol + 7][arow] = pa1.w;
            *(float4*)&Bs[nxt][brow][bcol]     = pb0;
            *(float4*)&Bs[nxt][brow][bcol + 4] = pb1;
            __syncthreads();
        }
    }

    #pragma unroll
    for (int i = 0; i < 8; i++) {
        int m = m0 + (i < 4 ? ty * 4 + i : 64 + ty * 4 + (i - 4));
        float* crow = C + (size_t)m * N;
        #pragma unroll
        for (int jh = 0; jh < 2; jh++) {
            int n = n0 + jh * 64 + tx * 4;
            float4 r;
            r.x = acc[i][jh * 4 + 0];
            r.y = acc[i][jh * 4 + 1];
            r.z = acc[i][jh * 4 + 2];
            r.w = acc[i][jh * 4 + 3];
            if (BIAS) {
                float4 bb = *(const float4*)(bias + n);
                r.x += bb.x; r.y += bb.y; r.z += bb.z; r.w += bb.w;
            }
            if (RELU) {
                r.x = fmaxf(r.x, 0.f); r.y = fmaxf(r.y, 0.f);
                r.z = fmaxf(r.z, 0.f); r.w = fmaxf(r.w, 0.f);
            }
            if (RES) {
                float4 rr = *(const float4*)(Res + (size_t)m * N + n);
                r.x += rr.x; r.y += rr.y; r.z += rr.z; r.w += rr.w;
            }
            *(float4*)(crow + n) = r;
        }
    }
}

// ---------------- Flash attention (fp32, causal, online softmax) ---------------
// Register-blocked: 64 queries x 64 keys per tile, 256 threads as 16x16 grid,
// each thread owns a 4x4 score tile and a 4(rows)x4(dims) output tile.
#define APAD 68
#define ATILE (64 * APAD)

__global__ void __launch_bounds__(256, 2) attn_kernel(
    const float* __restrict__ Q, const float* __restrict__ K,
    const float* __restrict__ V, float* __restrict__ O)
{
    extern __shared__ float sm[];
    float* Qs = sm;                 // [64][APAD]
    float* Ks = sm + ATILE;
    float* Vs = sm + 2 * ATILE;
    float* Ps = sm + 3 * ATILE;

    int qt = (int)gridDim.x - 1 - (int)blockIdx.x;   // heavy tiles first
    int h = blockIdx.y, b = blockIdx.z;
    int tid = threadIdx.x;
    int tx = tid & 15, ty = tid >> 4;

    // tile loaders: row lr (0..63), quarter lq -> 16 contiguous floats
    int lr = tid >> 2, lq = tid & 3;

    // Load Q tile
    {
        const float* qb = Q + (size_t)(b * SEQL + qt * 64 + lr) * DM + h * DH + lq * 16;
        #pragma unroll
        for (int u = 0; u < 4; u++)
            *(float4*)&Qs[lr * APAD + lq * 16 + u * 4] = *(const float4*)(qb + u * 4);
    }

    float m_prev[4], l[4], acc[4][4];
    #pragma unroll
    for (int i = 0; i < 4; i++) {
        m_prev[i] = -INFINITY; l[i] = 0.f;
        #pragma unroll
        for (int j = 0; j < 4; j++) acc[i][j] = 0.f;
    }

    for (int t = 0; t <= qt; t++) {
        __syncthreads();   // prev PV done reading Vs/Ps (and orders Qs on t=0)
        {
            const float* kb = K + (size_t)(b * SEQL + t * 64 + lr) * DM + h * DH + lq * 16;
            const float* vb = V + (size_t)(b * SEQL + t * 64 + lr) * DM + h * DH + lq * 16;
            #pragma unroll
            for (int u = 0; u < 4; u++) {
                *(float4*)&Ks[lr * APAD + lq * 16 + u * 4] = *(const float4*)(kb + u * 4);
                *(float4*)&Vs[lr * APAD + lq * 16 + u * 4] = *(const float4*)(vb + u * 4);
            }
        }
        __syncthreads();

        // scores S = Q @ K^T (contraction over d, both natural layout)
        float s[4][4];
        #pragma unroll
        for (int i = 0; i < 4; i++)
            #pragma unroll
            for (int j = 0; j < 4; j++) s[i][j] = 0.f;

        #pragma unroll
        for (int d4 = 0; d4 < 16; d4++) {
            float4 a[4], bf[4];
            #pragma unroll
            for (int i = 0; i < 4; i++)
                a[i] = *(const float4*)&Qs[(ty * 4 + i) * APAD + d4 * 4];
            #pragma unroll
            for (int j = 0; j < 4; j++)
                bf[j] = *(const float4*)&Ks[(tx * 4 + j) * APAD + d4 * 4];
            #pragma unroll
            for (int i = 0; i < 4; i++)
                #pragma unroll
                for (int j = 0; j < 4; j++)
                    s[i][j] += a[i].x * bf[j].x + a[i].y * bf[j].y
                             + a[i].z * bf[j].z + a[i].w * bf[j].w;
        }

        bool diag = (t == qt);
        #pragma unroll
        for (int i = 0; i < 4; i++)
            #pragma unroll
            for (int j = 0; j < 4; j++) {
                s[i][j] *= 0.125f;
                if (diag && (tx * 4 + j) > (ty * 4 + i)) s[i][j] = -INFINITY;
            }

        // online softmax per row (reduce across the 16 tx-lanes sharing the row)
        #pragma unroll
        for (int i = 0; i < 4; i++) {
            float mt = fmaxf(fmaxf(s[i][0], s[i][1]), fmaxf(s[i][2], s[i][3]));
            mt = fmaxf(mt, __shfl_xor_sync(0xffffffffu, mt, 1));
            mt = fmaxf(mt, __shfl_xor_sync(0xffffffffu, mt, 2));
            mt = fmaxf(mt, __shfl_xor_sync(0xffffffffu, mt, 4));
            mt = fmaxf(mt, __shfl_xor_sync(0xffffffffu, mt, 8));
            float m_new = fmaxf(m_prev[i], mt);
            float sc = __expf(m_prev[i] - m_new);
            float p0 = __expf(s[i][0] - m_new);
            float p1 = __expf(s[i][1] - m_new);
            float p2 = __expf(s[i][2] - m_new);
            float p3 = __expf(s[i][3] - m_new);
            s[i][0] = p0; s[i][1] = p1; s[i][2] = p2; s[i][3] = p3;
            float lt = p0 + p1 + p2 + p3;
            lt += __shfl_xor_sync(0xffffffffu, lt, 1);
            lt += __shfl_xor_sync(0xffffffffu, lt, 2);
            lt += __shfl_xor_sync(0xffffffffu, lt, 4);
            lt += __shfl_xor_sync(0xffffffffu, lt, 8);
            l[i] = l[i] * sc + lt;
            m_prev[i] = m_new;
            #pragma unroll
            for (int j = 0; j < 4; j++) acc[i][j] *= sc;
        }

        // store P tile (natural layout, vectorized)
        #pragma unroll
        for (int i = 0; i < 4; i++)
            *(float4*)&Ps[(ty * 4 + i) * APAD + tx * 4] =
                make_float4(s[i][0], s[i][1], s[i][2], s[i][3]);
        __syncthreads();

        // O += P @ V (contraction over keys c, both natural layout)
        #pragma unroll
        for (int c4 = 0; c4 < 16; c4++) {
            float4 pa[4], vr[4];
            #pragma unroll
            for (int i = 0; i < 4; i++)
                pa[i] = *(const float4*)&Ps[(ty * 4 + i) * APAD + c4 * 4];
            #pragma unroll
            for (int cc = 0; cc < 4; cc++)
                vr[cc] = *(const float4*)&Vs[(c4 * 4 + cc) * APAD + tx * 4];
            #pragma unroll
            for (int i = 0; i < 4; i++) {
                acc[i][0] += pa[i].x * vr[0].x + pa[i].y * vr[1].x + pa[i].z * vr[2].x + pa[i].w * vr[3].x;
                acc[i][1] += pa[i].x * vr[0].y + pa[i].y * vr[1].y + pa[i].z * vr[2].y + pa[i].w * vr[3].y;
                acc[i][2] += pa[i].x * vr[0].z + pa[i].y * vr[1].z + pa[i].z * vr[2].z + pa[i].w * vr[3].z;
                acc[i][3] += pa[i].x * vr[0].w + pa[i].y * vr[1].w + pa[i].z * vr[2].w + pa[i].w * vr[3].w;
            }
        }
    }

    #pragma unroll
    for (int i = 0; i < 4; i++) {
        float inv = 1.0f / l[i];
        int row = qt * 64 + ty * 4 + i;
        float* ob = O + (size_t)(b * SEQL + row) * DM + h * DH + tx * 4;
        *(float4*)ob = make_float4(acc[i][0] * inv, acc[i][1] * inv,
                                   acc[i][2] * inv, acc[i][3] * inv);
    }
}

// ---------------- launch ----------------
extern "C" void kernel_launch(void* const* d_in, const int* in_sizes, int n_in,
                              void* d_out, int out_size)
{
    const float* x   = (const float*)d_in[0];
    const float* wq  = (const float*)d_in[1];
    const float* wk  = (const float*)d_in[2];
    const float* wv  = (const float*)d_in[3];
    const float* wo  = (const float*)d_in[4];
    const float* w1  = (const float*)d_in[5];
    const float* b1  = (const float*)d_in[6];
    const float* w2  = (const float*)d_in[7];
    const float* b2  = (const float*)d_in[8];
    const float* g1  = (const float*)d_in[9];
    const float* be1 = (const float*)d_in[10];
    const float* g2  = (const float*)d_in[11];
    const float* be2 = (const float*)d_in[12];
    float* out = (float*)d_out;

    float *xn, *q, *k, *v, *attn, *x1, *hid;
    cudaGetSymbolAddress((void**)&xn,   g_xn);
    cudaGetSymbolAddress((void**)&q,    g_q);
    cudaGetSymbolAddress((void**)&k,    g_k);
    cudaGetSymbolAddress((void**)&v,    g_v);
    cudaGetSymbolAddress((void**)&attn, g_attn);
    cudaGetSymbolAddress((void**)&x1,   g_x1);
    cudaGetSymbolAddress((void**)&hid,  g_hid);

    static bool attr_done = false;
    if (!attr_done) {
        cudaFuncSetAttribute(attn_kernel, cudaFuncAttributeMaxDynamicSharedMemorySize,
                             4 * ATILE * sizeof(float));
        attr_done = true;
    }

    // LN1
    ln_kernel<<<TOK, 128>>>(x, g1, be1, xn);
    // QKV projections (M=4096, N=1024, K=1024)
    dim3 gqkv(DM / 128, TOK / 128);
    sgemm_kernel<false, false, false><<<gqkv, 256>>>(xn, wq, nullptr, nullptr, q, TOK, DM, DM);
    sgemm_kernel<false, false, false><<<gqkv, 256>>>(xn, wk, nullptr, nullptr, k, TOK, DM, DM);
    sgemm_kernel<false, false, false><<<gqkv, 256>>>(xn, wv, nullptr, nullptr, v, TOK, DM, DM);
    // Attention
    attn_kernel<<<dim3(SEQL / 64, NH, NB), 256, 4 * ATILE * sizeof(float)>>>(q, k, v, attn);
    // O projection + residual(x) -> x1
    sgemm_kernel<false, false, true><<<gqkv, 256>>>(attn, wo, nullptr, x, x1, TOK, DM, DM);
    // LN2
    ln_kernel<<<TOK, 128>>>(x1, g2, be2, xn);
    // FFN1: relu(xn @ w1 + b1) -> hid  (M=4096, N=4096, K=1024)
    sgemm_kernel<true, true, false><<<dim3(HID / 128, TOK / 128), 256>>>(xn, w1, b1, nullptr, hid, TOK, HID, DM);
    // FFN2: hid @ w2 + b2 + x1 -> out  (M=4096, N=1024, K=4096)
    sgemm_kernel<true, false, true><<<gqkv, 256>>>(hid, w2, b2, x1, out, TOK, DM, HID);
}

// round 4
// speedup vs baseline: 4.7397x; 1.5966x over previous
#include <cuda_runtime.h>
#include <cuda_bf16.h>
#include <math.h>
#include <stdint.h>

#define TOK   4096   // B*S tokens
#define DM    1024
#define HID   4096
#define SEQL  2048
#define NB    2
#define NH    16
#define DH    64

// ---------------- scratch (allocation-free: __device__ globals) ----------------
__device__ float g_xn[TOK * DM];
__device__ float g_q[TOK * DM];
__device__ float g_k[TOK * DM];
__device__ float g_v[TOK * DM];
__device__ float g_attn[TOK * DM];
__device__ float g_x1[TOK * DM];
__device__ float g_hid[TOK * HID];

// bf16 hi/lo split scratch
__device__ __align__(256) __nv_bfloat16 g_act_h[TOK * DM];
__device__ __align__(256) __nv_bfloat16 g_act_l[TOK * DM];
__device__ __align__(256) __nv_bfloat16 g_hid_h[TOK * HID];
__device__ __align__(256) __nv_bfloat16 g_hid_l[TOK * HID];
// weights transposed to [N,K] bf16 hi/lo
__device__ __align__(256) __nv_bfloat16 g_wq_h[DM * DM], g_wq_l[DM * DM];
__device__ __align__(256) __nv_bfloat16 g_wk_h[DM * DM], g_wk_l[DM * DM];
__device__ __align__(256) __nv_bfloat16 g_wv_h[DM * DM], g_wv_l[DM * DM];
__device__ __align__(256) __nv_bfloat16 g_wo_h[DM * DM], g_wo_l[DM * DM];
__device__ __align__(256) __nv_bfloat16 g_w1_h[DM * HID], g_w1_l[DM * HID];
__device__ __align__(256) __nv_bfloat16 g_w2_h[HID * DM], g_w2_l[HID * DM];

// ---------------- base-target PTX helpers (no sm_103a-only features!) ---------
__device__ __forceinline__ uint32_t smem_u32(const void* p) {
    uint32_t a;
    asm("{ .reg .u64 t; cvta.to.shared.u64 t, %1; cvt.u32.u64 %0, t; }"
        : "=r"(a) : "l"(p));
    return a;
}
__device__ __forceinline__ void cpa16(uint32_t s, const void* g) {
    asm volatile("cp.async.cg.shared.global [%0], [%1], 16;" :: "r"(s), "l"(g));
}
#define CP_COMMIT() asm volatile("cp.async.commit_group;" ::: "memory")
#define CP_WAIT(n)  asm volatile("cp.async.wait_group %0;" :: "n"(n) : "memory")

__device__ __forceinline__ void ldm_x4(uint32_t* r, uint32_t addr) {
    asm volatile("ldmatrix.sync.aligned.m8n8.x4.shared.b16 {%0,%1,%2,%3}, [%4];"
                 : "=r"(r[0]), "=r"(r[1]), "=r"(r[2]), "=r"(r[3]) : "r"(addr));
}
__device__ __forceinline__ void mma_bf16(float* d, const uint32_t* a, const uint32_t* b) {
    asm volatile(
        "mma.sync.aligned.m16n8k16.row.col.f32.bf16.bf16.f32 "
        "{%0,%1,%2,%3}, {%4,%5,%6,%7}, {%8,%9}, {%0,%1,%2,%3};"
        : "+f"(d[0]), "+f"(d[1]), "+f"(d[2]), "+f"(d[3])
        : "r"(a[0]), "r"(a[1]), "r"(a[2]), "r"(a[3]), "r"(b[0]), "r"(b[1]));
}

// ---------------- LayerNorm ----------------
__global__ void ln_kernel(const float* __restrict__ x,
                          const float* __restrict__ gamma,
                          const float* __restrict__ beta,
                          float* __restrict__ out)
{
    int t   = blockIdx.x;
    int tid = threadIdx.x;
    const float4* xr = (const float4*)(x + (size_t)t * DM);
    float4 v0 = xr[tid];
    float4 v1 = xr[tid + 128];
    float s  = v0.x + v0.y + v0.z + v0.w + v1.x + v1.y + v1.z + v1.w;
    float ss = v0.x*v0.x + v0.y*v0.y + v0.z*v0.z + v0.w*v0.w
             + v1.x*v1.x + v1.y*v1.y + v1.z*v1.z + v1.w*v1.w;
    #pragma unroll
    for (int o = 16; o; o >>= 1) {
        s  += __shfl_xor_sync(0xffffffffu, s,  o);
        ss += __shfl_xor_sync(0xffffffffu, ss, o);
    }
    __shared__ float sm_s[4], sm_ss[4];
    int w = tid >> 5, ln = tid & 31;
    if (ln == 0) { sm_s[w] = s; sm_ss[w] = ss; }
    __syncthreads();
    s  = sm_s[0] + sm_s[1] + sm_s[2] + sm_s[3];
    ss = sm_ss[0] + sm_ss[1] + sm_ss[2] + sm_ss[3];
    float mu   = s * (1.0f / DM);
    float var  = ss * (1.0f / DM) - mu * mu;
    float rstd = rsqrtf(var + 1e-5f);

    const float4* gr = (const float4*)gamma;
    const float4* br = (const float4*)beta;
    float4* o4 = (float4*)(out + (size_t)t * DM);
    #pragma unroll
    for (int u = 0; u < 2; u++) {
        int i = tid + u * 128;
        float4 xv = xr[i], gv = gr[i], bv = br[i];
        float4 r;
        r.x = (xv.x - mu) * rstd * gv.x + bv.x;
        r.y = (xv.y - mu) * rstd * gv.y + bv.y;
        r.z = (xv.z - mu) * rstd * gv.z + bv.z;
        r.w = (xv.w - mu) * rstd * gv.w + bv.w;
        o4[i] = r;
    }
}

// ---------------- split fp32 -> bf16 hi/lo ----------------
__global__ void split_kernel(const float* __restrict__ x,
                             __nv_bfloat16* __restrict__ h,
                             __nv_bfloat16* __restrict__ l)
{
    int i = (blockIdx.x * blockDim.x + threadIdx.x) * 8;
    float4 a = *(const float4*)(x + i);
    float4 b = *(const float4*)(x + i + 4);
    float vs[8] = {a.x, a.y, a.z, a.w, b.x, b.y, b.z, b.w};
    __nv_bfloat162 hh[4], ll[4];
    #pragma unroll
    for (int j = 0; j < 4; j++) {
        __nv_bfloat16 h0 = __float2bfloat16(vs[2*j]);
        __nv_bfloat16 h1 = __float2bfloat16(vs[2*j+1]);
        __nv_bfloat16 l0 = __float2bfloat16(vs[2*j]   - __bfloat162float(h0));
        __nv_bfloat16 l1 = __float2bfloat16(vs[2*j+1] - __bfloat162float(h1));
        hh[j] = __nv_bfloat162(h0, h1);
        ll[j] = __nv_bfloat162(l0, l1);
    }
    *(uint4*)(h + i) = *(uint4*)hh;
    *(uint4*)(l + i) = *(uint4*)ll;
}

// ---------------- transpose + split: w[K,N] fp32 -> th/tl[N,K] bf16 -----------
__global__ void tsplit_kernel(const float* __restrict__ w,
                              __nv_bfloat16* __restrict__ th,
                              __nv_bfloat16* __restrict__ tl,
                              int K, int N)
{
    __shared__ float t[32][33];
    int tx = threadIdx.x, ty = threadIdx.y;
    int n0 = blockIdx.x * 32, k0 = blockIdx.y * 32;
    #pragma unroll
    for (int i = 0; i < 4; i++)
        t[ty + i * 8][tx] = w[(size_t)(k0 + ty + i * 8) * N + n0 + tx];
    __syncthreads();
    #pragma unroll
    for (int i = 0; i < 4; i++) {
        float v = t[tx][ty + i * 8];
        __nv_bfloat16 hi = __float2bfloat16(v);
        __nv_bfloat16 lo = __float2bfloat16(v - __bfloat162float(hi));
        size_t o = (size_t)(n0 + ty + i * 8) * K + k0 + tx;
        th[o] = hi;
        tl[o] = lo;
    }
}

// ---------------- mma.sync split-bf16 GEMM ----------------
// C[M,N] = (Ah+Al)[M,K] @ (Bh+Bl)[N,K]^T, 3 products, fp32 reg accumulators.
// CTA 128x128, BK=32, 8 warps each 64m x 32n.
#define LDT    40                         // smem row stride in bf16 (80 bytes)
#define TILEB  (128 * LDT * 2)            // 10240 bytes per tile array
#define STAGEB (4 * TILEB)                // Ah, Al, Bh, Bl
#define GEMM_SMEM (2 * STAGEB)            // 81920 bytes

template<bool BIAS, bool RELU, bool RES>
__global__ void __launch_bounds__(256) tc_gemm_kernel(
    const __nv_bfloat16* __restrict__ Ah, const __nv_bfloat16* __restrict__ Al,
    const __nv_bfloat16* __restrict__ Bh, const __nv_bfloat16* __restrict__ Bl,
    const float* __restrict__ bias, const float* __restrict__ Res,
    float* __restrict__ C, int M, int N, int K)
{
    extern __shared__ char smem[];
    const uint32_t sb = smem_u32(smem);
    int tid = threadIdx.x;
    int wid = tid >> 5, lane = tid & 31;
    int wm = wid & 1, wn = wid >> 1;          // warp tile: rows wm*64, cols wn*32
    int m0 = blockIdx.y * 128, n0 = blockIdx.x * 128;

    float acc[4][4][4];
    #pragma unroll
    for (int i = 0; i < 4; i++)
        #pragma unroll
        for (int j = 0; j < 4; j++)
            #pragma unroll
            for (int r = 0; r < 4; r++) acc[i][j][r] = 0.f;

    // loader geometry: 512 slots of 16B per tile array; 2 slots per thread
    int r0 = (tid * 2) >> 2,      c0 = (tid * 2) & 3;
    int r1 = (tid * 2 + 1) >> 2,  c1 = (tid * 2 + 1) & 3;

    int nc = K >> 5;

    auto load_chunk = [&](int c, int st) {
        int kc = c << 5;
        uint32_t base = sb + st * STAGEB;
        size_t ga0 = (size_t)(m0 + r0) * K + kc + c0 * 8;
        size_t ga1 = (size_t)(m0 + r1) * K + kc + c1 * 8;
        size_t gb0 = (size_t)(n0 + r0) * K + kc + c0 * 8;
        size_t gb1 = (size_t)(n0 + r1) * K + kc + c1 * 8;
        uint32_t s0 = r0 * 80 + c0 * 16, s1 = r1 * 80 + c1 * 16;
        cpa16(base + s0,              Ah + ga0);
        cpa16(base + s1,              Ah + ga1);
        cpa16(base + TILEB + s0,      Al + ga0);
        cpa16(base + TILEB + s1,      Al + ga1);
        cpa16(base + 2 * TILEB + s0,  Bh + gb0);
        cpa16(base + 2 * TILEB + s1,  Bh + gb1);
        cpa16(base + 3 * TILEB + s0,  Bl + gb0);
        cpa16(base + 3 * TILEB + s1,  Bl + gb1);
        CP_COMMIT();
    };

    load_chunk(0, 0);

    // per-warp ldmatrix lane addressing (byte offsets within a tile array)
    int aRow = wm * 64 + (lane & 15);              // + mt*16
    uint32_t aOff = (uint32_t)(aRow * 80 + (lane >> 4) * 16);
    int bm = lane >> 3, br = lane & 7;
    int bRow = wn * 32 + ((bm & 2) ? 8 : 0) + br;  // + p*16
    uint32_t bOff = (uint32_t)(bRow * 80 + ((bm & 1) ? 16 : 0));

    for (int c = 0; c < nc; c++) {
        int st = c & 1;
        if (c + 1 < nc) { load_chunk(c + 1, st ^ 1); CP_WAIT(1); }
        else            { CP_WAIT(0); }
        __syncthreads();

        uint32_t base = sb + st * STAGEB;
        #pragma unroll
        for (int ks = 0; ks < 2; ks++) {
            uint32_t kb = ks * 32;
            uint32_t af[4][4], bhf[4][2], blf[4][2];
            // A_h frags
            #pragma unroll
            for (int mt = 0; mt < 4; mt++)
                ldm_x4(af[mt], base + aOff + mt * (16 * 80) + kb);
            // B_h frags (two x4 loads cover 4 n8 tiles)
            #pragma unroll
            for (int p = 0; p < 2; p++) {
                uint32_t t4[4];
                ldm_x4(t4, base + 2 * TILEB + bOff + p * (16 * 80) + kb);
                bhf[2*p][0] = t4[0]; bhf[2*p][1] = t4[1];
                bhf[2*p+1][0] = t4[2]; bhf[2*p+1][1] = t4[3];
            }
            // hi x hi
            #pragma unroll
            for (int mt = 0; mt < 4; mt++)
                #pragma unroll
                for (int nt = 0; nt < 4; nt++)
                    mma_bf16(acc[mt][nt], af[mt], bhf[nt]);
            // B_l frags, hi x lo
            #pragma unroll
            for (int p = 0; p < 2; p++) {
                uint32_t t4[4];
                ldm_x4(t4, base + 3 * TILEB + bOff + p * (16 * 80) + kb);
                blf[2*p][0] = t4[0]; blf[2*p][1] = t4[1];
                blf[2*p+1][0] = t4[2]; blf[2*p+1][1] = t4[3];
            }
            #pragma unroll
            for (int mt = 0; mt < 4; mt++)
                #pragma unroll
                for (int nt = 0; nt < 4; nt++)
                    mma_bf16(acc[mt][nt], af[mt], blf[nt]);
            // A_l frags (reuse af), lo x hi
            #pragma unroll
            for (int mt = 0; mt < 4; mt++)
                ldm_x4(af[mt], base + TILEB + aOff + mt * (16 * 80) + kb);
            #pragma unroll
            for (int mt = 0; mt < 4; mt++)
                #pragma unroll
                for (int nt = 0; nt < 4; nt++)
                    mma_bf16(acc[mt][nt], af[mt], bhf[nt]);
        }
        __syncthreads();
    }

    // epilogue: fragment layout d0,d1 -> row g cols 2t,2t+1 ; d2,d3 -> row g+8
    int g = lane >> 2, tq = lane & 3;
    #pragma unroll
    for (int mt = 0; mt < 4; mt++) {
        int mbase = m0 + wm * 64 + mt * 16 + g;
        #pragma unroll
        for (int nt = 0; nt < 4; nt++) {
            int n = n0 + wn * 32 + nt * 8 + tq * 2;
            float2 v0 = make_float2(acc[mt][nt][0], acc[mt][nt][1]);
            float2 v1 = make_float2(acc[mt][nt][2], acc[mt][nt][3]);
            if (BIAS) {
                float2 bb = *(const float2*)(bias + n);
                v0.x += bb.x; v0.y += bb.y; v1.x += bb.x; v1.y += bb.y;
            }
            if (RELU) {
                v0.x = fmaxf(v0.x, 0.f); v0.y = fmaxf(v0.y, 0.f);
                v1.x = fmaxf(v1.x, 0.f); v1.y = fmaxf(v1.y, 0.f);
            }
            if (RES) {
                float2 q0 = *(const float2*)(Res + (size_t)mbase * N + n);
                float2 q1 = *(const float2*)(Res + (size_t)(mbase + 8) * N + n);
                v0.x += q0.x; v0.y += q0.y; v1.x += q1.x; v1.y += q1.y;
            }
            *(float2*)(C + (size_t)mbase * N + n) = v0;
            *(float2*)(C + (size_t)(mbase + 8) * N + n) = v1;
        }
    }
}

// ---------------- Flash attention (fp32, causal, online softmax) --------------
#define APAD 68
#define ATILE (64 * APAD)

__global__ void __launch_bounds__(256, 2) attn_kernel(
    const float* __restrict__ Q, const float* __restrict__ K,
    const float* __restrict__ V, float* __restrict__ O)
{
    extern __shared__ float sm[];
    float* Qs = sm;
    float* Ks = sm + ATILE;
    float* Vs = sm + 2 * ATILE;
    float* Ps = sm + 3 * ATILE;

    int qt = (int)gridDim.x - 1 - (int)blockIdx.x;
    int h = blockIdx.y, b = blockIdx.z;
    int tid = threadIdx.x;
    int tx = tid & 15, ty = tid >> 4;
    int lr = tid >> 2, lq = tid & 3;

    {
        const float* qb = Q + (size_t)(b * SEQL + qt * 64 + lr) * DM + h * DH + lq * 16;
        #pragma unroll
        for (int u = 0; u < 4; u++)
            *(float4*)&Qs[lr * APAD + lq * 16 + u * 4] = *(const float4*)(qb + u * 4);
    }

    float m_prev[4], l[4], acc[4][4];
    #pragma unroll
    for (int i = 0; i < 4; i++) {
        m_prev[i] = -INFINITY; l[i] = 0.f;
        #pragma unroll
        for (int j = 0; j < 4; j++) acc[i][j] = 0.f;
    }

    for (int t = 0; t <= qt; t++) {
        __syncthreads();
        {
            const float* kb = K + (size_t)(b * SEQL + t * 64 + lr) * DM + h * DH + lq * 16;
            const float* vb = V + (size_t)(b * SEQL + t * 64 + lr) * DM + h * DH + lq * 16;
            #pragma unroll
            for (int u = 0; u < 4; u++) {
                *(float4*)&Ks[lr * APAD + lq * 16 + u * 4] = *(const float4*)(kb + u * 4);
                *(float4*)&Vs[lr * APAD + lq * 16 + u * 4] = *(const float4*)(vb + u * 4);
            }
        }
        __syncthreads();

        float s[4][4];
        #pragma unroll
        for (int i = 0; i < 4; i++)
            #pragma unroll
            for (int j = 0; j < 4; j++) s[i][j] = 0.f;

        #pragma unroll
        for (int d4 = 0; d4 < 16; d4++) {
            float4 a[4], bf[4];
            #pragma unroll
            for (int i = 0; i < 4; i++)
                a[i] = *(const float4*)&Qs[(ty * 4 + i) * APAD + d4 * 4];
            #pragma unroll
            for (int j = 0; j < 4; j++)
                bf[j] = *(const float4*)&Ks[(tx * 4 + j) * APAD + d4 * 4];
            #pragma unroll
            for (int i = 0; i < 4; i++)
                #pragma unroll
                for (int j = 0; j < 4; j++)
                    s[i][j] += a[i].x * bf[j].x + a[i].y * bf[j].y
                             + a[i].z * bf[j].z + a[i].w * bf[j].w;
        }

        bool diag = (t == qt);
        #pragma unroll
        for (int i = 0; i < 4; i++)
            #pragma unroll
            for (int j = 0; j < 4; j++) {
                s[i][j] *= 0.125f;
                if (diag && (tx * 4 + j) > (ty * 4 + i)) s[i][j] = -INFINITY;
            }

        #pragma unroll
        for (int i = 0; i < 4; i++) {
            float mt = fmaxf(fmaxf(s[i][0], s[i][1]), fmaxf(s[i][2], s[i][3]));
            mt = fmaxf(mt, __shfl_xor_sync(0xffffffffu, mt, 1));
            mt = fmaxf(mt, __shfl_xor_sync(0xffffffffu, mt, 2));
            mt = fmaxf(mt, __shfl_xor_sync(0xffffffffu, mt, 4));
            mt = fmaxf(mt, __shfl_xor_sync(0xffffffffu, mt, 8));
            float m_new = fmaxf(m_prev[i], mt);
            float sc = __expf(m_prev[i] - m_new);
            float p0 = __expf(s[i][0] - m_new);
            float p1 = __expf(s[i][1] - m_new);
            float p2 = __expf(s[i][2] - m_new);
            float p3 = __expf(s[i][3] - m_new);
            s[i][0] = p0; s[i][1] = p1; s[i][2] = p2; s[i][3] = p3;
            float lt = p0 + p1 + p2 + p3;
            lt += __shfl_xor_sync(0xffffffffu, lt, 1);
            lt += __shfl_xor_sync(0xffffffffu, lt, 2);
            lt += __shfl_xor_sync(0xffffffffu, lt, 4);
            lt += __shfl_xor_sync(0xffffffffu, lt, 8);
            l[i] = l[i] * sc + lt;
            m_prev[i] = m_new;
            #pragma unroll
            for (int j = 0; j < 4; j++) acc[i][j] *= sc;
        }

        #pragma unroll
        for (int i = 0; i < 4; i++)
            *(float4*)&Ps[(ty * 4 + i) * APAD + tx * 4] =
                make_float4(s[i][0], s[i][1], s[i][2], s[i][3]);
        __syncthreads();

        #pragma unroll
        for (int c4 = 0; c4 < 16; c4++) {
            float4 pa[4], vr[4];
            #pragma unroll
            for (int i = 0; i < 4; i++)
                pa[i] = *(const float4*)&Ps[(ty * 4 + i) * APAD + c4 * 4];
            #pragma unroll
            for (int cc = 0; cc < 4; cc++)
                vr[cc] = *(const float4*)&Vs[(c4 * 4 + cc) * APAD + tx * 4];
            #pragma unroll
            for (int i = 0; i < 4; i++) {
                acc[i][0] += pa[i].x * vr[0].x + pa[i].y * vr[1].x + pa[i].z * vr[2].x + pa[i].w * vr[3].x;
                acc[i][1] += pa[i].x * vr[0].y + pa[i].y * vr[1].y + pa[i].z * vr[2].y + pa[i].w * vr[3].y;
                acc[i][2] += pa[i].x * vr[0].z + pa[i].y * vr[1].z + pa[i].z * vr[2].z + pa[i].w * vr[3].z;
                acc[i][3] += pa[i].x * vr[0].w + pa[i].y * vr[1].w + pa[i].z * vr[2].w + pa[i].w * vr[3].w;
            }
        }
    }

    #pragma unroll
    for (int i = 0; i < 4; i++) {
        float inv = 1.0f / l[i];
        int row = qt * 64 + ty * 4 + i;
        float* ob = O + (size_t)(b * SEQL + row) * DM + h * DH + tx * 4;
        *(float4*)ob = make_float4(acc[i][0] * inv, acc[i][1] * inv,
                                   acc[i][2] * inv, acc[i][3] * inv);
    }
}

// ---------------- launch ----------------
extern "C" void kernel_launch(void* const* d_in, const int* in_sizes, int n_in,
                              void* d_out, int out_size)
{
    const float* x   = (const float*)d_in[0];
    const float* wq  = (const float*)d_in[1];
    const float* wk  = (const float*)d_in[2];
    const float* wv  = (const float*)d_in[3];
    const float* wo  = (const float*)d_in[4];
    const float* w1  = (const float*)d_in[5];
    const float* b1  = (const float*)d_in[6];
    const float* w2  = (const float*)d_in[7];
    const float* b2  = (const float*)d_in[8];
    const float* g1  = (const float*)d_in[9];
    const float* be1 = (const float*)d_in[10];
    const float* g2  = (const float*)d_in[11];
    const float* be2 = (const float*)d_in[12];
    float* out = (float*)d_out;

    float *xn, *q, *k, *v, *attn, *x1, *hid;
    cudaGetSymbolAddress((void**)&xn,   g_xn);
    cudaGetSymbolAddress((void**)&q,    g_q);
    cudaGetSymbolAddress((void**)&k,    g_k);
    cudaGetSymbolAddress((void**)&v,    g_v);
    cudaGetSymbolAddress((void**)&attn, g_attn);
    cudaGetSymbolAddress((void**)&x1,   g_x1);
    cudaGetSymbolAddress((void**)&hid,  g_hid);

    __nv_bfloat16 *ah, *al, *hh, *hl;
    __nv_bfloat16 *wqh, *wql, *wkh, *wkl, *wvh, *wvl, *woh, *wol, *w1h, *w1l, *w2h, *w2l;
    cudaGetSymbolAddress((void**)&ah,  g_act_h);
    cudaGetSymbolAddress((void**)&al,  g_act_l);
    cudaGetSymbolAddress((void**)&hh,  g_hid_h);
    cudaGetSymbolAddress((void**)&hl,  g_hid_l);
    cudaGetSymbolAddress((void**)&wqh, g_wq_h);  cudaGetSymbolAddress((void**)&wql, g_wq_l);
    cudaGetSymbolAddress((void**)&wkh, g_wk_h);  cudaGetSymbolAddress((void**)&wkl, g_wk_l);
    cudaGetSymbolAddress((void**)&wvh, g_wv_h);  cudaGetSymbolAddress((void**)&wvl, g_wv_l);
    cudaGetSymbolAddress((void**)&woh, g_wo_h);  cudaGetSymbolAddress((void**)&wol, g_wo_l);
    cudaGetSymbolAddress((void**)&w1h, g_w1_h);  cudaGetSymbolAddress((void**)&w1l, g_w1_l);
    cudaGetSymbolAddress((void**)&w2h, g_w2_h);  cudaGetSymbolAddress((void**)&w2l, g_w2_l);

    cudaFuncSetAttribute(attn_kernel, cudaFuncAttributeMaxDynamicSharedMemorySize,
                         4 * ATILE * sizeof(float));
    cudaFuncSetAttribute(tc_gemm_kernel<false, false, false>,
                         cudaFuncAttributeMaxDynamicSharedMemorySize, GEMM_SMEM);
    cudaFuncSetAttribute(tc_gemm_kernel<false, false, true>,
                         cudaFuncAttributeMaxDynamicSharedMemorySize, GEMM_SMEM);
    cudaFuncSetAttribute(tc_gemm_kernel<true, true, false>,
                         cudaFuncAttributeMaxDynamicSharedMemorySize, GEMM_SMEM);
    cudaFuncSetAttribute(tc_gemm_kernel<true, false, true>,
                         cudaFuncAttributeMaxDynamicSharedMemorySize, GEMM_SMEM);

    dim3 t32(32, 8);
    // weight transpose+split
    tsplit_kernel<<<dim3(DM / 32, DM / 32), t32>>>(wq, wqh, wql, DM, DM);
    tsplit_kernel<<<dim3(DM / 32, DM / 32), t32>>>(wk, wkh, wkl, DM, DM);
    tsplit_kernel<<<dim3(DM / 32, DM / 32), t32>>>(wv, wvh, wvl, DM, DM);
    tsplit_kernel<<<dim3(DM / 32, DM / 32), t32>>>(wo, woh, wol, DM, DM);
    tsplit_kernel<<<dim3(HID / 32, DM / 32), t32>>>(w1, w1h, w1l, DM, HID);
    tsplit_kernel<<<dim3(DM / 32, HID / 32), t32>>>(w2, w2h, w2l, HID, DM);

    // LN1 + activation split
    ln_kernel<<<TOK, 128>>>(x, g1, be1, xn);
    split_kernel<<<TOK * DM / (256 * 8), 256>>>(xn, ah, al);

    // QKV projections
    dim3 gqkv(DM / 128, TOK / 128);
    tc_gemm_kernel<false, false, false><<<gqkv, 256, GEMM_SMEM>>>(
        ah, al, wqh, wql, nullptr, nullptr, q, TOK, DM, DM);
    tc_gemm_kernel<false, false, false><<<gqkv, 256, GEMM_SMEM>>>(
        ah, al, wkh, wkl, nullptr, nullptr, k, TOK, DM, DM);
    tc_gemm_kernel<false, false, false><<<gqkv, 256, GEMM_SMEM>>>(
        ah, al, wvh, wvl, nullptr, nullptr, v, TOK, DM, DM);

    // Attention
    attn_kernel<<<dim3(SEQL / 64, NH, NB), 256, 4 * ATILE * sizeof(float)>>>(q, k, v, attn);

    // O projection + residual
    split_kernel<<<TOK * DM / (256 * 8), 256>>>(attn, ah, al);
    tc_gemm_kernel<false, false, true><<<gqkv, 256, GEMM_SMEM>>>(
        ah, al, woh, wol, nullptr, x, x1, TOK, DM, DM);

    // LN2 + split
    ln_kernel<<<TOK, 128>>>(x1, g2, be2, xn);
    split_kernel<<<TOK * DM / (256 * 8), 256>>>(xn, ah, al);

    // FFN1: relu(xn @ w1 + b1)
    tc_gemm_kernel<true, true, false><<<dim3(HID / 128, TOK / 128), 256, GEMM_SMEM>>>(
        ah, al, w1h, w1l, b1, nullptr, hid, TOK, HID, DM);
    split_kernel<<<TOK * HID / (256 * 8), 256>>>(hid, hh, hl);

    // FFN2: hid @ w2 + b2 + x1 -> out
    tc_gemm_kernel<true, false, true><<<gqkv, 256, GEMM_SMEM>>>(
        hh, hl, w2h, w2l, b2, x1, out, TOK, DM, HID);
}

// round 5
// speedup vs baseline: 7.2875x; 1.5375x over previous
#include <cuda_runtime.h>
#include <cuda_bf16.h>
#include <math.h>
#include <stdint.h>

#define TOK   4096   // B*S tokens
#define DM    1024
#define HID   4096
#define SEQL  2048
#define NB    2
#define NH    16
#define DH    64

// ---------------- scratch (allocation-free: __device__ globals) ----------------
__device__ float g_xn[TOK * DM];
__device__ float g_q[TOK * DM];
__device__ float g_k[TOK * DM];
__device__ float g_v[TOK * DM];
__device__ float g_attn[TOK * DM];
__device__ float g_x1[TOK * DM];
__device__ float g_hid[TOK * HID];

// bf16 hi/lo split scratch
__device__ __align__(256) __nv_bfloat16 g_act_h[TOK * DM];
__device__ __align__(256) __nv_bfloat16 g_act_l[TOK * DM];
__device__ __align__(256) __nv_bfloat16 g_hid_h[TOK * HID];
__device__ __align__(256) __nv_bfloat16 g_hid_l[TOK * HID];
// attention operand splits
__device__ __align__(256) __nv_bfloat16 g_qh[TOK * DM], g_ql[TOK * DM];
__device__ __align__(256) __nv_bfloat16 g_kh[TOK * DM], g_kl[TOK * DM];
__device__ __align__(256) __nv_bfloat16 g_vth[TOK * DM], g_vtl[TOK * DM]; // [b][h][d][key]
// weights transposed to [N,K] bf16 hi/lo
__device__ __align__(256) __nv_bfloat16 g_wq_h[DM * DM], g_wq_l[DM * DM];
__device__ __align__(256) __nv_bfloat16 g_wk_h[DM * DM], g_wk_l[DM * DM];
__device__ __align__(256) __nv_bfloat16 g_wv_h[DM * DM], g_wv_l[DM * DM];
__device__ __align__(256) __nv_bfloat16 g_wo_h[DM * DM], g_wo_l[DM * DM];
__device__ __align__(256) __nv_bfloat16 g_w1_h[DM * HID], g_w1_l[DM * HID];
__device__ __align__(256) __nv_bfloat16 g_w2_h[HID * DM], g_w2_l[HID * DM];

// ---------------- base-target PTX helpers ----------------
__device__ __forceinline__ uint32_t smem_u32(const void* p) {
    uint32_t a;
    asm("{ .reg .u64 t; cvta.to.shared.u64 t, %1; cvt.u32.u64 %0, t; }"
        : "=r"(a) : "l"(p));
    return a;
}
__device__ __forceinline__ void cpa16(uint32_t s, const void* g) {
    asm volatile("cp.async.cg.shared.global [%0], [%1], 16;" :: "r"(s), "l"(g));
}
#define CP_COMMIT() asm volatile("cp.async.commit_group;" ::: "memory")
#define CP_WAIT(n)  asm volatile("cp.async.wait_group %0;" :: "n"(n) : "memory")

__device__ __forceinline__ void ldm_x4(uint32_t* r, uint32_t addr) {
    asm volatile("ldmatrix.sync.aligned.m8n8.x4.shared.b16 {%0,%1,%2,%3}, [%4];"
                 : "=r"(r[0]), "=r"(r[1]), "=r"(r[2]), "=r"(r[3]) : "r"(addr));
}
__device__ __forceinline__ void mma_bf16(float* d, const uint32_t* a, const uint32_t* b) {
    asm volatile(
        "mma.sync.aligned.m16n8k16.row.col.f32.bf16.bf16.f32 "
        "{%0,%1,%2,%3}, {%4,%5,%6,%7}, {%8,%9}, {%0,%1,%2,%3};"
        : "+f"(d[0]), "+f"(d[1]), "+f"(d[2]), "+f"(d[3])
        : "r"(a[0]), "r"(a[1]), "r"(a[2]), "r"(a[3]), "r"(b[0]), "r"(b[1]));
}
__device__ __forceinline__ uint32_t packbf2(float lo, float hi) {
    __nv_bfloat162 t = __floats2bfloat162_rn(lo, hi);
    return *(uint32_t*)&t;
}

// ---------------- LayerNorm ----------------
__global__ void ln_kernel(const float* __restrict__ x,
                          const float* __restrict__ gamma,
                          const float* __restrict__ beta,
                          float* __restrict__ out)
{
    int t   = blockIdx.x;
    int tid = threadIdx.x;
    const float4* xr = (const float4*)(x + (size_t)t * DM);
    float4 v0 = xr[tid];
    float4 v1 = xr[tid + 128];
    float s  = v0.x + v0.y + v0.z + v0.w + v1.x + v1.y + v1.z + v1.w;
    float ss = v0.x*v0.x + v0.y*v0.y + v0.z*v0.z + v0.w*v0.w
             + v1.x*v1.x + v1.y*v1.y + v1.z*v1.z + v1.w*v1.w;
    #pragma unroll
    for (int o = 16; o; o >>= 1) {
        s  += __shfl_xor_sync(0xffffffffu, s,  o);
        ss += __shfl_xor_sync(0xffffffffu, ss, o);
    }
    __shared__ float sm_s[4], sm_ss[4];
    int w = tid >> 5, ln = tid & 31;
    if (ln == 0) { sm_s[w] = s; sm_ss[w] = ss; }
    __syncthreads();
    s  = sm_s[0] + sm_s[1] + sm_s[2] + sm_s[3];
    ss = sm_ss[0] + sm_ss[1] + sm_ss[2] + sm_ss[3];
    float mu   = s * (1.0f / DM);
    float var  = ss * (1.0f / DM) - mu * mu;
    float rstd = rsqrtf(var + 1e-5f);

    const float4* gr = (const float4*)gamma;
    const float4* br = (const float4*)beta;
    float4* o4 = (float4*)(out + (size_t)t * DM);
    #pragma unroll
    for (int u = 0; u < 2; u++) {
        int i = tid + u * 128;
        float4 xv = xr[i], gv = gr[i], bv = br[i];
        float4 r;
        r.x = (xv.x - mu) * rstd * gv.x + bv.x;
        r.y = (xv.y - mu) * rstd * gv.y + bv.y;
        r.z = (xv.z - mu) * rstd * gv.z + bv.z;
        r.w = (xv.w - mu) * rstd * gv.w + bv.w;
        o4[i] = r;
    }
}

// ---------------- split fp32 -> bf16 hi/lo ----------------
__global__ void split_kernel(const float* __restrict__ x,
                             __nv_bfloat16* __restrict__ h,
                             __nv_bfloat16* __restrict__ l)
{
    int i = (blockIdx.x * blockDim.x + threadIdx.x) * 8;
    float4 a = *(const float4*)(x + i);
    float4 b = *(const float4*)(x + i + 4);
    float vs[8] = {a.x, a.y, a.z, a.w, b.x, b.y, b.z, b.w};
    __nv_bfloat162 hh[4], ll[4];
    #pragma unroll
    for (int j = 0; j < 4; j++) {
        __nv_bfloat16 h0 = __float2bfloat16(vs[2*j]);
        __nv_bfloat16 h1 = __float2bfloat16(vs[2*j+1]);
        __nv_bfloat16 l0 = __float2bfloat16(vs[2*j]   - __bfloat162float(h0));
        __nv_bfloat16 l1 = __float2bfloat16(vs[2*j+1] - __bfloat162float(h1));
        hh[j] = __nv_bfloat162(h0, h1);
        ll[j] = __nv_bfloat162(l0, l1);
    }
    *(uint4*)(h + i) = *(uint4*)hh;
    *(uint4*)(l + i) = *(uint4*)ll;
}

// ---------------- transpose + split: w[K,N] fp32 -> th/tl[N,K] bf16 -----------
__global__ void tsplit_kernel(const float* __restrict__ w,
                              __nv_bfloat16* __restrict__ th,
                              __nv_bfloat16* __restrict__ tl,
                              int K, int N)
{
    __shared__ float t[32][33];
    int tx = threadIdx.x, ty = threadIdx.y;
    int n0 = blockIdx.x * 32, k0 = blockIdx.y * 32;
    #pragma unroll
    for (int i = 0; i < 4; i++)
        t[ty + i * 8][tx] = w[(size_t)(k0 + ty + i * 8) * N + n0 + tx];
    __syncthreads();
    #pragma unroll
    for (int i = 0; i < 4; i++) {
        float v = t[tx][ty + i * 8];
        __nv_bfloat16 hi = __float2bfloat16(v);
        __nv_bfloat16 lo = __float2bfloat16(v - __bfloat162float(hi));
        size_t o = (size_t)(n0 + ty + i * 8) * K + k0 + tx;
        th[o] = hi;
        tl[o] = lo;
    }
}

// ---- per-(b,h) transpose+split of V: v[b*S+s][h*64+d] -> vt[(b*NH+h)*64+d][s]
__global__ void vtrans_split_kernel(const float* __restrict__ v,
                                    __nv_bfloat16* __restrict__ th,
                                    __nv_bfloat16* __restrict__ tl)
{
    __shared__ float t[32][33];
    int tx = threadIdx.x, ty = threadIdx.y;
    int bh = blockIdx.z;
    int b = bh / NH, h = bh % NH;
    int s0 = blockIdx.x * 32, d0 = blockIdx.y * 32;
    #pragma unroll
    for (int i = 0; i < 4; i++)
        t[ty + i * 8][tx] = v[(size_t)(b * SEQL + s0 + ty + i * 8) * DM + h * DH + d0 + tx];
    __syncthreads();
    #pragma unroll
    for (int i = 0; i < 4; i++) {
        float val = t[tx][ty + i * 8];   // v[s0+tx][d0+ty+i*8]
        __nv_bfloat16 hi = __float2bfloat16(val);
        __nv_bfloat16 lo = __float2bfloat16(val - __bfloat162float(hi));
        size_t o = ((size_t)bh * DH + d0 + ty + i * 8) * SEQL + s0 + tx;
        th[o] = hi;
        tl[o] = lo;
    }
}

// ---------------- mma.sync split-bf16 GEMM (unchanged from R4) ----------------
#define LDT    40
#define TILEB  (128 * LDT * 2)
#define STAGEB (4 * TILEB)
#define GEMM_SMEM (2 * STAGEB)

template<bool BIAS, bool RELU, bool RES>
__global__ void __launch_bounds__(256) tc_gemm_kernel(
    const __nv_bfloat16* __restrict__ Ah, const __nv_bfloat16* __restrict__ Al,
    const __nv_bfloat16* __restrict__ Bh, const __nv_bfloat16* __restrict__ Bl,
    const float* __restrict__ bias, const float* __restrict__ Res,
    float* __restrict__ C, int M, int N, int K)
{
    extern __shared__ char smem[];
    const uint32_t sb = smem_u32(smem);
    int tid = threadIdx.x;
    int wid = tid >> 5, lane = tid & 31;
    int wm = wid & 1, wn = wid >> 1;
    int m0 = blockIdx.y * 128, n0 = blockIdx.x * 128;

    float acc[4][4][4];
    #pragma unroll
    for (int i = 0; i < 4; i++)
        #pragma unroll
        for (int j = 0; j < 4; j++)
            #pragma unroll
            for (int r = 0; r < 4; r++) acc[i][j][r] = 0.f;

    int r0 = (tid * 2) >> 2,      c0 = (tid * 2) & 3;
    int r1 = (tid * 2 + 1) >> 2,  c1 = (tid * 2 + 1) & 3;
    int nc = K >> 5;

    auto load_chunk = [&](int c, int st) {
        int kc = c << 5;
        uint32_t base = sb + st * STAGEB;
        size_t ga0 = (size_t)(m0 + r0) * K + kc + c0 * 8;
        size_t ga1 = (size_t)(m0 + r1) * K + kc + c1 * 8;
        size_t gb0 = (size_t)(n0 + r0) * K + kc + c0 * 8;
        size_t gb1 = (size_t)(n0 + r1) * K + kc + c1 * 8;
        uint32_t s0 = r0 * 80 + c0 * 16, s1 = r1 * 80 + c1 * 16;
        cpa16(base + s0,              Ah + ga0);
        cpa16(base + s1,              Ah + ga1);
        cpa16(base + TILEB + s0,      Al + ga0);
        cpa16(base + TILEB + s1,      Al + ga1);
        cpa16(base + 2 * TILEB + s0,  Bh + gb0);
        cpa16(base + 2 * TILEB + s1,  Bh + gb1);
        cpa16(base + 3 * TILEB + s0,  Bl + gb0);
        cpa16(base + 3 * TILEB + s1,  Bl + gb1);
        CP_COMMIT();
    };

    load_chunk(0, 0);

    int aRow = wm * 64 + (lane & 15);
    uint32_t aOff = (uint32_t)(aRow * 80 + (lane >> 4) * 16);
    int bm = lane >> 3, br = lane & 7;
    int bRow = wn * 32 + ((bm & 2) ? 8 : 0) + br;
    uint32_t bOff = (uint32_t)(bRow * 80 + ((bm & 1) ? 16 : 0));

    for (int c = 0; c < nc; c++) {
        int st = c & 1;
        if (c + 1 < nc) { load_chunk(c + 1, st ^ 1); CP_WAIT(1); }
        else            { CP_WAIT(0); }
        __syncthreads();

        uint32_t base = sb + st * STAGEB;
        #pragma unroll
        for (int ks = 0; ks < 2; ks++) {
            uint32_t kb = ks * 32;
            uint32_t af[4][4], bhf[4][2], blf[4][2];
            #pragma unroll
            for (int mt = 0; mt < 4; mt++)
                ldm_x4(af[mt], base + aOff + mt * (16 * 80) + kb);
            #pragma unroll
            for (int p = 0; p < 2; p++) {
                uint32_t t4[4];
                ldm_x4(t4, base + 2 * TILEB + bOff + p * (16 * 80) + kb);
                bhf[2*p][0] = t4[0]; bhf[2*p][1] = t4[1];
                bhf[2*p+1][0] = t4[2]; bhf[2*p+1][1] = t4[3];
            }
            #pragma unroll
            for (int mt = 0; mt < 4; mt++)
                #pragma unroll
                for (int nt = 0; nt < 4; nt++)
                    mma_bf16(acc[mt][nt], af[mt], bhf[nt]);
            #pragma unroll
            for (int p = 0; p < 2; p++) {
                uint32_t t4[4];
                ldm_x4(t4, base + 3 * TILEB + bOff + p * (16 * 80) + kb);
                blf[2*p][0] = t4[0]; blf[2*p][1] = t4[1];
                blf[2*p+1][0] = t4[2]; blf[2*p+1][1] = t4[3];
            }
            #pragma unroll
            for (int mt = 0; mt < 4; mt++)
                #pragma unroll
                for (int nt = 0; nt < 4; nt++)
                    mma_bf16(acc[mt][nt], af[mt], blf[nt]);
            #pragma unroll
            for (int mt = 0; mt < 4; mt++)
                ldm_x4(af[mt], base + TILEB + aOff + mt * (16 * 80) + kb);
            #pragma unroll
            for (int mt = 0; mt < 4; mt++)
                #pragma unroll
                for (int nt = 0; nt < 4; nt++)
                    mma_bf16(acc[mt][nt], af[mt], bhf[nt]);
        }
        __syncthreads();
    }

    int g = lane >> 2, tq = lane & 3;
    #pragma unroll
    for (int mt = 0; mt < 4; mt++) {
        int mbase = m0 + wm * 64 + mt * 16 + g;
        #pragma unroll
        for (int nt = 0; nt < 4; nt++) {
            int n = n0 + wn * 32 + nt * 8 + tq * 2;
            float2 v0 = make_float2(acc[mt][nt][0], acc[mt][nt][1]);
            float2 v1 = make_float2(acc[mt][nt][2], acc[mt][nt][3]);
            if (BIAS) {
                float2 bb = *(const float2*)(bias + n);
                v0.x += bb.x; v0.y += bb.y; v1.x += bb.x; v1.y += bb.y;
            }
            if (RELU) {
                v0.x = fmaxf(v0.x, 0.f); v0.y = fmaxf(v0.y, 0.f);
                v1.x = fmaxf(v1.x, 0.f); v1.y = fmaxf(v1.y, 0.f);
            }
            if (RES) {
                float2 q0 = *(const float2*)(Res + (size_t)mbase * N + n);
                float2 q1 = *(const float2*)(Res + (size_t)(mbase + 8) * N + n);
                v0.x += q0.x; v0.y += q0.y; v1.x += q1.x; v1.y += q1.y;
            }
            *(float2*)(C + (size_t)mbase * N + n) = v0;
            *(float2*)(C + (size_t)(mbase + 8) * N + n) = v1;
        }
    }
}

// ---------------- tensor-core flash attention (split-bf16) --------------------
// Block: 64 queries x (head, batch), 128 threads (4 warps, 16 q-rows each).
// S = Qh.Kh^T + Qh.Kl^T + Ql.Kh^T ; O += Ph.Vh + Ph.Vl + Pl.Vh (P from regs).
#define ALD  144                    // smem row stride bytes (64 bf16 + 8 pad)
#define ATB  (64 * ALD)             // 9216 bytes per tile
#define ASTG (4 * ATB)              // Kh, Kl, Vth, Vtl
#define ATT_SMEM (2 * ATB + 2 * ASTG)   // Qh,Ql + 2 stages = 92160

__global__ void __launch_bounds__(128) attn_tc_kernel(
    const __nv_bfloat16* __restrict__ Qh, const __nv_bfloat16* __restrict__ Ql,
    const __nv_bfloat16* __restrict__ Kh, const __nv_bfloat16* __restrict__ Kl,
    const __nv_bfloat16* __restrict__ Vth, const __nv_bfloat16* __restrict__ Vtl,
    float* __restrict__ O)
{
    extern __shared__ char smc[];
    const uint32_t sb = smem_u32(smc);
    int qt = (int)gridDim.x - 1 - (int)blockIdx.x;   // heavy tiles first
    int h = blockIdx.y, b = blockIdx.z;
    int tid = threadIdx.x;
    int wm = tid >> 5, lane = tid & 31;

    // ---- loaders: per array, thread covers 4 16B chunks: slot = tid*4+i ----
    auto load_kv = [&](int t, int st) {
        uint32_t base = sb + 2 * ATB + st * ASTG;
        #pragma unroll
        for (int i = 0; i < 4; i++) {
            int slot = tid * 4 + i;
            int r = slot >> 3, c = slot & 7;
            size_t gk = (size_t)(b * SEQL + t * 64 + r) * DM + h * DH + c * 8;
            size_t gv = ((size_t)(b * NH + h) * DH + r) * SEQL + t * 64 + c * 8;
            uint32_t so = (uint32_t)(r * ALD + c * 16);
            cpa16(base + so,           Kh + gk);
            cpa16(base + ATB + so,     Kl + gk);
            cpa16(base + 2 * ATB + so, Vth + gv);
            cpa16(base + 3 * ATB + so, Vtl + gv);
        }
    };

    // Q tiles + key tile 0 in group 0
    #pragma unroll
    for (int i = 0; i < 4; i++) {
        int slot = tid * 4 + i;
        int r = slot >> 3, c = slot & 7;
        size_t gq = (size_t)(b * SEQL + qt * 64 + r) * DM + h * DH + c * 8;
        uint32_t so = (uint32_t)(r * ALD + c * 16);
        cpa16(sb + so,       Qh + gq);
        cpa16(sb + ATB + so, Ql + gq);
    }
    load_kv(0, 0);
    CP_COMMIT();

    float oacc[8][4];
    #pragma unroll
    for (int nt = 0; nt < 8; nt++)
        #pragma unroll
        for (int j = 0; j < 4; j++) oacc[nt][j] = 0.f;
    float mrow[2] = {-INFINITY, -INFINITY};
    float lrow[2] = {0.f, 0.f};

    uint32_t aOff = (uint32_t)((wm * 16 + (lane & 15)) * ALD + (lane >> 4) * 16);
    int bm = lane >> 3, brr = lane & 7;
    uint32_t bOff = (uint32_t)((((bm & 2) ? 8 : 0) + brr) * ALD + ((bm & 1) ? 16 : 0));

    for (int t = 0; t <= qt; t++) {
        int st = t & 1;
        if (t < qt) { load_kv(t + 1, st ^ 1); CP_COMMIT(); CP_WAIT(1); }
        else        { CP_WAIT(0); }
        __syncthreads();

        uint32_t kbase = sb + 2 * ATB + st * ASTG;

        // ---- scores ----
        float sacc[8][4];
        #pragma unroll
        for (int nt = 0; nt < 8; nt++)
            #pragma unroll
            for (int j = 0; j < 4; j++) sacc[nt][j] = 0.f;

        #pragma unroll
        for (int kt = 0; kt < 4; kt++) {
            uint32_t kb = kt * 32;
            uint32_t ah[4], al[4];
            ldm_x4(ah, sb + aOff + kb);
            ldm_x4(al, sb + ATB + aOff + kb);
            #pragma unroll
            for (int p = 0; p < 4; p++) {
                uint32_t t4[4];
                ldm_x4(t4, kbase + bOff + p * (16 * ALD) + kb);
                uint32_t b0[2] = {t4[0], t4[1]}, b1[2] = {t4[2], t4[3]};
                mma_bf16(sacc[2*p],   ah, b0);
                mma_bf16(sacc[2*p+1], ah, b1);
                mma_bf16(sacc[2*p],   al, b0);
                mma_bf16(sacc[2*p+1], al, b1);
                ldm_x4(t4, kbase + ATB + bOff + p * (16 * ALD) + kb);
                uint32_t c0[2] = {t4[0], t4[1]}, c1[2] = {t4[2], t4[3]};
                mma_bf16(sacc[2*p],   ah, c0);
                mma_bf16(sacc[2*p+1], ah, c1);
            }
        }

        // ---- scale + causal mask ----
        int g = lane >> 2, colb = (lane & 3) * 2;
        bool diag = (t == qt);
        #pragma unroll
        for (int nt = 0; nt < 8; nt++)
            #pragma unroll
            for (int j = 0; j < 4; j++) {
                float s = sacc[nt][j] * 0.125f;
                if (diag) {
                    int col = nt * 8 + colb + (j & 1);
                    int qr  = wm * 16 + g + ((j >= 2) ? 8 : 0);
                    if (col > qr) s = -1e30f;
                }
                sacc[nt][j] = s;
            }

        // ---- online softmax (rows g and g+8; 4 lanes share a row) ----
        float mt0 = -INFINITY, mt1 = -INFINITY;
        #pragma unroll
        for (int nt = 0; nt < 8; nt++) {
            mt0 = fmaxf(mt0, fmaxf(sacc[nt][0], sacc[nt][1]));
            mt1 = fmaxf(mt1, fmaxf(sacc[nt][2], sacc[nt][3]));
        }
        mt0 = fmaxf(mt0, __shfl_xor_sync(0xffffffffu, mt0, 1));
        mt0 = fmaxf(mt0, __shfl_xor_sync(0xffffffffu, mt0, 2));
        mt1 = fmaxf(mt1, __shfl_xor_sync(0xffffffffu, mt1, 1));
        mt1 = fmaxf(mt1, __shfl_xor_sync(0xffffffffu, mt1, 2));
        float mn0 = fmaxf(mrow[0], mt0), mn1 = fmaxf(mrow[1], mt1);
        float sc0 = __expf(mrow[0] - mn0), sc1 = __expf(mrow[1] - mn1);
        float lt0 = 0.f, lt1 = 0.f;
        #pragma unroll
        for (int nt = 0; nt < 8; nt++) {
            float p0 = __expf(sacc[nt][0] - mn0);
            float p1 = __expf(sacc[nt][1] - mn0);
            float p2 = __expf(sacc[nt][2] - mn1);
            float p3 = __expf(sacc[nt][3] - mn1);
            sacc[nt][0] = p0; sacc[nt][1] = p1; sacc[nt][2] = p2; sacc[nt][3] = p3;
            lt0 += p0 + p1; lt1 += p2 + p3;
        }
        lt0 += __shfl_xor_sync(0xffffffffu, lt0, 1);
        lt0 += __shfl_xor_sync(0xffffffffu, lt0, 2);
        lt1 += __shfl_xor_sync(0xffffffffu, lt1, 1);
        lt1 += __shfl_xor_sync(0xffffffffu, lt1, 2);
        lrow[0] = lrow[0] * sc0 + lt0;
        lrow[1] = lrow[1] * sc1 + lt1;
        mrow[0] = mn0; mrow[1] = mn1;
        #pragma unroll
        for (int nt = 0; nt < 8; nt++) {
            oacc[nt][0] *= sc0; oacc[nt][1] *= sc0;
            oacc[nt][2] *= sc1; oacc[nt][3] *= sc1;
        }

        // ---- O += P @ V  (P fragments built from registers) ----
        #pragma unroll
        for (int kk = 0; kk < 4; kk++) {
            float p00 = sacc[2*kk][0],   p01 = sacc[2*kk][1];
            float p02 = sacc[2*kk][2],   p03 = sacc[2*kk][3];
            float p10 = sacc[2*kk+1][0], p11 = sacc[2*kk+1][1];
            float p12 = sacc[2*kk+1][2], p13 = sacc[2*kk+1][3];
            float h00 = __bfloat162float(__float2bfloat16(p00));
            float h01 = __bfloat162float(__float2bfloat16(p01));
            float h02 = __bfloat162float(__float2bfloat16(p02));
            float h03 = __bfloat162float(__float2bfloat16(p03));
            float h10 = __bfloat162float(__float2bfloat16(p10));
            float h11 = __bfloat162float(__float2bfloat16(p11));
            float h12 = __bfloat162float(__float2bfloat16(p12));
            float h13 = __bfloat162float(__float2bfloat16(p13));
            uint32_t pah[4], pal[4];
            pah[0] = packbf2(h00, h01); pah[1] = packbf2(h02, h03);
            pah[2] = packbf2(h10, h11); pah[3] = packbf2(h12, h13);
            pal[0] = packbf2(p00 - h00, p01 - h01);
            pal[1] = packbf2(p02 - h02, p03 - h03);
            pal[2] = packbf2(p10 - h10, p11 - h11);
            pal[3] = packbf2(p12 - h12, p13 - h13);

            uint32_t kb = kk * 32;
            #pragma unroll
            for (int p = 0; p < 4; p++) {
                uint32_t t4[4];
                ldm_x4(t4, kbase + 2 * ATB + bOff + p * (16 * ALD) + kb);
                uint32_t b0[2] = {t4[0], t4[1]}, b1[2] = {t4[2], t4[3]};
                mma_bf16(oacc[2*p],   pah, b0);
                mma_bf16(oacc[2*p+1], pah, b1);
                mma_bf16(oacc[2*p],   pal, b0);
                mma_bf16(oacc[2*p+1], pal, b1);
                ldm_x4(t4, kbase + 3 * ATB + bOff + p * (16 * ALD) + kb);
                uint32_t c0[2] = {t4[0], t4[1]}, c1[2] = {t4[2], t4[3]};
                mma_bf16(oacc[2*p],   pah, c0);
                mma_bf16(oacc[2*p+1], pah, c1);
            }
        }
        __syncthreads();
    }

    // ---- epilogue ----
    float inv0 = 1.0f / lrow[0], inv1 = 1.0f / lrow[1];
    int g = lane >> 2, tq = lane & 3;
    int row0 = qt * 64 + wm * 16 + g;
    #pragma unroll
    for (int nt = 0; nt < 8; nt++) {
        int d = h * DH + nt * 8 + tq * 2;
        *(float2*)(O + (size_t)(b * SEQL + row0) * DM + d) =
            make_float2(oacc[nt][0] * inv0, oacc[nt][1] * inv0);
        *(float2*)(O + (size_t)(b * SEQL + row0 + 8) * DM + d) =
            make_float2(oacc[nt][2] * inv1, oacc[nt][3] * inv1);
    }
}

// ---------------- launch ----------------
extern "C" void kernel_launch(void* const* d_in, const int* in_sizes, int n_in,
                              void* d_out, int out_size)
{
    const float* x   = (const float*)d_in[0];
    const float* wq  = (const float*)d_in[1];
    const float* wk  = (const float*)d_in[2];
    const float* wv  = (const float*)d_in[3];
    const float* wo  = (const float*)d_in[4];
    const float* w1  = (const float*)d_in[5];
    const float* b1  = (const float*)d_in[6];
    const float* w2  = (const float*)d_in[7];
    const float* b2  = (const float*)d_in[8];
    const float* g1  = (const float*)d_in[9];
    const float* be1 = (const float*)d_in[10];
    const float* g2  = (const float*)d_in[11];
    const float* be2 = (const float*)d_in[12];
    float* out = (float*)d_out;

    float *xn, *q, *k, *v, *attn, *x1, *hid;
    cudaGetSymbolAddress((void**)&xn,   g_xn);
    cudaGetSymbolAddress((void**)&q,    g_q);
    cudaGetSymbolAddress((void**)&k,    g_k);
    cudaGetSymbolAddress((void**)&v,    g_v);
    cudaGetSymbolAddress((void**)&attn, g_attn);
    cudaGetSymbolAddress((void**)&x1,   g_x1);
    cudaGetSymbolAddress((void**)&hid,  g_hid);

    __nv_bfloat16 *ah, *al, *hh, *hl, *qh, *ql, *kh, *kl, *vth, *vtl;
    __nv_bfloat16 *wqh, *wql, *wkh, *wkl, *wvh, *wvl, *woh, *wol, *w1h, *w1l, *w2h, *w2l;
    cudaGetSymbolAddress((void**)&ah,  g_act_h);
    cudaGetSymbolAddress((void**)&al,  g_act_l);
    cudaGetSymbolAddress((void**)&hh,  g_hid_h);
    cudaGetSymbolAddress((void**)&hl,  g_hid_l);
    cudaGetSymbolAddress((void**)&qh,  g_qh);   cudaGetSymbolAddress((void**)&ql,  g_ql);
    cudaGetSymbolAddress((void**)&kh,  g_kh);   cudaGetSymbolAddress((void**)&kl,  g_kl);
    cudaGetSymbolAddress((void**)&vth, g_vth);  cudaGetSymbolAddress((void**)&vtl, g_vtl);
    cudaGetSymbolAddress((void**)&wqh, g_wq_h); cudaGetSymbolAddress((void**)&wql, g_wq_l);
    cudaGetSymbolAddress((void**)&wkh, g_wk_h); cudaGetSymbolAddress((void**)&wkl, g_wk_l);
    cudaGetSymbolAddress((void**)&wvh, g_wv_h); cudaGetSymbolAddress((void**)&wvl, g_wv_l);
    cudaGetSymbolAddress((void**)&woh, g_wo_h); cudaGetSymbolAddress((void**)&wol, g_wo_l);
    cudaGetSymbolAddress((void**)&w1h, g_w1_h); cudaGetSymbolAddress((void**)&w1l, g_w1_l);
    cudaGetSymbolAddress((void**)&w2h, g_w2_h); cudaGetSymbolAddress((void**)&w2l, g_w2_l);

    cudaFuncSetAttribute(attn_tc_kernel, cudaFuncAttributeMaxDynamicSharedMemorySize,
                         ATT_SMEM);
    cudaFuncSetAttribute(tc_gemm_kernel<false, false, false>,
                         cudaFuncAttributeMaxDynamicSharedMemorySize, GEMM_SMEM);
    cudaFuncSetAttribute(tc_gemm_kernel<false, false, true>,
                         cudaFuncAttributeMaxDynamicSharedMemorySize, GEMM_SMEM);
    cudaFuncSetAttribute(tc_gemm_kernel<true, true, false>,
                         cudaFuncAttributeMaxDynamicSharedMemorySize, GEMM_SMEM);
    cudaFuncSetAttribute(tc_gemm_kernel<true, false, true>,
                         cudaFuncAttributeMaxDynamicSharedMemorySize, GEMM_SMEM);

    dim3 t32(32, 8);
    // weight transpose+split
    tsplit_kernel<<<dim3(DM / 32, DM / 32), t32>>>(wq, wqh, wql, DM, DM);
    tsplit_kernel<<<dim3(DM / 32, DM / 32), t32>>>(wk, wkh, wkl, DM, DM);
    tsplit_kernel<<<dim3(DM / 32, DM / 32), t32>>>(wv, wvh, wvl, DM, DM);
    tsplit_kernel<<<dim3(DM / 32, DM / 32), t32>>>(wo, woh, wol, DM, DM);
    tsplit_kernel<<<dim3(HID / 32, DM / 32), t32>>>(w1, w1h, w1l, DM, HID);
    tsplit_kernel<<<dim3(DM / 32, HID / 32), t32>>>(w2, w2h, w2l, HID, DM);

    // LN1 + activation split
    ln_kernel<<<TOK, 128>>>(x, g1, be1, xn);
    split_kernel<<<TOK * DM / (256 * 8), 256>>>(xn, ah, al);

    // QKV projections
    dim3 gqkv(DM / 128, TOK / 128);
    tc_gemm_kernel<false, false, false><<<gqkv, 256, GEMM_SMEM>>>(
        ah, al, wqh, wql, nullptr, nullptr, q, TOK, DM, DM);
    tc_gemm_kernel<false, false, false><<<gqkv, 256, GEMM_SMEM>>>(
        ah, al, wkh, wkl, nullptr, nullptr, k, TOK, DM, DM);
    tc_gemm_kernel<false, false, false><<<gqkv, 256, GEMM_SMEM>>>(
        ah, al, wvh, wvl, nullptr, nullptr, v, TOK, DM, DM);

    // attention operand splits
    split_kernel<<<TOK * DM / (256 * 8), 256>>>(q, qh, ql);
    split_kernel<<<TOK * DM / (256 * 8), 256>>>(k, kh, kl);
    vtrans_split_kernel<<<dim3(SEQL / 32, DH / 32, NB * NH), t32>>>(v, vth, vtl);

    // tensor-core attention
    attn_tc_kernel<<<dim3(SEQL / 64, NH, NB), 128, ATT_SMEM>>>(
        qh, ql, kh, kl, vth, vtl, attn);

    // O projection + residual
    split_kernel<<<TOK * DM / (256 * 8), 256>>>(attn, ah, al);
    tc_gemm_kernel<false, false, true><<<gqkv, 256, GEMM_SMEM>>>(
        ah, al, woh, wol, nullptr, x, x1, TOK, DM, DM);

    // LN2 + split
    ln_kernel<<<TOK, 128>>>(x1, g2, be2, xn);
    split_kernel<<<TOK * DM / (256 * 8), 256>>>(xn, ah, al);

    // FFN1: relu(xn @ w1 + b1)
    tc_gemm_kernel<true, true, false><<<dim3(HID / 128, TOK / 128), 256, GEMM_SMEM>>>(
        ah, al, w1h, w1l, b1, nullptr, hid, TOK, HID, DM);
    split_kernel<<<TOK * HID / (256 * 8), 256>>>(hid, hh, hl);

    // FFN2: hid @ w2 + b2 + x1 -> out
    tc_gemm_kernel<true, false, true><<<gqkv, 256, GEMM_SMEM>>>(
        hh, hl, w2h, w2l, b2, x1, out, TOK, DM, HID);
}

// round 6
// speedup vs baseline: 14.9542x; 2.0520x over previous
#include <cuda_runtime.h>
#include <cuda_fp16.h>
#include <math.h>
#include <stdint.h>

#define TOK   4096   // B*S tokens
#define DM    1024
#define HID   4096
#define SEQL  2048
#define NB    2
#define NH    16
#define DH    64

// ---------------- scratch (allocation-free: __device__ globals) ----------------
__device__ float g_x1[TOK * DM];                       // residual after attention
__device__ __align__(256) __half g_xnh[TOK * DM];      // LN output, fp16
__device__ __align__(256) __half g_q16[TOK * DM];
__device__ __align__(256) __half g_k16[TOK * DM];
__device__ __align__(256) __half g_v16[TOK * DM];
__device__ __align__(256) __half g_vt16[TOK * DM];     // [b][h][d][key]
__device__ __align__(256) __half g_attn16[TOK * DM];
__device__ __align__(256) __half g_hid16[TOK * HID];
// weights transposed to [N,K] fp16
__device__ __align__(256) __half g_wq16[DM * DM];
__device__ __align__(256) __half g_wk16[DM * DM];
__device__ __align__(256) __half g_wv16[DM * DM];
__device__ __align__(256) __half g_wo16[DM * DM];
__device__ __align__(256) __half g_w116[DM * HID];
__device__ __align__(256) __half g_w216[HID * DM];

// ---------------- base-target PTX helpers ----------------
__device__ __forceinline__ uint32_t smem_u32(const void* p) {
    uint32_t a;
    asm("{ .reg .u64 t; cvta.to.shared.u64 t, %1; cvt.u32.u64 %0, t; }"
        : "=r"(a) : "l"(p));
    return a;
}
__device__ __forceinline__ void cpa16(uint32_t s, const void* g) {
    asm volatile("cp.async.cg.shared.global [%0], [%1], 16;" :: "r"(s), "l"(g));
}
#define CP_COMMIT() asm volatile("cp.async.commit_group;" ::: "memory")
#define CP_WAIT(n)  asm volatile("cp.async.wait_group %0;" :: "n"(n) : "memory")

__device__ __forceinline__ void ldm_x4(uint32_t* r, uint32_t addr) {
    asm volatile("ldmatrix.sync.aligned.m8n8.x4.shared.b16 {%0,%1,%2,%3}, [%4];"
                 : "=r"(r[0]), "=r"(r[1]), "=r"(r[2]), "=r"(r[3]) : "r"(addr));
}
__device__ __forceinline__ void mma_f16(float* d, const uint32_t* a, const uint32_t* b) {
    asm volatile(
        "mma.sync.aligned.m16n8k16.row.col.f32.f16.f16.f32 "
        "{%0,%1,%2,%3}, {%4,%5,%6,%7}, {%8,%9}, {%0,%1,%2,%3};"
        : "+f"(d[0]), "+f"(d[1]), "+f"(d[2]), "+f"(d[3])
        : "r"(a[0]), "r"(a[1]), "r"(a[2]), "r"(a[3]), "r"(b[0]), "r"(b[1]));
}
__device__ __forceinline__ uint32_t packh2(float lo, float hi) {
    __half2 t = __floats2half2_rn(lo, hi);
    return *(uint32_t*)&t;
}

// ---------------- LayerNorm -> fp16 ----------------
__global__ void ln_kernel(const float* __restrict__ x,
                          const float* __restrict__ gamma,
                          const float* __restrict__ beta,
                          __half* __restrict__ out)
{
    int t   = blockIdx.x;
    int tid = threadIdx.x;
    const float4* xr = (const float4*)(x + (size_t)t * DM);
    float4 v0 = xr[tid];
    float4 v1 = xr[tid + 128];
    float s  = v0.x + v0.y + v0.z + v0.w + v1.x + v1.y + v1.z + v1.w;
    float ss = v0.x*v0.x + v0.y*v0.y + v0.z*v0.z + v0.w*v0.w
             + v1.x*v1.x + v1.y*v1.y + v1.z*v1.z + v1.w*v1.w;
    #pragma unroll
    for (int o = 16; o; o >>= 1) {
        s  += __shfl_xor_sync(0xffffffffu, s,  o);
        ss += __shfl_xor_sync(0xffffffffu, ss, o);
    }
    __shared__ float sm_s[4], sm_ss[4];
    int w = tid >> 5, ln = tid & 31;
    if (ln == 0) { sm_s[w] = s; sm_ss[w] = ss; }
    __syncthreads();
    s  = sm_s[0] + sm_s[1] + sm_s[2] + sm_s[3];
    ss = sm_ss[0] + sm_ss[1] + sm_ss[2] + sm_ss[3];
    float mu   = s * (1.0f / DM);
    float var  = ss * (1.0f / DM) - mu * mu;
    float rstd = rsqrtf(var + 1e-5f);

    const float4* gr = (const float4*)gamma;
    const float4* br = (const float4*)beta;
    __half* oh = out + (size_t)t * DM;
    #pragma unroll
    for (int u = 0; u < 2; u++) {
        int i = tid + u * 128;
        float4 xv = xr[i], gv = gr[i], bv = br[i];
        float rx = (xv.x - mu) * rstd * gv.x + bv.x;
        float ry = (xv.y - mu) * rstd * gv.y + bv.y;
        float rz = (xv.z - mu) * rstd * gv.z + bv.z;
        float rw = (xv.w - mu) * rstd * gv.w + bv.w;
        uint2 pk;
        pk.x = packh2(rx, ry);
        pk.y = packh2(rz, rw);
        *(uint2*)(oh + i * 4) = pk;
    }
}

// ---------------- transpose: w[K,N] fp32 -> t16[N,K] fp16 ---------------------
__global__ void tsplit_kernel(const float* __restrict__ w,
                              __half* __restrict__ th, int K, int N)
{
    __shared__ float t[32][33];
    int tx = threadIdx.x, ty = threadIdx.y;
    int n0 = blockIdx.x * 32, k0 = blockIdx.y * 32;
    #pragma unroll
    for (int i = 0; i < 4; i++)
        t[ty + i * 8][tx] = w[(size_t)(k0 + ty + i * 8) * N + n0 + tx];
    __syncthreads();
    #pragma unroll
    for (int i = 0; i < 4; i++)
        th[(size_t)(n0 + ty + i * 8) * K + k0 + tx] = __float2half_rn(t[tx][ty + i * 8]);
}

// ---- per-(b,h) transpose of V fp16: v[b*S+s][h*64+d] -> vt[(b*NH+h)*64+d][s]
__global__ void vtrans_kernel(const __half* __restrict__ v,
                              __half* __restrict__ vt)
{
    __shared__ __half t[32][40];
    int tx = threadIdx.x, ty = threadIdx.y;
    int bh = blockIdx.z;
    int b = bh / NH, h = bh % NH;
    int s0 = blockIdx.x * 32, d0 = blockIdx.y * 32;
    #pragma unroll
    for (int i = 0; i < 4; i++)
        t[ty + i * 8][tx] = v[(size_t)(b * SEQL + s0 + ty + i * 8) * DM + h * DH + d0 + tx];
    __syncthreads();
    #pragma unroll
    for (int i = 0; i < 4; i++)
        vt[((size_t)bh * DH + d0 + ty + i * 8) * SEQL + s0 + tx] = t[tx][ty + i * 8];
}

// ---------------- mma.sync fp16 GEMM ----------------
// C[M,N] = A[M,K] @ B[N,K]^T, fp16 operands, fp32 accumulate.
// CTA 128x128, BK=32, 8 warps each 64m x 32n, cp.async double-buffered.
#define LDT    40                        // smem row stride in fp16 (80 bytes)
#define TILEB  (128 * LDT * 2)           // 10240 bytes per tile array
#define STAGEB (2 * TILEB)               // A, B
#define GEMM_SMEM (2 * STAGEB)           // 40960 bytes

template<bool BIAS, bool RELU, bool RES, bool OUTH>
__global__ void __launch_bounds__(256) tc_gemm_kernel(
    const __half* __restrict__ A, const __half* __restrict__ B,
    const float* __restrict__ bias, const float* __restrict__ Res,
    float* __restrict__ Cf, __half* __restrict__ Ch, int M, int N, int K)
{
    extern __shared__ char smem[];
    const uint32_t sb = smem_u32(smem);
    int tid = threadIdx.x;
    int wid = tid >> 5, lane = tid & 31;
    int wm = wid & 1, wn = wid >> 1;
    int m0 = blockIdx.y * 128, n0 = blockIdx.x * 128;

    float acc[4][4][4];
    #pragma unroll
    for (int i = 0; i < 4; i++)
        #pragma unroll
        for (int j = 0; j < 4; j++)
            #pragma unroll
            for (int r = 0; r < 4; r++) acc[i][j][r] = 0.f;

    int r0 = (tid * 2) >> 2,      c0 = (tid * 2) & 3;
    int r1 = (tid * 2 + 1) >> 2,  c1 = (tid * 2 + 1) & 3;
    int nc = K >> 5;

    auto load_chunk = [&](int c, int st) {
        int kc = c << 5;
        uint32_t base = sb + st * STAGEB;
        size_t ga0 = (size_t)(m0 + r0) * K + kc + c0 * 8;
        size_t ga1 = (size_t)(m0 + r1) * K + kc + c1 * 8;
        size_t gb0 = (size_t)(n0 + r0) * K + kc + c0 * 8;
        size_t gb1 = (size_t)(n0 + r1) * K + kc + c1 * 8;
        uint32_t s0 = r0 * 80 + c0 * 16, s1 = r1 * 80 + c1 * 16;
        cpa16(base + s0,          A + ga0);
        cpa16(base + s1,          A + ga1);
        cpa16(base + TILEB + s0,  B + gb0);
        cpa16(base + TILEB + s1,  B + gb1);
        CP_COMMIT();
    };

    load_chunk(0, 0);

    int aRow = wm * 64 + (lane & 15);
    uint32_t aOff = (uint32_t)(aRow * 80 + (lane >> 4) * 16);
    int bm = lane >> 3, br = lane & 7;
    int bRow = wn * 32 + ((bm & 2) ? 8 : 0) + br;
    uint32_t bOff = (uint32_t)(bRow * 80 + ((bm & 1) ? 16 : 0));

    for (int c = 0; c < nc; c++) {
        int st = c & 1;
        if (c + 1 < nc) { load_chunk(c + 1, st ^ 1); CP_WAIT(1); }
        else            { CP_WAIT(0); }
        __syncthreads();

        uint32_t base = sb + st * STAGEB;
        #pragma unroll
        for (int ks = 0; ks < 2; ks++) {
            uint32_t kb = ks * 32;
            uint32_t af[4][4], bf[4][2];
            #pragma unroll
            for (int mt = 0; mt < 4; mt++)
                ldm_x4(af[mt], base + aOff + mt * (16 * 80) + kb);
            #pragma unroll
            for (int p = 0; p < 2; p++) {
                uint32_t t4[4];
                ldm_x4(t4, base + TILEB + bOff + p * (16 * 80) + kb);
                bf[2*p][0] = t4[0]; bf[2*p][1] = t4[1];
                bf[2*p+1][0] = t4[2]; bf[2*p+1][1] = t4[3];
            }
            #pragma unroll
            for (int mt = 0; mt < 4; mt++)
                #pragma unroll
                for (int nt = 0; nt < 4; nt++)
                    mma_f16(acc[mt][nt], af[mt], bf[nt]);
        }
        __syncthreads();
    }

    int g = lane >> 2, tq = lane & 3;
    #pragma unroll
    for (int mt = 0; mt < 4; mt++) {
        int mbase = m0 + wm * 64 + mt * 16 + g;
        #pragma unroll
        for (int nt = 0; nt < 4; nt++) {
            int n = n0 + wn * 32 + nt * 8 + tq * 2;
            float2 v0 = make_float2(acc[mt][nt][0], acc[mt][nt][1]);
            float2 v1 = make_float2(acc[mt][nt][2], acc[mt][nt][3]);
            if (BIAS) {
                float2 bb = *(const float2*)(bias + n);
                v0.x += bb.x; v0.y += bb.y; v1.x += bb.x; v1.y += bb.y;
            }
            if (RELU) {
                v0.x = fmaxf(v0.x, 0.f); v0.y = fmaxf(v0.y, 0.f);
                v1.x = fmaxf(v1.x, 0.f); v1.y = fmaxf(v1.y, 0.f);
            }
            if (RES) {
                float2 q0 = *(const float2*)(Res + (size_t)mbase * N + n);
                float2 q1 = *(const float2*)(Res + (size_t)(mbase + 8) * N + n);
                v0.x += q0.x; v0.y += q0.y; v1.x += q1.x; v1.y += q1.y;
            }
            if (OUTH) {
                *(uint32_t*)(Ch + (size_t)mbase * N + n)       = packh2(v0.x, v0.y);
                *(uint32_t*)(Ch + (size_t)(mbase + 8) * N + n) = packh2(v1.x, v1.y);
            } else {
                *(float2*)(Cf + (size_t)mbase * N + n) = v0;
                *(float2*)(Cf + (size_t)(mbase + 8) * N + n) = v1;
            }
        }
    }
}

// ---------------- tensor-core flash attention (fp16) --------------------------
// Block: 64 queries x (head, batch), 128 threads (4 warps, 16 q-rows each).
#define ALD  144                    // smem row stride bytes (64 fp16 + 8 pad)
#define ATB  (64 * ALD)             // 9216 bytes per tile
#define ASTG (2 * ATB)              // K, Vt
#define ATT_SMEM (ATB + 2 * ASTG)   // Q + 2 stages = 46080

__global__ void __launch_bounds__(128) attn_tc_kernel(
    const __half* __restrict__ Q, const __half* __restrict__ K,
    const __half* __restrict__ Vt, __half* __restrict__ O)
{
    extern __shared__ char smc[];
    const uint32_t sb = smem_u32(smc);
    int qt = (int)gridDim.x - 1 - (int)blockIdx.x;   // heavy tiles first
    int h = blockIdx.y, b = blockIdx.z;
    int tid = threadIdx.x;
    int wm = tid >> 5, lane = tid & 31;

    auto load_kv = [&](int t, int st) {
        uint32_t base = sb + ATB + st * ASTG;
        #pragma unroll
        for (int i = 0; i < 4; i++) {
            int slot = tid * 4 + i;
            int r = slot >> 3, c = slot & 7;
            size_t gk = (size_t)(b * SEQL + t * 64 + r) * DM + h * DH + c * 8;
            size_t gv = ((size_t)(b * NH + h) * DH + r) * SEQL + t * 64 + c * 8;
            uint32_t so = (uint32_t)(r * ALD + c * 16);
            cpa16(base + so,       K + gk);
            cpa16(base + ATB + so, Vt + gv);
        }
    };

    #pragma unroll
    for (int i = 0; i < 4; i++) {
        int slot = tid * 4 + i;
        int r = slot >> 3, c = slot & 7;
        size_t gq = (size_t)(b * SEQL + qt * 64 + r) * DM + h * DH + c * 8;
        cpa16(sb + (uint32_t)(r * ALD + c * 16), Q + gq);
    }
    load_kv(0, 0);
    CP_COMMIT();

    float oacc[8][4];
    #pragma unroll
    for (int nt = 0; nt < 8; nt++)
        #pragma unroll
        for (int j = 0; j < 4; j++) oacc[nt][j] = 0.f;
    float mrow[2] = {-INFINITY, -INFINITY};
    float lrow[2] = {0.f, 0.f};

    uint32_t aOff = (uint32_t)((wm * 16 + (lane & 15)) * ALD + (lane >> 4) * 16);
    int bm = lane >> 3, brr = lane & 7;
    uint32_t bOff = (uint32_t)((((bm & 2) ? 8 : 0) + brr) * ALD + ((bm & 1) ? 16 : 0));

    for (int t = 0; t <= qt; t++) {
        int st = t & 1;
        if (t < qt) { load_kv(t + 1, st ^ 1); CP_COMMIT(); CP_WAIT(1); }
        else        { CP_WAIT(0); }
        __syncthreads();

        uint32_t kbase = sb + ATB + st * ASTG;
        uint32_t vbase = kbase + ATB;

        // ---- scores ----
        float sacc[8][4];
        #pragma unroll
        for (int nt = 0; nt < 8; nt++)
            #pragma unroll
            for (int j = 0; j < 4; j++) sacc[nt][j] = 0.f;

        #pragma unroll
        for (int kt = 0; kt < 4; kt++) {
            uint32_t kb = kt * 32;
            uint32_t a4[4];
            ldm_x4(a4, sb + aOff + kb);
            #pragma unroll
            for (int p = 0; p < 4; p++) {
                uint32_t t4[4];
                ldm_x4(t4, kbase + bOff + p * (16 * ALD) + kb);
                uint32_t b0[2] = {t4[0], t4[1]}, b1[2] = {t4[2], t4[3]};
                mma_f16(sacc[2*p],   a4, b0);
                mma_f16(sacc[2*p+1], a4, b1);
            }
        }

        // ---- scale + causal mask ----
        int g = lane >> 2, colb = (lane & 3) * 2;
        bool diag = (t == qt);
        #pragma unroll
        for (int nt = 0; nt < 8; nt++)
            #pragma unroll
            for (int j = 0; j < 4; j++) {
                float s = sacc[nt][j] * 0.125f;
                if (diag) {
                    int col = nt * 8 + colb + (j & 1);
                    int qr  = wm * 16 + g + ((j >= 2) ? 8 : 0);
                    if (col > qr) s = -1e30f;
                }
                sacc[nt][j] = s;
            }

        // ---- online softmax ----
        float mt0 = -INFINITY, mt1 = -INFINITY;
        #pragma unroll
        for (int nt = 0; nt < 8; nt++) {
            mt0 = fmaxf(mt0, fmaxf(sacc[nt][0], sacc[nt][1]));
            mt1 = fmaxf(mt1, fmaxf(sacc[nt][2], sacc[nt][3]));
        }
        mt0 = fmaxf(mt0, __shfl_xor_sync(0xffffffffu, mt0, 1));
        mt0 = fmaxf(mt0, __shfl_xor_sync(0xffffffffu, mt0, 2));
        mt1 = fmaxf(mt1, __shfl_xor_sync(0xffffffffu, mt1, 1));
        mt1 = fmaxf(mt1, __shfl_xor_sync(0xffffffffu, mt1, 2));
        float mn0 = fmaxf(mrow[0], mt0), mn1 = fmaxf(mrow[1], mt1);
        float sc0 = __expf(mrow[0] - mn0), sc1 = __expf(mrow[1] - mn1);
        float lt0 = 0.f, lt1 = 0.f;
        #pragma unroll
        for (int nt = 0; nt < 8; nt++) {
            float p0 = __expf(sacc[nt][0] - mn0);
            float p1 = __expf(sacc[nt][1] - mn0);
            float p2 = __expf(sacc[nt][2] - mn1);
            float p3 = __expf(sacc[nt][3] - mn1);
            sacc[nt][0] = p0; sacc[nt][1] = p1; sacc[nt][2] = p2; sacc[nt][3] = p3;
            lt0 += p0 + p1; lt1 += p2 + p3;
        }
        lt0 += __shfl_xor_sync(0xffffffffu, lt0, 1);
        lt0 += __shfl_xor_sync(0xffffffffu, lt0, 2);
        lt1 += __shfl_xor_sync(0xffffffffu, lt1, 1);
        lt1 += __shfl_xor_sync(0xffffffffu, lt1, 2);
        lrow[0] = lrow[0] * sc0 + lt0;
        lrow[1] = lrow[1] * sc1 + lt1;
        mrow[0] = mn0; mrow[1] = mn1;
        #pragma unroll
        for (int nt = 0; nt < 8; nt++) {
            oacc[nt][0] *= sc0; oacc[nt][1] *= sc0;
            oacc[nt][2] *= sc1; oacc[nt][3] *= sc1;
        }

        // ---- O += P @ V (P fragments built from registers, fp16) ----
        #pragma unroll
        for (int kk = 0; kk < 4; kk++) {
            uint32_t pa[4];
            pa[0] = packh2(sacc[2*kk][0],   sacc[2*kk][1]);
            pa[1] = packh2(sacc[2*kk][2],   sacc[2*kk][3]);
            pa[2] = packh2(sacc[2*kk+1][0], sacc[2*kk+1][1]);
            pa[3] = packh2(sacc[2*kk+1][2], sacc[2*kk+1][3]);
            uint32_t kb = kk * 32;
            #pragma unroll
            for (int p = 0; p < 4; p++) {
                uint32_t t4[4];
                ldm_x4(t4, vbase + bOff + p * (16 * ALD) + kb);
                uint32_t b0[2] = {t4[0], t4[1]}, b1[2] = {t4[2], t4[3]};
                mma_f16(oacc[2*p],   pa, b0);
                mma_f16(oacc[2*p+1], pa, b1);
            }
        }
        __syncthreads();
    }

    // ---- epilogue: fp16 out ----
    float inv0 = 1.0f / lrow[0], inv1 = 1.0f / lrow[1];
    int g = lane >> 2, tq = lane & 3;
    int row0 = qt * 64 + wm * 16 + g;
    #pragma unroll
    for (int nt = 0; nt < 8; nt++) {
        int d = h * DH + nt * 8 + tq * 2;
        *(uint32_t*)(O + (size_t)(b * SEQL + row0) * DM + d) =
            packh2(oacc[nt][0] * inv0, oacc[nt][1] * inv0);
        *(uint32_t*)(O + (size_t)(b * SEQL + row0 + 8) * DM + d) =
            packh2(oacc[nt][2] * inv1, oacc[nt][3] * inv1);
    }
}

// ---------------- launch ----------------
extern "C" void kernel_launch(void* const* d_in, const int* in_sizes, int n_in,
                              void* d_out, int out_size)
{
    const float* x   = (const float*)d_in[0];
    const float* wq  = (const float*)d_in[1];
    const float* wk  = (const float*)d_in[2];
    const float* wv  = (const float*)d_in[3];
    const float* wo  = (const float*)d_in[4];
    const float* w1  = (const float*)d_in[5];
    const float* b1  = (const float*)d_in[6];
    const float* w2  = (const float*)d_in[7];
    const float* b2  = (const float*)d_in[8];
    const float* g1  = (const float*)d_in[9];
    const float* be1 = (const float*)d_in[10];
    const float* g2  = (const float*)d_in[11];
    const float* be2 = (const float*)d_in[12];
    float* out = (float*)d_out;

    float* x1;
    cudaGetSymbolAddress((void**)&x1, g_x1);
    __half *xnh, *q16, *k16, *v16, *vt16, *attn16, *hid16;
    __half *wq16, *wk16, *wv16, *wo16, *w116, *w216;
    cudaGetSymbolAddress((void**)&xnh,    g_xnh);
    cudaGetSymbolAddress((void**)&q16,    g_q16);
    cudaGetSymbolAddress((void**)&k16,    g_k16);
    cudaGetSymbolAddress((void**)&v16,    g_v16);
    cudaGetSymbolAddress((void**)&vt16,   g_vt16);
    cudaGetSymbolAddress((void**)&attn16, g_attn16);
    cudaGetSymbolAddress((void**)&hid16,  g_hid16);
    cudaGetSymbolAddress((void**)&wq16,   g_wq16);
    cudaGetSymbolAddress((void**)&wk16,   g_wk16);
    cudaGetSymbolAddress((void**)&wv16,   g_wv16);
    cudaGetSymbolAddress((void**)&wo16,   g_wo16);
    cudaGetSymbolAddress((void**)&w116,   g_w116);
    cudaGetSymbolAddress((void**)&w216,   g_w216);

    cudaFuncSetAttribute(attn_tc_kernel, cudaFuncAttributeMaxDynamicSharedMemorySize,
                         ATT_SMEM);
    cudaFuncSetAttribute(tc_gemm_kernel<false, false, false, true>,
                         cudaFuncAttributeMaxDynamicSharedMemorySize, GEMM_SMEM);
    cudaFuncSetAttribute(tc_gemm_kernel<false, false, true, false>,
                         cudaFuncAttributeMaxDynamicSharedMemorySize, GEMM_SMEM);
    cudaFuncSetAttribute(tc_gemm_kernel<true, true, false, true>,
                         cudaFuncAttributeMaxDynamicSharedMemorySize, GEMM_SMEM);
    cudaFuncSetAttribute(tc_gemm_kernel<true, false, true, false>,
                         cudaFuncAttributeMaxDynamicSharedMemorySize, GEMM_SMEM);

    dim3 t32(32, 8);
    // weight transpose -> fp16 [N,K]
    tsplit_kernel<<<dim3(DM / 32, DM / 32), t32>>>(wq, wq16, DM, DM);
    tsplit_kernel<<<dim3(DM / 32, DM / 32), t32>>>(wk, wk16, DM, DM);
    tsplit_kernel<<<dim3(DM / 32, DM / 32), t32>>>(wv, wv16, DM, DM);
    tsplit_kernel<<<dim3(DM / 32, DM / 32), t32>>>(wo, wo16, DM, DM);
    tsplit_kernel<<<dim3(HID / 32, DM / 32), t32>>>(w1, w116, DM, HID);
    tsplit_kernel<<<dim3(DM / 32, HID / 32), t32>>>(w2, w216, HID, DM);

    // LN1 -> fp16
    ln_kernel<<<TOK, 128>>>(x, g1, be1, xnh);

    // QKV projections -> fp16 outputs
    dim3 gqkv(DM / 128, TOK / 128);
    tc_gemm_kernel<false, false, false, true><<<gqkv, 256, GEMM_SMEM>>>(
        xnh, wq16, nullptr, nullptr, nullptr, q16, TOK, DM, DM);
    tc_gemm_kernel<false, false, false, true><<<gqkv, 256, GEMM_SMEM>>>(
        xnh, wk16, nullptr, nullptr, nullptr, k16, TOK, DM, DM);
    tc_gemm_kernel<false, false, false, true><<<gqkv, 256, GEMM_SMEM>>>(
        xnh, wv16, nullptr, nullptr, nullptr, v16, TOK, DM, DM);

    // V transpose per (b,h)
    vtrans_kernel<<<dim3(SEQL / 32, DH / 32, NB * NH), t32>>>(v16, vt16);

    // tensor-core attention -> fp16
    attn_tc_kernel<<<dim3(SEQL / 64, NH, NB), 128, ATT_SMEM>>>(q16, k16, vt16, attn16);

    // O projection + residual(x) -> x1 (fp32)
    tc_gemm_kernel<false, false, true, false><<<gqkv, 256, GEMM_SMEM>>>(
        attn16, wo16, nullptr, x, x1, nullptr, TOK, DM, DM);

    // LN2 -> fp16
    ln_kernel<<<TOK, 128>>>(x1, g2, be2, xnh);

    // FFN1: relu(xn @ w1 + b1) -> fp16 hid
    tc_gemm_kernel<true, true, false, true><<<dim3(HID / 128, TOK / 128), 256, GEMM_SMEM>>>(
        xnh, w116, b1, nullptr, nullptr, hid16, TOK, HID, DM);

    // FFN2: hid @ w2 + b2 + x1 -> out (fp32)
    tc_gemm_kernel<true, false, true, false><<<gqkv, 256, GEMM_SMEM>>>(
        hid16, w216, b2, x1, out, nullptr, TOK, DM, HID);
}

// round 7
// speedup vs baseline: 18.6024x; 1.2440x over previous
#include <cuda_runtime.h>
#include <cuda_fp16.h>
#include <math.h>
#include <stdint.h>

#define TOK   4096   // B*S tokens
#define DM    1024
#define HID   4096
#define SEQL  2048
#define NB    2
#define NH    16
#define DH    64

// ---------------- scratch (allocation-free: __device__ globals) ----------------
__device__ float g_x1[TOK * DM];                         // residual after attention
__device__ __align__(256) __half g_xnh[TOK * DM];        // LN output, fp16
__device__ __align__(256) __half g_qkv16[3 * TOK * DM];  // fused q|k|v
__device__ __align__(256) __half g_vt16[TOK * DM];       // [b][h][d][key]
__device__ __align__(256) __half g_attn16[TOK * DM];
__device__ __align__(256) __half g_hid16[TOK * HID];
// weights transposed to [N,K] fp16
__device__ __align__(256) __half g_wqkv16[3 * DM * DM];  // fused wq|wk|wv rows
__device__ __align__(256) __half g_wo16[DM * DM];
__device__ __align__(256) __half g_w116[DM * HID];
__device__ __align__(256) __half g_w216[HID * DM];

// ---------------- base-target PTX helpers ----------------
__device__ __forceinline__ uint32_t smem_u32(const void* p) {
    uint32_t a;
    asm("{ .reg .u64 t; cvta.to.shared.u64 t, %1; cvt.u32.u64 %0, t; }"
        : "=r"(a) : "l"(p));
    return a;
}
__device__ __forceinline__ void cpa16(uint32_t s, const void* g) {
    asm volatile("cp.async.cg.shared.global [%0], [%1], 16;" :: "r"(s), "l"(g));
}
#define CP_COMMIT() asm volatile("cp.async.commit_group;" ::: "memory")
#define CP_WAIT(n)  asm volatile("cp.async.wait_group %0;" :: "n"(n) : "memory")

__device__ __forceinline__ void ldm_x4(uint32_t* r, uint32_t addr) {
    asm volatile("ldmatrix.sync.aligned.m8n8.x4.shared.b16 {%0,%1,%2,%3}, [%4];"
                 : "=r"(r[0]), "=r"(r[1]), "=r"(r[2]), "=r"(r[3]) : "r"(addr));
}
__device__ __forceinline__ void mma_f16(float* d, const uint32_t* a, const uint32_t* b) {
    asm volatile(
        "mma.sync.aligned.m16n8k16.row.col.f32.f16.f16.f32 "
        "{%0,%1,%2,%3}, {%4,%5,%6,%7}, {%8,%9}, {%0,%1,%2,%3};"
        : "+f"(d[0]), "+f"(d[1]), "+f"(d[2]), "+f"(d[3])
        : "r"(a[0]), "r"(a[1]), "r"(a[2]), "r"(a[3]), "r"(b[0]), "r"(b[1]));
}
__device__ __forceinline__ uint32_t packh2(float lo, float hi) {
    __half2 t = __floats2half2_rn(lo, hi);
    return *(uint32_t*)&t;
}

// ---------------- LayerNorm -> fp16 ----------------
__global__ void ln_kernel(const float* __restrict__ x,
                          const float* __restrict__ gamma,
                          const float* __restrict__ beta,
                          __half* __restrict__ out)
{
    int t   = blockIdx.x;
    int tid = threadIdx.x;
    const float4* xr = (const float4*)(x + (size_t)t * DM);
    float4 v0 = xr[tid];
    float4 v1 = xr[tid + 128];
    float s  = v0.x + v0.y + v0.z + v0.w + v1.x + v1.y + v1.z + v1.w;
    float ss = v0.x*v0.x + v0.y*v0.y + v0.z*v0.z + v0.w*v0.w
             + v1.x*v1.x + v1.y*v1.y + v1.z*v1.z + v1.w*v1.w;
    #pragma unroll
    for (int o = 16; o; o >>= 1) {
        s  += __shfl_xor_sync(0xffffffffu, s,  o);
        ss += __shfl_xor_sync(0xffffffffu, ss, o);
    }
    __shared__ float sm_s[4], sm_ss[4];
    int w = tid >> 5, ln = tid & 31;
    if (ln == 0) { sm_s[w] = s; sm_ss[w] = ss; }
    __syncthreads();
    s  = sm_s[0] + sm_s[1] + sm_s[2] + sm_s[3];
    ss = sm_ss[0] + sm_ss[1] + sm_ss[2] + sm_ss[3];
    float mu   = s * (1.0f / DM);
    float var  = ss * (1.0f / DM) - mu * mu;
    float rstd = rsqrtf(var + 1e-5f);

    const float4* gr = (const float4*)gamma;
    const float4* br = (const float4*)beta;
    __half* oh = out + (size_t)t * DM;
    #pragma unroll
    for (int u = 0; u < 2; u++) {
        int i = tid + u * 128;
        float4 xv = xr[i], gv = gr[i], bv = br[i];
        float rx = (xv.x - mu) * rstd * gv.x + bv.x;
        float ry = (xv.y - mu) * rstd * gv.y + bv.y;
        float rz = (xv.z - mu) * rstd * gv.z + bv.z;
        float rw = (xv.w - mu) * rstd * gv.w + bv.w;
        uint2 pk;
        pk.x = packh2(rx, ry);
        pk.y = packh2(rz, rw);
        *(uint2*)(oh + i * 4) = pk;
    }
}

// ---------------- transpose: w[K,N] fp32 -> t16[N,K] fp16 ---------------------
__global__ void tsplit_kernel(const float* __restrict__ w,
                              __half* __restrict__ th, int K, int N)
{
    __shared__ float t[32][33];
    int tx = threadIdx.x, ty = threadIdx.y;
    int n0 = blockIdx.x * 32, k0 = blockIdx.y * 32;
    #pragma unroll
    for (int i = 0; i < 4; i++)
        t[ty + i * 8][tx] = w[(size_t)(k0 + ty + i * 8) * N + n0 + tx];
    __syncthreads();
    #pragma unroll
    for (int i = 0; i < 4; i++)
        th[(size_t)(n0 + ty + i * 8) * K + k0 + tx] = __float2half_rn(t[tx][ty + i * 8]);
}

// ---- per-(b,h) transpose of V fp16: v[b*S+s][h*64+d] -> vt[(b*NH+h)*64+d][s]
__global__ void vtrans_kernel(const __half* __restrict__ v,
                              __half* __restrict__ vt)
{
    __shared__ __half t[32][40];
    int tx = threadIdx.x, ty = threadIdx.y;
    int bh = blockIdx.z;
    int b = bh / NH, h = bh % NH;
    int s0 = blockIdx.x * 32, d0 = blockIdx.y * 32;
    #pragma unroll
    for (int i = 0; i < 4; i++)
        t[ty + i * 8][tx] = v[(size_t)(b * SEQL + s0 + ty + i * 8) * DM + h * DH + d0 + tx];
    __syncthreads();
    #pragma unroll
    for (int i = 0; i < 4; i++)
        vt[((size_t)bh * DH + d0 + ty + i * 8) * SEQL + s0 + tx] = t[tx][ty + i * 8];
}

// ---------------- mma.sync fp16 GEMM, 256x128 CTA tile ------------------------
// C[M,N] = A[M,K] @ B[N,K]^T. 8 warps (4m x 2n), warp tile 64x64, BK=64,
// 3-stage cp.async ring. Row stride 144B (64 halfs + 8 pad), conflict-free ldm.
#define GLDA      144
#define GA_BYTES  (256 * GLDA)             // 36864
#define GB_BYTES  (128 * GLDA)             // 18432
#define GSTAGE    (GA_BYTES + GB_BYTES)    // 55296
#define GEMM_SMEM (3 * GSTAGE)             // 165888

template<bool BIAS, bool RELU, bool RES, bool OUTH, bool QKVOUT>
__global__ void __launch_bounds__(256) tc_gemm_kernel(
    const __half* __restrict__ A, const __half* __restrict__ B,
    const float* __restrict__ bias, const float* __restrict__ Res,
    float* __restrict__ Cf, __half* __restrict__ Ch, int M, int N, int K)
{
    extern __shared__ char smem[];
    const uint32_t sb = smem_u32(smem);
    int tid = threadIdx.x;
    int wid = tid >> 5, lane = tid & 31;
    int wm = wid & 3, wn = wid >> 2;                 // warp tile: rows wm*64, cols wn*64
    int m0 = blockIdx.y * 256, n0 = blockIdx.x * 128;

    float acc[4][8][4];
    #pragma unroll
    for (int i = 0; i < 4; i++)
        #pragma unroll
        for (int j = 0; j < 8; j++)
            #pragma unroll
            for (int r = 0; r < 4; r++) acc[i][j][r] = 0.f;

    int nc = K >> 6;

    auto load_chunk = [&](int c, int st) {
        int kc = c << 6;
        uint32_t base = sb + st * GSTAGE;
        #pragma unroll
        for (int i = 0; i < 12; i++) {
            int slot = tid + (i << 8);
            if (slot < 2048) {                 // A: 256 rows x 8 chunks
                int r = slot >> 3, ch = slot & 7;
                cpa16(base + r * GLDA + ch * 16,
                      A + (size_t)(m0 + r) * K + kc + ch * 8);
            } else {                           // B: 128 rows x 8 chunks
                int s2 = slot - 2048;
                int r = s2 >> 3, ch = s2 & 7;
                cpa16(base + GA_BYTES + r * GLDA + ch * 16,
                      B + (size_t)(n0 + r) * K + kc + ch * 8);
            }
        }
        CP_COMMIT();
    };

    load_chunk(0, 0);
    load_chunk(1, 1);
    load_chunk(2, 2);

    uint32_t aOff = (uint32_t)((wm * 64 + (lane & 15)) * GLDA + (lane >> 4) * 16);
    int bm = lane >> 3, brr = lane & 7;
    uint32_t bOff = (uint32_t)((wn * 64 + ((bm & 2) ? 8 : 0) + brr) * GLDA
                               + ((bm & 1) ? 16 : 0));

    for (int c = 0; c < nc; c++) {
        int st = c % 3;
        CP_WAIT(2);
        __syncthreads();
        uint32_t base = sb + st * GSTAGE;
        #pragma unroll
        for (int ks = 0; ks < 4; ks++) {
            uint32_t kb = ks * 32;
            uint32_t af[4][4], bf[8][2];
            #pragma unroll
            for (int mt = 0; mt < 4; mt++)
                ldm_x4(af[mt], base + aOff + mt * (16 * GLDA) + kb);
            #pragma unroll
            for (int p = 0; p < 4; p++) {
                uint32_t t4[4];
                ldm_x4(t4, base + GA_BYTES + bOff + p * (16 * GLDA) + kb);
                bf[2*p][0] = t4[0]; bf[2*p][1] = t4[1];
                bf[2*p+1][0] = t4[2]; bf[2*p+1][1] = t4[3];
            }
            #pragma unroll
            for (int mt = 0; mt < 4; mt++)
                #pragma unroll
                for (int nt = 0; nt < 8; nt++)
                    mma_f16(acc[mt][nt], af[mt], bf[nt]);
        }
        __syncthreads();
        if (c + 3 < nc) load_chunk(c + 3, st);
        else            CP_COMMIT();           // keep group counting aligned
    }

    int g = lane >> 2, tq = lane & 3;
    #pragma unroll
    for (int mt = 0; mt < 4; mt++) {
        int mbase = m0 + wm * 64 + mt * 16 + g;
        #pragma unroll
        for (int nt = 0; nt < 8; nt++) {
            int n = n0 + wn * 64 + nt * 8 + tq * 2;
            float2 v0 = make_float2(acc[mt][nt][0], acc[mt][nt][1]);
            float2 v1 = make_float2(acc[mt][nt][2], acc[mt][nt][3]);
            if (BIAS) {
                float2 bb = *(const float2*)(bias + n);
                v0.x += bb.x; v0.y += bb.y; v1.x += bb.x; v1.y += bb.y;
            }
            if (RELU) {
                v0.x = fmaxf(v0.x, 0.f); v0.y = fmaxf(v0.y, 0.f);
                v1.x = fmaxf(v1.x, 0.f); v1.y = fmaxf(v1.y, 0.f);
            }
            if (RES) {
                float2 q0 = *(const float2*)(Res + (size_t)mbase * N + n);
                float2 q1 = *(const float2*)(Res + (size_t)(mbase + 8) * N + n);
                v0.x += q0.x; v0.y += q0.y; v1.x += q1.x; v1.y += q1.y;
            }
            if (QKVOUT) {
                int which = n >> 10, nn = n & 1023;
                __half* dst = Ch + (size_t)which * (TOK * DM) + (size_t)mbase * DM + nn;
                *(uint32_t*)dst                    = packh2(v0.x, v0.y);
                *(uint32_t*)(dst + (size_t)8 * DM) = packh2(v1.x, v1.y);
            } else if (OUTH) {
                *(uint32_t*)(Ch + (size_t)mbase * N + n)       = packh2(v0.x, v0.y);
                *(uint32_t*)(Ch + (size_t)(mbase + 8) * N + n) = packh2(v1.x, v1.y);
            } else {
                *(float2*)(Cf + (size_t)mbase * N + n) = v0;
                *(float2*)(Cf + (size_t)(mbase + 8) * N + n) = v1;
            }
        }
    }
}

// ---------------- tensor-core flash attention (fp16, 128-query CTAs) ----------
// Block: 128 queries x (head, batch), 256 threads (8 warps, 16 q-rows each).
#define ALD  144                    // smem row stride bytes (64 fp16 + 8 pad)
#define ATB  (64 * ALD)             // 9216 bytes per 64-row tile
#define QTB  (128 * ALD)            // 18432 Q tile
#define ASTG (2 * ATB)              // K, Vt per stage
#define ATT_SMEM (QTB + 2 * ASTG)   // 55296

__global__ void __launch_bounds__(256) attn_tc_kernel(
    const __half* __restrict__ Q, const __half* __restrict__ K,
    const __half* __restrict__ Vt, __half* __restrict__ O)
{
    extern __shared__ char smc[];
    const uint32_t sb = smem_u32(smc);
    int qt = (int)gridDim.x - 1 - (int)blockIdx.x;   // heavy tiles first
    int h = blockIdx.y, b = blockIdx.z;
    int tid = threadIdx.x;
    int wm = tid >> 5, lane = tid & 31;

    auto load_kv = [&](int t, int st) {
        uint32_t base = sb + QTB + st * ASTG;
        #pragma unroll
        for (int i = 0; i < 2; i++) {
            int slot = tid * 2 + i;
            int r = slot >> 3, c = slot & 7;
            size_t gk = (size_t)(b * SEQL + t * 64 + r) * DM + h * DH + c * 8;
            size_t gv = ((size_t)(b * NH + h) * DH + r) * SEQL + t * 64 + c * 8;
            uint32_t so = (uint32_t)(r * ALD + c * 16);
            cpa16(base + so,       K + gk);
            cpa16(base + ATB + so, Vt + gv);
        }
    };

    #pragma unroll
    for (int i = 0; i < 4; i++) {
        int slot = tid * 4 + i;
        int r = slot >> 3, c = slot & 7;     // r 0..127
        size_t gq = (size_t)(b * SEQL + qt * 128 + r) * DM + h * DH + c * 8;
        cpa16(sb + (uint32_t)(r * ALD + c * 16), Q + gq);
    }
    load_kv(0, 0);
    CP_COMMIT();

    float oacc[8][4];
    #pragma unroll
    for (int nt = 0; nt < 8; nt++)
        #pragma unroll
        for (int j = 0; j < 4; j++) oacc[nt][j] = 0.f;
    float mrow[2] = {-INFINITY, -INFINITY};
    float lrow[2] = {0.f, 0.f};

    uint32_t aOff = (uint32_t)((wm * 16 + (lane & 15)) * ALD + (lane >> 4) * 16);
    int bm = lane >> 3, brr = lane & 7;
    uint32_t bOff = (uint32_t)(((bm & 2) ? 8 : 0) * ALD + brr * ALD + ((bm & 1) ? 16 : 0));

    int ntile = 2 * qt + 2;
    for (int t = 0; t < ntile; t++) {
        int st = t & 1;
        if (t + 1 < ntile) { load_kv(t + 1, st ^ 1); CP_COMMIT(); CP_WAIT(1); }
        else               { CP_WAIT(0); }
        __syncthreads();

        uint32_t kbase = sb + QTB + st * ASTG;
        uint32_t vbase = kbase + ATB;

        // ---- scores ----
        float sacc[8][4];
        #pragma unroll
        for (int nt = 0; nt < 8; nt++)
            #pragma unroll
            for (int j = 0; j < 4; j++) sacc[nt][j] = 0.f;

        #pragma unroll
        for (int kt = 0; kt < 4; kt++) {
            uint32_t kb = kt * 32;
            uint32_t a4[4];
            ldm_x4(a4, sb + aOff + kb);
            #pragma unroll
            for (int p = 0; p < 4; p++) {
                uint32_t t4[4];
                ldm_x4(t4, kbase + bOff + p * (16 * ALD) + kb);
                uint32_t b0[2] = {t4[0], t4[1]}, b1[2] = {t4[2], t4[3]};
                mma_f16(sacc[2*p],   a4, b0);
                mma_f16(sacc[2*p+1], a4, b1);
            }
        }

        // ---- scale + causal mask (only the last two key tiles can clip) ----
        int g = lane >> 2, colb = (lane & 3) * 2;
        bool diag = (t >= 2 * qt);
        #pragma unroll
        for (int nt = 0; nt < 8; nt++)
            #pragma unroll
            for (int j = 0; j < 4; j++) {
                float s = sacc[nt][j] * 0.125f;
                if (diag) {
                    int col = t * 64 + nt * 8 + colb + (j & 1);
                    int qr  = qt * 128 + wm * 16 + g + ((j >= 2) ? 8 : 0);
                    if (col > qr) s = -1e30f;
                }
                sacc[nt][j] = s;
            }

        // ---- online softmax ----
        float mt0 = -INFINITY, mt1 = -INFINITY;
        #pragma unroll
        for (int nt = 0; nt < 8; nt++) {
            mt0 = fmaxf(mt0, fmaxf(sacc[nt][0], sacc[nt][1]));
            mt1 = fmaxf(mt1, fmaxf(sacc[nt][2], sacc[nt][3]));
        }
        mt0 = fmaxf(mt0, __shfl_xor_sync(0xffffffffu, mt0, 1));
        mt0 = fmaxf(mt0, __shfl_xor_sync(0xffffffffu, mt0, 2));
        mt1 = fmaxf(mt1, __shfl_xor_sync(0xffffffffu, mt1, 1));
        mt1 = fmaxf(mt1, __shfl_xor_sync(0xffffffffu, mt1, 2));
        float mn0 = fmaxf(mrow[0], mt0), mn1 = fmaxf(mrow[1], mt1);
        float sc0 = __expf(mrow[0] - mn0), sc1 = __expf(mrow[1] - mn1);
        float lt0 = 0.f, lt1 = 0.f;
        #pragma unroll
        for (int nt = 0; nt < 8; nt++) {
            float p0 = __expf(sacc[nt][0] - mn0);
            float p1 = __expf(sacc[nt][1] - mn0);
            float p2 = __expf(sacc[nt][2] - mn1);
            float p3 = __expf(sacc[nt][3] - mn1);
            sacc[nt][0] = p0; sacc[nt][1] = p1; sacc[nt][2] = p2; sacc[nt][3] = p3;
            lt0 += p0 + p1; lt1 += p2 + p3;
        }
        lt0 += __shfl_xor_sync(0xffffffffu, lt0, 1);
        lt0 += __shfl_xor_sync(0xffffffffu, lt0, 2);
        lt1 += __shfl_xor_sync(0xffffffffu, lt1, 1);
        lt1 += __shfl_xor_sync(0xffffffffu, lt1, 2);
        lrow[0] = lrow[0] * sc0 + lt0;
        lrow[1] = lrow[1] * sc1 + lt1;
        mrow[0] = mn0; mrow[1] = mn1;
        #pragma unroll
        for (int nt = 0; nt < 8; nt++) {
            oacc[nt][0] *= sc0; oacc[nt][1] *= sc0;
            oacc[nt][2] *= sc1; oacc[nt][3] *= sc1;
        }

        // ---- O += P @ V (P fragments from registers) ----
        #pragma unroll
        for (int kk = 0; kk < 4; kk++) {
            uint32_t pa[4];
            pa[0] = packh2(sacc[2*kk][0],   sacc[2*kk][1]);
            pa[1] = packh2(sacc[2*kk][2],   sacc[2*kk][3]);
            pa[2] = packh2(sacc[2*kk+1][0], sacc[2*kk+1][1]);
            pa[3] = packh2(sacc[2*kk+1][2], sacc[2*kk+1][3]);
            uint32_t kb = kk * 32;
            #pragma unroll
            for (int p = 0; p < 4; p++) {
                uint32_t t4[4];
                ldm_x4(t4, vbase + bOff + p * (16 * ALD) + kb);
                uint32_t b0[2] = {t4[0], t4[1]}, b1[2] = {t4[2], t4[3]};
                mma_f16(oacc[2*p],   pa, b0);
                mma_f16(oacc[2*p+1], pa, b1);
            }
        }
        __syncthreads();
    }

    // ---- epilogue: fp16 out ----
    float inv0 = 1.0f / lrow[0], inv1 = 1.0f / lrow[1];
    int g = lane >> 2, tq = lane & 3;
    int row0 = qt * 128 + wm * 16 + g;
    #pragma unroll
    for (int nt = 0; nt < 8; nt++) {
        int d = h * DH + nt * 8 + tq * 2;
        *(uint32_t*)(O + (size_t)(b * SEQL + row0) * DM + d) =
            packh2(oacc[nt][0] * inv0, oacc[nt][1] * inv0);
        *(uint32_t*)(O + (size_t)(b * SEQL + row0 + 8) * DM + d) =
            packh2(oacc[nt][2] * inv1, oacc[nt][3] * inv1);
    }
}

// ---------------- launch ----------------
extern "C" void kernel_launch(void* const* d_in, const int* in_sizes, int n_in,
                              void* d_out, int out_size)
{
    const float* x   = (const float*)d_in[0];
    const float* wq  = (const float*)d_in[1];
    const float* wk  = (const float*)d_in[2];
    const float* wv  = (const float*)d_in[3];
    const float* wo  = (const float*)d_in[4];
    const float* w1  = (const float*)d_in[5];
    const float* b1  = (const float*)d_in[6];
    const float* w2  = (const float*)d_in[7];
    const float* b2  = (const float*)d_in[8];
    const float* g1  = (const float*)d_in[9];
    const float* be1 = (const float*)d_in[10];
    const float* g2  = (const float*)d_in[11];
    const float* be2 = (const float*)d_in[12];
    float* out = (float*)d_out;

    float* x1;
    cudaGetSymbolAddress((void**)&x1, g_x1);
    __half *xnh, *qkv16, *vt16, *attn16, *hid16;
    __half *wqkv16, *wo16, *w116, *w216;
    cudaGetSymbolAddress((void**)&xnh,    g_xnh);
    cudaGetSymbolAddress((void**)&qkv16,  g_qkv16);
    cudaGetSymbolAddress((void**)&vt16,   g_vt16);
    cudaGetSymbolAddress((void**)&attn16, g_attn16);
    cudaGetSymbolAddress((void**)&hid16,  g_hid16);
    cudaGetSymbolAddress((void**)&wqkv16, g_wqkv16);
    cudaGetSymbolAddress((void**)&wo16,   g_wo16);
    cudaGetSymbolAddress((void**)&w116,   g_w116);
    cudaGetSymbolAddress((void**)&w216,   g_w216);
    __half* q16 = qkv16;
    __half* k16 = qkv16 + (size_t)TOK * DM;
    __half* v16 = qkv16 + 2 * (size_t)TOK * DM;

    cudaFuncSetAttribute(attn_tc_kernel, cudaFuncAttributeMaxDynamicSharedMemorySize,
                         ATT_SMEM);
    cudaFuncSetAttribute(tc_gemm_kernel<false, false, false, true, true>,
                         cudaFuncAttributeMaxDynamicSharedMemorySize, GEMM_SMEM);
    cudaFuncSetAttribute(tc_gemm_kernel<false, false, true, false, false>,
                         cudaFuncAttributeMaxDynamicSharedMemorySize, GEMM_SMEM);
    cudaFuncSetAttribute(tc_gemm_kernel<true, true, false, true, false>,
                         cudaFuncAttributeMaxDynamicSharedMemorySize, GEMM_SMEM);
    cudaFuncSetAttribute(tc_gemm_kernel<true, false, true, false, false>,
                         cudaFuncAttributeMaxDynamicSharedMemorySize, GEMM_SMEM);

    dim3 t32(32, 8);
    // weight transposes -> fp16 [N,K]; wq|wk|wv stacked into wqkv
    tsplit_kernel<<<dim3(DM / 32, DM / 32), t32>>>(wq, wqkv16, DM, DM);
    tsplit_kernel<<<dim3(DM / 32, DM / 32), t32>>>(wk, wqkv16 + (size_t)DM * DM, DM, DM);
    tsplit_kernel<<<dim3(DM / 32, DM / 32), t32>>>(wv, wqkv16 + 2 * (size_t)DM * DM, DM, DM);
    tsplit_kernel<<<dim3(DM / 32, DM / 32), t32>>>(wo, wo16, DM, DM);
    tsplit_kernel<<<dim3(HID / 32, DM / 32), t32>>>(w1, w116, DM, HID);
    tsplit_kernel<<<dim3(DM / 32, HID / 32), t32>>>(w2, w216, HID, DM);

    // LN1 -> fp16
    ln_kernel<<<TOK, 128>>>(x, g1, be1, xnh);

    // fused QKV projection (N=3072) -> q|k|v fp16
    tc_gemm_kernel<false, false, false, true, true>
        <<<dim3(3 * DM / 128, TOK / 256), 256, GEMM_SMEM>>>(
        xnh, wqkv16, nullptr, nullptr, nullptr, qkv16, TOK, 3 * DM, DM);

    // V transpose per (b,h)
    vtrans_kernel<<<dim3(SEQL / 32, DH / 32, NB * NH), t32>>>(v16, vt16);

    // tensor-core attention -> fp16
    attn_tc_kernel<<<dim3(SEQL / 128, NH, NB), 256, ATT_SMEM>>>(q16, k16, vt16, attn16);

    // O projection + residual(x) -> x1 (fp32)
    tc_gemm_kernel<false, false, true, false, false>
        <<<dim3(DM / 128, TOK / 256), 256, GEMM_SMEM>>>(
        attn16, wo16, nullptr, x, x1, nullptr, TOK, DM, DM);

    // LN2 -> fp16
    ln_kernel<<<TOK, 128>>>(x1, g2, be2, xnh);

    // FFN1: relu(xn @ w1 + b1) -> fp16 hid
    tc_gemm_kernel<true, true, false, true, false>
        <<<dim3(HID / 128, TOK / 256), 256, GEMM_SMEM>>>(
        xnh, w116, b1, nullptr, nullptr, hid16, TOK, HID, DM);

    // FFN2: hid @ w2 + b2 + x1 -> out (fp32)
    tc_gemm_kernel<true, false, true, false, false>
        <<<dim3(DM / 128, TOK / 256), 256, GEMM_SMEM>>>(
        hid16, w216, b2, x1, out, nullptr, TOK, DM, HID);
}

// round 8
// speedup vs baseline: 19.4291x; 1.0444x over previous
#include <cuda_runtime.h>
#include <cuda_fp16.h>
#include <math.h>
#include <stdint.h>

#define TOK   4096   // B*S tokens
#define DM    1024
#define HID   4096
#define SEQL  2048
#define NB    2
#define NH    16
#define DH    64

// ---------------- scratch (allocation-free: __device__ globals) ----------------
__device__ float g_x1[TOK * DM];                         // residual after attention
__device__ __align__(256) __half g_xnh[TOK * DM];        // LN output, fp16
__device__ __align__(256) __half g_qkv16[3 * TOK * DM];  // fused q|k|v
__device__ __align__(256) __half g_attn16[TOK * DM];
__device__ __align__(256) __half g_hid16[TOK * HID];
// weights transposed to [N,K] fp16
__device__ __align__(256) __half g_wqkv16[3 * DM * DM];  // fused wq|wk|wv rows
__device__ __align__(256) __half g_wo16[DM * DM];
__device__ __align__(256) __half g_w116[DM * HID];
__device__ __align__(256) __half g_w216[HID * DM];

// ---------------- base-target PTX helpers ----------------
__device__ __forceinline__ uint32_t smem_u32(const void* p) {
    uint32_t a;
    asm("{ .reg .u64 t; cvta.to.shared.u64 t, %1; cvt.u32.u64 %0, t; }"
        : "=r"(a) : "l"(p));
    return a;
}
__device__ __forceinline__ void cpa16(uint32_t s, const void* g) {
    asm volatile("cp.async.cg.shared.global [%0], [%1], 16;" :: "r"(s), "l"(g));
}
#define CP_COMMIT() asm volatile("cp.async.commit_group;" ::: "memory")
#define CP_WAIT(n)  asm volatile("cp.async.wait_group %0;" :: "n"(n) : "memory")

__device__ __forceinline__ void ldm_x4(uint32_t* r, uint32_t addr) {
    asm volatile("ldmatrix.sync.aligned.m8n8.x4.shared.b16 {%0,%1,%2,%3}, [%4];"
                 : "=r"(r[0]), "=r"(r[1]), "=r"(r[2]), "=r"(r[3]) : "r"(addr));
}
__device__ __forceinline__ void ldm_x4_t(uint32_t* r, uint32_t addr) {
    asm volatile("ldmatrix.sync.aligned.m8n8.x4.trans.shared.b16 {%0,%1,%2,%3}, [%4];"
                 : "=r"(r[0]), "=r"(r[1]), "=r"(r[2]), "=r"(r[3]) : "r"(addr));
}
__device__ __forceinline__ void mma_f16(float* d, const uint32_t* a, const uint32_t* b) {
    asm volatile(
        "mma.sync.aligned.m16n8k16.row.col.f32.f16.f16.f32 "
        "{%0,%1,%2,%3}, {%4,%5,%6,%7}, {%8,%9}, {%0,%1,%2,%3};"
        : "+f"(d[0]), "+f"(d[1]), "+f"(d[2]), "+f"(d[3])
        : "r"(a[0]), "r"(a[1]), "r"(a[2]), "r"(a[3]), "r"(b[0]), "r"(b[1]));
}
__device__ __forceinline__ uint32_t packh2(float lo, float hi) {
    __half2 t = __floats2half2_rn(lo, hi);
    return *(uint32_t*)&t;
}

// ---------------- LayerNorm -> fp16 ----------------
__global__ void ln_kernel(const float* __restrict__ x,
                          const float* __restrict__ gamma,
                          const float* __restrict__ beta,
                          __half* __restrict__ out)
{
    int t   = blockIdx.x;
    int tid = threadIdx.x;
    const float4* xr = (const float4*)(x + (size_t)t * DM);
    float4 v0 = xr[tid];
    float4 v1 = xr[tid + 128];
    float s  = v0.x + v0.y + v0.z + v0.w + v1.x + v1.y + v1.z + v1.w;
    float ss = v0.x*v0.x + v0.y*v0.y + v0.z*v0.z + v0.w*v0.w
             + v1.x*v1.x + v1.y*v1.y + v1.z*v1.z + v1.w*v1.w;
    #pragma unroll
    for (int o = 16; o; o >>= 1) {
        s  += __shfl_xor_sync(0xffffffffu, s,  o);
        ss += __shfl_xor_sync(0xffffffffu, ss, o);
    }
    __shared__ float sm_s[4], sm_ss[4];
    int w = tid >> 5, ln = tid & 31;
    if (ln == 0) { sm_s[w] = s; sm_ss[w] = ss; }
    __syncthreads();
    s  = sm_s[0] + sm_s[1] + sm_s[2] + sm_s[3];
    ss = sm_ss[0] + sm_ss[1] + sm_ss[2] + sm_ss[3];
    float mu   = s * (1.0f / DM);
    float var  = ss * (1.0f / DM) - mu * mu;
    float rstd = rsqrtf(var + 1e-5f);

    const float4* gr = (const float4*)gamma;
    const float4* br = (const float4*)beta;
    __half* oh = out + (size_t)t * DM;
    #pragma unroll
    for (int u = 0; u < 2; u++) {
        int i = tid + u * 128;
        float4 xv = xr[i], gv = gr[i], bv = br[i];
        float rx = (xv.x - mu) * rstd * gv.x + bv.x;
        float ry = (xv.y - mu) * rstd * gv.y + bv.y;
        float rz = (xv.z - mu) * rstd * gv.z + bv.z;
        float rw = (xv.w - mu) * rstd * gv.w + bv.w;
        uint2 pk;
        pk.x = packh2(rx, ry);
        pk.y = packh2(rz, rw);
        *(uint2*)(oh + i * 4) = pk;
    }
}

// ---------------- fused weight prep: all six w[K,N] fp32 -> [N,K] fp16 --------
// grid.x = 12288 blocks of 32x8 threads, 32x32 tile each.
__global__ void wprep_kernel(const float* __restrict__ wq, const float* __restrict__ wk,
                             const float* __restrict__ wv, const float* __restrict__ wo,
                             const float* __restrict__ w1, const float* __restrict__ w2,
                             __half* __restrict__ owqkv, __half* __restrict__ owo,
                             __half* __restrict__ ow1,   __half* __restrict__ ow2)
{
    __shared__ float t[32][33];
    int bid = blockIdx.x;
    const float* src; __half* dst; int K, N, tile;
    if (bid < 1024)      { src = wq; dst = owqkv;                 K = DM;  N = DM;  tile = bid; }
    else if (bid < 2048) { src = wk; dst = owqkv + DM * DM;       K = DM;  N = DM;  tile = bid - 1024; }
    else if (bid < 3072) { src = wv; dst = owqkv + 2 * DM * DM;   K = DM;  N = DM;  tile = bid - 2048; }
    else if (bid < 4096) { src = wo; dst = owo;                   K = DM;  N = DM;  tile = bid - 3072; }
    else if (bid < 8192) { src = w1; dst = ow1;                   K = DM;  N = HID; tile = bid - 4096; }
    else                 { src = w2; dst = ow2;                   K = HID; N = DM;  tile = bid - 8192; }
    int tpr = N >> 5;
    int n0 = (tile % tpr) * 32, k0 = (tile / tpr) * 32;

    int tx = threadIdx.x, ty = threadIdx.y;
    #pragma unroll
    for (int i = 0; i < 4; i++)
        t[ty + i * 8][tx] = src[(size_t)(k0 + ty + i * 8) * N + n0 + tx];
    __syncthreads();
    #pragma unroll
    for (int i = 0; i < 4; i++)
        dst[(size_t)(n0 + ty + i * 8) * K + k0 + tx] = __float2half_rn(t[tx][ty + i * 8]);
}

// ---------------- mma.sync fp16 GEMM, 256x128 CTA tile ------------------------
#define GLDA      144
#define GA_BYTES  (256 * GLDA)             // 36864
#define GB_BYTES  (128 * GLDA)             // 18432
#define GSTAGE    (GA_BYTES + GB_BYTES)    // 55296
#define GEMM_SMEM (3 * GSTAGE)             // 165888

template<bool BIAS, bool RELU, bool RES, bool OUTH, bool QKVOUT>
__global__ void __launch_bounds__(256) tc_gemm_kernel(
    const __half* __restrict__ A, const __half* __restrict__ B,
    const float* __restrict__ bias, const float* __restrict__ Res,
    float* __restrict__ Cf, __half* __restrict__ Ch, int M, int N, int K)
{
    extern __shared__ char smem[];
    const uint32_t sb = smem_u32(smem);
    int tid = threadIdx.x;
    int wid = tid >> 5, lane = tid & 31;
    int wm = wid & 3, wn = wid >> 2;
    int m0 = blockIdx.y * 256, n0 = blockIdx.x * 128;

    float acc[4][8][4];
    #pragma unroll
    for (int i = 0; i < 4; i++)
        #pragma unroll
        for (int j = 0; j < 8; j++)
            #pragma unroll
            for (int r = 0; r < 4; r++) acc[i][j][r] = 0.f;

    int nc = K >> 6;

    auto load_chunk = [&](int c, int st) {
        int kc = c << 6;
        uint32_t base = sb + st * GSTAGE;
        #pragma unroll
        for (int i = 0; i < 12; i++) {
            int slot = tid + (i << 8);
            if (slot < 2048) {
                int r = slot >> 3, ch = slot & 7;
                cpa16(base + r * GLDA + ch * 16,
                      A + (size_t)(m0 + r) * K + kc + ch * 8);
            } else {
                int s2 = slot - 2048;
                int r = s2 >> 3, ch = s2 & 7;
                cpa16(base + GA_BYTES + r * GLDA + ch * 16,
                      B + (size_t)(n0 + r) * K + kc + ch * 8);
            }
        }
        CP_COMMIT();
    };

    load_chunk(0, 0);
    load_chunk(1, 1);
    load_chunk(2, 2);

    uint32_t aOff = (uint32_t)((wm * 64 + (lane & 15)) * GLDA + (lane >> 4) * 16);
    int bm = lane >> 3, brr = lane & 7;
    uint32_t bOff = (uint32_t)((wn * 64 + ((bm & 2) ? 8 : 0) + brr) * GLDA
                               + ((bm & 1) ? 16 : 0));

    for (int c = 0; c < nc; c++) {
        int st = c % 3;
        CP_WAIT(2);
        __syncthreads();
        uint32_t base = sb + st * GSTAGE;
        #pragma unroll
        for (int ks = 0; ks < 4; ks++) {
            uint32_t kb = ks * 32;
            uint32_t af[4][4], bf[8][2];
            #pragma unroll
            for (int mt = 0; mt < 4; mt++)
                ldm_x4(af[mt], base + aOff + mt * (16 * GLDA) + kb);
            #pragma unroll
            for (int p = 0; p < 4; p++) {
                uint32_t t4[4];
                ldm_x4(t4, base + GA_BYTES + bOff + p * (16 * GLDA) + kb);
                bf[2*p][0] = t4[0]; bf[2*p][1] = t4[1];
                bf[2*p+1][0] = t4[2]; bf[2*p+1][1] = t4[3];
            }
            #pragma unroll
            for (int mt = 0; mt < 4; mt++)
                #pragma unroll
                for (int nt = 0; nt < 8; nt++)
                    mma_f16(acc[mt][nt], af[mt], bf[nt]);
        }
        __syncthreads();
        if (c + 3 < nc) load_chunk(c + 3, st);
        else            CP_COMMIT();
    }

    int g = lane >> 2, tq = lane & 3;
    #pragma unroll
    for (int mt = 0; mt < 4; mt++) {
        int mbase = m0 + wm * 64 + mt * 16 + g;
        #pragma unroll
        for (int nt = 0; nt < 8; nt++) {
            int n = n0 + wn * 64 + nt * 8 + tq * 2;
            float2 v0 = make_float2(acc[mt][nt][0], acc[mt][nt][1]);
            float2 v1 = make_float2(acc[mt][nt][2], acc[mt][nt][3]);
            if (BIAS) {
                float2 bb = *(const float2*)(bias + n);
                v0.x += bb.x; v0.y += bb.y; v1.x += bb.x; v1.y += bb.y;
            }
            if (RELU) {
                v0.x = fmaxf(v0.x, 0.f); v0.y = fmaxf(v0.y, 0.f);
                v1.x = fmaxf(v1.x, 0.f); v1.y = fmaxf(v1.y, 0.f);
            }
            if (RES) {
                float2 q0 = *(const float2*)(Res + (size_t)mbase * N + n);
                float2 q1 = *(const float2*)(Res + (size_t)(mbase + 8) * N + n);
                v0.x += q0.x; v0.y += q0.y; v1.x += q1.x; v1.y += q1.y;
            }
            if (QKVOUT) {
                int which = n >> 10, nn = n & 1023;
                __half* dst = Ch + (size_t)which * (TOK * DM) + (size_t)mbase * DM + nn;
                *(uint32_t*)dst                    = packh2(v0.x, v0.y);
                *(uint32_t*)(dst + (size_t)8 * DM) = packh2(v1.x, v1.y);
            } else if (OUTH) {
                *(uint32_t*)(Ch + (size_t)mbase * N + n)       = packh2(v0.x, v0.y);
                *(uint32_t*)(Ch + (size_t)(mbase + 8) * N + n) = packh2(v1.x, v1.y);
            } else {
                *(float2*)(Cf + (size_t)mbase * N + n) = v0;
                *(float2*)(Cf + (size_t)(mbase + 8) * N + n) = v1;
            }
        }
    }
}

// ---------------- tensor-core flash attention (fp16, 128-query CTAs) ----------
// V loaded in natural [key][d] layout; P·V B-fragments via ldmatrix.trans.
#define ALD  144
#define ATB  (64 * ALD)
#define QTB  (128 * ALD)
#define ASTG (2 * ATB)              // K, V per stage
#define ATT_SMEM (QTB + 2 * ASTG)   // 55296

__global__ void __launch_bounds__(256) attn_tc_kernel(
    const __half* __restrict__ Q, const __half* __restrict__ K,
    const __half* __restrict__ V, __half* __restrict__ O)
{
    extern __shared__ char smc[];
    const uint32_t sb = smem_u32(smc);
    int qt = (int)gridDim.x - 1 - (int)blockIdx.x;
    int h = blockIdx.y, b = blockIdx.z;
    int tid = threadIdx.x;
    int wm = tid >> 5, lane = tid & 31;

    auto load_kv = [&](int t, int st) {
        uint32_t base = sb + QTB + st * ASTG;
        #pragma unroll
        for (int i = 0; i < 2; i++) {
            int slot = tid * 2 + i;
            int r = slot >> 3, c = slot & 7;
            size_t gk = (size_t)(b * SEQL + t * 64 + r) * DM + h * DH + c * 8;
            uint32_t so = (uint32_t)(r * ALD + c * 16);
            cpa16(base + so,       K + gk);
            cpa16(base + ATB + so, V + gk);
        }
    };

    #pragma unroll
    for (int i = 0; i < 4; i++) {
        int slot = tid * 4 + i;
        int r = slot >> 3, c = slot & 7;
        size_t gq = (size_t)(b * SEQL + qt * 128 + r) * DM + h * DH + c * 8;
        cpa16(sb + (uint32_t)(r * ALD + c * 16), Q + gq);
    }
    load_kv(0, 0);
    CP_COMMIT();

    float oacc[8][4];
    #pragma unroll
    for (int nt = 0; nt < 8; nt++)
        #pragma unroll
        for (int j = 0; j < 4; j++) oacc[nt][j] = 0.f;
    float mrow[2] = {-INFINITY, -INFINITY};
    float lrow[2] = {0.f, 0.f};

    uint32_t aOff = (uint32_t)((wm * 16 + (lane & 15)) * ALD + (lane >> 4) * 16);
    int bm = lane >> 3, brr = lane & 7;
    uint32_t bOff = (uint32_t)((((bm & 2) ? 8 : 0) + brr) * ALD + ((bm & 1) ? 16 : 0));
    uint32_t vtOff = (uint32_t)((lane & 15) * ALD + (lane >> 4) * 16);

    int ntile = 2 * qt + 2;
    for (int t = 0; t < ntile; t++) {
        int st = t & 1;
        if (t + 1 < ntile) { load_kv(t + 1, st ^ 1); CP_COMMIT(); CP_WAIT(1); }
        else               { CP_WAIT(0); }
        __syncthreads();

        uint32_t kbase = sb + QTB + st * ASTG;
        uint32_t vbase = kbase + ATB;

        // ---- scores ----
        float sacc[8][4];
        #pragma unroll
        for (int nt = 0; nt < 8; nt++)
            #pragma unroll
            for (int j = 0; j < 4; j++) sacc[nt][j] = 0.f;

        #pragma unroll
        for (int kt = 0; kt < 4; kt++) {
            uint32_t kb = kt * 32;
            uint32_t a4[4];
            ldm_x4(a4, sb + aOff + kb);
            #pragma unroll
            for (int p = 0; p < 4; p++) {
                uint32_t t4[4];
                ldm_x4(t4, kbase + bOff + p * (16 * ALD) + kb);
                uint32_t b0[2] = {t4[0], t4[1]}, b1[2] = {t4[2], t4[3]};
                mma_f16(sacc[2*p],   a4, b0);
                mma_f16(sacc[2*p+1], a4, b1);
            }
        }

        // ---- scale + causal mask ----
        int g = lane >> 2, colb = (lane & 3) * 2;
        bool diag = (t >= 2 * qt);
        #pragma unroll
        for (int nt = 0; nt < 8; nt++)
            #pragma unroll
            for (int j = 0; j < 4; j++) {
                float s = sacc[nt][j] * 0.125f;
                if (diag) {
                    int col = t * 64 + nt * 8 + colb + (j & 1);
                    int qr  = qt * 128 + wm * 16 + g + ((j >= 2) ? 8 : 0);
                    if (col > qr) s = -1e30f;
                }
                sacc[nt][j] = s;
            }

        // ---- online softmax ----
        float mt0 = -INFINITY, mt1 = -INFINITY;
        #pragma unroll
        for (int nt = 0; nt < 8; nt++) {
            mt0 = fmaxf(mt0, fmaxf(sacc[nt][0], sacc[nt][1]));
            mt1 = fmaxf(mt1, fmaxf(sacc[nt][2], sacc[nt][3]));
        }
        mt0 = fmaxf(mt0, __shfl_xor_sync(0xffffffffu, mt0, 1));
        mt0 = fmaxf(mt0, __shfl_xor_sync(0xffffffffu, mt0, 2));
        mt1 = fmaxf(mt1, __shfl_xor_sync(0xffffffffu, mt1, 1));
        mt1 = fmaxf(mt1, __shfl_xor_sync(0xffffffffu, mt1, 2));
        float mn0 = fmaxf(mrow[0], mt0), mn1 = fmaxf(mrow[1], mt1);
        float sc0 = __expf(mrow[0] - mn0), sc1 = __expf(mrow[1] - mn1);
        float lt0 = 0.f, lt1 = 0.f;
        #pragma unroll
        for (int nt = 0; nt < 8; nt++) {
            float p0 = __expf(sacc[nt][0] - mn0);
            float p1 = __expf(sacc[nt][1] - mn0);
            float p2 = __expf(sacc[nt][2] - mn1);
            float p3 = __expf(sacc[nt][3] - mn1);
            sacc[nt][0] = p0; sacc[nt][1] = p1; sacc[nt][2] = p2; sacc[nt][3] = p3;
            lt0 += p0 + p1; lt1 += p2 + p3;
        }
        lt0 += __shfl_xor_sync(0xffffffffu, lt0, 1);
        lt0 += __shfl_xor_sync(0xffffffffu, lt0, 2);
        lt1 += __shfl_xor_sync(0xffffffffu, lt1, 1);
        lt1 += __shfl_xor_sync(0xffffffffu, lt1, 2);
        lrow[0] = lrow[0] * sc0 + lt0;
        lrow[1] = lrow[1] * sc1 + lt1;
        mrow[0] = mn0; mrow[1] = mn1;
        #pragma unroll
        for (int nt = 0; nt < 8; nt++) {
            oacc[nt][0] *= sc0; oacc[nt][1] *= sc0;
            oacc[nt][2] *= sc1; oacc[nt][3] *= sc1;
        }

        // ---- O += P @ V : V natural [key][d], B-frags via ldmatrix.trans ----
        #pragma unroll
        for (int kk = 0; kk < 4; kk++) {
            uint32_t pa[4];
            pa[0] = packh2(sacc[2*kk][0],   sacc[2*kk][1]);
            pa[1] = packh2(sacc[2*kk][2],   sacc[2*kk][3]);
            pa[2] = packh2(sacc[2*kk+1][0], sacc[2*kk+1][1]);
            pa[3] = packh2(sacc[2*kk+1][2], sacc[2*kk+1][3]);
            uint32_t rowb = vbase + vtOff + kk * (16 * ALD);
            #pragma unroll
            for (int p = 0; p < 4; p++) {
                uint32_t t4[4];
                ldm_x4_t(t4, rowb + p * 32);
                uint32_t b0[2] = {t4[0], t4[1]}, b1[2] = {t4[2], t4[3]};
                mma_f16(oacc[2*p],   pa, b0);
                mma_f16(oacc[2*p+1], pa, b1);
            }
        }
        __syncthreads();
    }

    // ---- epilogue: fp16 out ----
    float inv0 = 1.0f / lrow[0], inv1 = 1.0f / lrow[1];
    int g = lane >> 2, tq = lane & 3;
    int row0 = qt * 128 + wm * 16 + g;
    #pragma unroll
    for (int nt = 0; nt < 8; nt++) {
        int d = h * DH + nt * 8 + tq * 2;
        *(uint32_t*)(O + (size_t)(b * SEQL + row0) * DM + d) =
            packh2(oacc[nt][0] * inv0, oacc[nt][1] * inv0);
        *(uint32_t*)(O + (size_t)(b * SEQL + row0 + 8) * DM + d) =
            packh2(oacc[nt][2] * inv1, oacc[nt][3] * inv1);
    }
}

// ---------------- launch ----------------
extern "C" void kernel_launch(void* const* d_in, const int* in_sizes, int n_in,
                              void* d_out, int out_size)
{
    const float* x   = (const float*)d_in[0];
    const float* wq  = (const float*)d_in[1];
    const float* wk  = (const float*)d_in[2];
    const float* wv  = (const float*)d_in[3];
    const float* wo  = (const float*)d_in[4];
    const float* w1  = (const float*)d_in[5];
    const float* b1  = (const float*)d_in[6];
    const float* w2  = (const float*)d_in[7];
    const float* b2  = (const float*)d_in[8];
    const float* g1  = (const float*)d_in[9];
    const float* be1 = (const float*)d_in[10];
    const float* g2  = (const float*)d_in[11];
    const float* be2 = (const float*)d_in[12];
    float* out = (float*)d_out;

    float* x1;
    cudaGetSymbolAddress((void**)&x1, g_x1);
    __half *xnh, *qkv16, *attn16, *hid16;
    __half *wqkv16, *wo16, *w116, *w216;
    cudaGetSymbolAddress((void**)&xnh,    g_xnh);
    cudaGetSymbolAddress((void**)&qkv16,  g_qkv16);
    cudaGetSymbolAddress((void**)&attn16, g_attn16);
    cudaGetSymbolAddress((void**)&hid16,  g_hid16);
    cudaGetSymbolAddress((void**)&wqkv16, g_wqkv16);
    cudaGetSymbolAddress((void**)&wo16,   g_wo16);
    cudaGetSymbolAddress((void**)&w116,   g_w116);
    cudaGetSymbolAddress((void**)&w216,   g_w216);
    __half* q16 = qkv16;
    __half* k16 = qkv16 + (size_t)TOK * DM;
    __half* v16 = qkv16 + 2 * (size_t)TOK * DM;

    cudaFuncSetAttribute(attn_tc_kernel, cudaFuncAttributeMaxDynamicSharedMemorySize,
                         ATT_SMEM);
    cudaFuncSetAttribute(tc_gemm_kernel<false, false, false, true, true>,
                         cudaFuncAttributeMaxDynamicSharedMemorySize, GEMM_SMEM);
    cudaFuncSetAttribute(tc_gemm_kernel<false, false, true, false, false>,
                         cudaFuncAttributeMaxDynamicSharedMemorySize, GEMM_SMEM);
    cudaFuncSetAttribute(tc_gemm_kernel<true, true, false, true, false>,
                         cudaFuncAttributeMaxDynamicSharedMemorySize, GEMM_SMEM);
    cudaFuncSetAttribute(tc_gemm_kernel<true, false, true, false, false>,
                         cudaFuncAttributeMaxDynamicSharedMemorySize, GEMM_SMEM);

    // fused weight prep (single launch)
    wprep_kernel<<<12288, dim3(32, 8)>>>(wq, wk, wv, wo, w1, w2,
                                         wqkv16, wo16, w116, w216);

    // LN1 -> fp16
    ln_kernel<<<TOK, 128>>>(x, g1, be1, xnh);

    // fused QKV projection (N=3072) -> q|k|v fp16
    tc_gemm_kernel<false, false, false, true, true>
        <<<dim3(3 * DM / 128, TOK / 256), 256, GEMM_SMEM>>>(
        xnh, wqkv16, nullptr, nullptr, nullptr, qkv16, TOK, 3 * DM, DM);

    // tensor-core attention -> fp16 (V consumed in natural layout)
    attn_tc_kernel<<<dim3(SEQL / 128, NH, NB), 256, ATT_SMEM>>>(q16, k16, v16, attn16);

    // O projection + residual(x) -> x1 (fp32)
    tc_gemm_kernel<false, false, true, false, false>
        <<<dim3(DM / 128, TOK / 256), 256, GEMM_SMEM>>>(
        attn16, wo16, nullptr, x, x1, nullptr, TOK, DM, DM);

    // LN2 -> fp16
    ln_kernel<<<TOK, 128>>>(x1, g2, be2, xnh);

    // FFN1: relu(xn @ w1 + b1) -> fp16 hid
    tc_gemm_kernel<true, true, false, true, false>
        <<<dim3(HID / 128, TOK / 256), 256, GEMM_SMEM>>>(
        xnh, w116, b1, nullptr, nullptr, hid16, TOK, HID, DM);

    // FFN2: hid @ w2 + b2 + x1 -> out (fp32)
    tc_gemm_kernel<true, false, true, false, false>
        <<<dim3(DM / 128, TOK / 256), 256, GEMM_SMEM>>>(
        hid16, w216, b2, x1, out, nullptr, TOK, DM, HID);
}

// round 9
// speedup vs baseline: 19.4701x; 1.0021x over previous
#include <cuda_runtime.h>
#include <cuda_fp16.h>
#include <math.h>
#include <stdint.h>

#define TOK   4096   // B*S tokens
#define DM    1024
#define HID   4096
#define SEQL  2048
#define NB    2
#define NH    16
#define DH    64

// ---------------- scratch (allocation-free: __device__ globals) ----------------
__device__ float g_x1[TOK * DM];                         // residual after attention
__device__ __align__(256) __half g_xnh[TOK * DM];        // LN output, fp16
__device__ __align__(256) __half g_qkv16[3 * TOK * DM];  // fused q|k|v
__device__ __align__(256) __half g_attn16[TOK * DM];
__device__ __align__(256) __half g_hid16[TOK * HID];
// weights transposed to [N,K] fp16
__device__ __align__(256) __half g_wqkv16[3 * DM * DM];  // fused wq|wk|wv rows
__device__ __align__(256) __half g_wo16[DM * DM];
__device__ __align__(256) __half g_w116[DM * HID];
__device__ __align__(256) __half g_w216[HID * DM];

// ---------------- base-target PTX helpers ----------------
__device__ __forceinline__ uint32_t smem_u32(const void* p) {
    uint32_t a;
    asm("{ .reg .u64 t; cvta.to.shared.u64 t, %1; cvt.u32.u64 %0, t; }"
        : "=r"(a) : "l"(p));
    return a;
}
__device__ __forceinline__ void cpa16(uint32_t s, const void* g) {
    asm volatile("cp.async.cg.shared.global [%0], [%1], 16;" :: "r"(s), "l"(g));
}
#define CP_COMMIT() asm volatile("cp.async.commit_group;" ::: "memory")
#define CP_WAIT(n)  asm volatile("cp.async.wait_group %0;" :: "n"(n) : "memory")

__device__ __forceinline__ void ldm_x4(uint32_t* r, uint32_t addr) {
    asm volatile("ldmatrix.sync.aligned.m8n8.x4.shared.b16 {%0,%1,%2,%3}, [%4];"
                 : "=r"(r[0]), "=r"(r[1]), "=r"(r[2]), "=r"(r[3]) : "r"(addr));
}
__device__ __forceinline__ void ldm_x4_t(uint32_t* r, uint32_t addr) {
    asm volatile("ldmatrix.sync.aligned.m8n8.x4.trans.shared.b16 {%0,%1,%2,%3}, [%4];"
                 : "=r"(r[0]), "=r"(r[1]), "=r"(r[2]), "=r"(r[3]) : "r"(addr));
}
__device__ __forceinline__ void mma_f16(float* d, const uint32_t* a, const uint32_t* b) {
    asm volatile(
        "mma.sync.aligned.m16n8k16.row.col.f32.f16.f16.f32 "
        "{%0,%1,%2,%3}, {%4,%5,%6,%7}, {%8,%9}, {%0,%1,%2,%3};"
        : "+f"(d[0]), "+f"(d[1]), "+f"(d[2]), "+f"(d[3])
        : "r"(a[0]), "r"(a[1]), "r"(a[2]), "r"(a[3]), "r"(b[0]), "r"(b[1]));
}
__device__ __forceinline__ uint32_t packh2(float lo, float hi) {
    __half2 t = __floats2half2_rn(lo, hi);
    return *(uint32_t*)&t;
}

// ---------------- LayerNorm -> fp16 ----------------
__global__ void ln_kernel(const float* __restrict__ x,
                          const float* __restrict__ gamma,
                          const float* __restrict__ beta,
                          __half* __restrict__ out)
{
    int t   = blockIdx.x;
    int tid = threadIdx.x;
    const float4* xr = (const float4*)(x + (size_t)t * DM);
    float4 v0 = xr[tid];
    float4 v1 = xr[tid + 128];
    float s  = v0.x + v0.y + v0.z + v0.w + v1.x + v1.y + v1.z + v1.w;
    float ss = v0.x*v0.x + v0.y*v0.y + v0.z*v0.z + v0.w*v0.w
             + v1.x*v1.x + v1.y*v1.y + v1.z*v1.z + v1.w*v1.w;
    #pragma unroll
    for (int o = 16; o; o >>= 1) {
        s  += __shfl_xor_sync(0xffffffffu, s,  o);
        ss += __shfl_xor_sync(0xffffffffu, ss, o);
    }
    __shared__ float sm_s[4], sm_ss[4];
    int w = tid >> 5, ln = tid & 31;
    if (ln == 0) { sm_s[w] = s; sm_ss[w] = ss; }
    __syncthreads();
    s  = sm_s[0] + sm_s[1] + sm_s[2] + sm_s[3];
    ss = sm_ss[0] + sm_ss[1] + sm_ss[2] + sm_ss[3];
    float mu   = s * (1.0f / DM);
    float var  = ss * (1.0f / DM) - mu * mu;
    float rstd = rsqrtf(var + 1e-5f);

    const float4* gr = (const float4*)gamma;
    const float4* br = (const float4*)beta;
    __half* oh = out + (size_t)t * DM;
    #pragma unroll
    for (int u = 0; u < 2; u++) {
        int i = tid + u * 128;
        float4 xv = xr[i], gv = gr[i], bv = br[i];
        float rx = (xv.x - mu) * rstd * gv.x + bv.x;
        float ry = (xv.y - mu) * rstd * gv.y + bv.y;
        float rz = (xv.z - mu) * rstd * gv.z + bv.z;
        float rw = (xv.w - mu) * rstd * gv.w + bv.w;
        uint2 pk;
        pk.x = packh2(rx, ry);
        pk.y = packh2(rz, rw);
        *(uint2*)(oh + i * 4) = pk;
    }
}

// ---------------- fused weight prep: all six w[K,N] fp32 -> [N,K] fp16 --------
__global__ void wprep_kernel(const float* __restrict__ wq, const float* __restrict__ wk,
                             const float* __restrict__ wv, const float* __restrict__ wo,
                             const float* __restrict__ w1, const float* __restrict__ w2,
                             __half* __restrict__ owqkv, __half* __restrict__ owo,
                             __half* __restrict__ ow1,   __half* __restrict__ ow2)
{
    __shared__ float t[32][33];
    int bid = blockIdx.x;
    const float* src; __half* dst; int K, N, tile;
    if (bid < 1024)      { src = wq; dst = owqkv;                 K = DM;  N = DM;  tile = bid; }
    else if (bid < 2048) { src = wk; dst = owqkv + DM * DM;       K = DM;  N = DM;  tile = bid - 1024; }
    else if (bid < 3072) { src = wv; dst = owqkv + 2 * DM * DM;   K = DM;  N = DM;  tile = bid - 2048; }
    else if (bid < 4096) { src = wo; dst = owo;                   K = DM;  N = DM;  tile = bid - 3072; }
    else if (bid < 8192) { src = w1; dst = ow1;                   K = DM;  N = HID; tile = bid - 4096; }
    else                 { src = w2; dst = ow2;                   K = HID; N = DM;  tile = bid - 8192; }
    int tpr = N >> 5;
    int n0 = (tile % tpr) * 32, k0 = (tile / tpr) * 32;

    int tx = threadIdx.x, ty = threadIdx.y;
    #pragma unroll
    for (int i = 0; i < 4; i++)
        t[ty + i * 8][tx] = src[(size_t)(k0 + ty + i * 8) * N + n0 + tx];
    __syncthreads();
    #pragma unroll
    for (int i = 0; i < 4; i++)
        dst[(size_t)(n0 + ty + i * 8) * K + k0 + tx] = __float2half_rn(t[tx][ty + i * 8]);
}

// ---------------- mma.sync fp16 GEMM, 256x128 CTA tile, 4-stage ring ----------
#define GLDA      144
#define GA_BYTES  (256 * GLDA)             // 36864
#define GB_BYTES  (128 * GLDA)             // 18432
#define GSTAGE    (GA_BYTES + GB_BYTES)    // 55296
#define GEMM_SMEM (4 * GSTAGE)             // 221184

template<bool BIAS, bool RELU, bool RES, bool OUTH, bool QKVOUT>
__global__ void __launch_bounds__(256) tc_gemm_kernel(
    const __half* __restrict__ A, const __half* __restrict__ B,
    const float* __restrict__ bias, const float* __restrict__ Res,
    float* __restrict__ Cf, __half* __restrict__ Ch, int M, int N, int K)
{
    extern __shared__ char smem[];
    const uint32_t sb = smem_u32(smem);
    int tid = threadIdx.x;
    int wid = tid >> 5, lane = tid & 31;
    int wm = wid & 3, wn = wid >> 2;
    int m0 = blockIdx.y * 256, n0 = blockIdx.x * 128;

    float acc[4][8][4];
    #pragma unroll
    for (int i = 0; i < 4; i++)
        #pragma unroll
        for (int j = 0; j < 8; j++)
            #pragma unroll
            for (int r = 0; r < 4; r++) acc[i][j][r] = 0.f;

    int nc = K >> 6;

    auto load_chunk = [&](int c, int st) {
        int kc = c << 6;
        uint32_t base = sb + st * GSTAGE;
        #pragma unroll
        for (int i = 0; i < 12; i++) {
            int slot = tid + (i << 8);
            if (slot < 2048) {
                int r = slot >> 3, ch = slot & 7;
                cpa16(base + r * GLDA + ch * 16,
                      A + (size_t)(m0 + r) * K + kc + ch * 8);
            } else {
                int s2 = slot - 2048;
                int r = s2 >> 3, ch = s2 & 7;
                cpa16(base + GA_BYTES + r * GLDA + ch * 16,
                      B + (size_t)(n0 + r) * K + kc + ch * 8);
            }
        }
        CP_COMMIT();
    };

    load_chunk(0, 0);
    load_chunk(1, 1);
    load_chunk(2, 2);

    uint32_t aOff = (uint32_t)((wm * 64 + (lane & 15)) * GLDA + (lane >> 4) * 16);
    int bm = lane >> 3, brr = lane & 7;
    uint32_t bOff = (uint32_t)((wn * 64 + ((bm & 2) ? 8 : 0) + brr) * GLDA
                               + ((bm & 1) ? 16 : 0));

    for (int c = 0; c < nc; c++) {
        int st = c & 3;
        CP_WAIT(2);
        __syncthreads();
        // prefetch AFTER the barrier: stage (c+3)&3 == (c-1)&3, consumed by every
        // warp before it passed this barrier -> single sync per chunk is safe.
        if (c + 3 < nc) load_chunk(c + 3, (c + 3) & 3);
        else            CP_COMMIT();           // keep group counting aligned
        uint32_t base = sb + st * GSTAGE;
        #pragma unroll
        for (int ks = 0; ks < 4; ks++) {
            uint32_t kb = ks * 32;
            uint32_t af[4][4], bf[8][2];
            #pragma unroll
            for (int mt = 0; mt < 4; mt++)
                ldm_x4(af[mt], base + aOff + mt * (16 * GLDA) + kb);
            #pragma unroll
            for (int p = 0; p < 4; p++) {
                uint32_t t4[4];
                ldm_x4(t4, base + GA_BYTES + bOff + p * (16 * GLDA) + kb);
                bf[2*p][0] = t4[0]; bf[2*p][1] = t4[1];
                bf[2*p+1][0] = t4[2]; bf[2*p+1][1] = t4[3];
            }
            #pragma unroll
            for (int mt = 0; mt < 4; mt++)
                #pragma unroll
                for (int nt = 0; nt < 8; nt++)
                    mma_f16(acc[mt][nt], af[mt], bf[nt]);
        }
    }

    int g = lane >> 2, tq = lane & 3;
    #pragma unroll
    for (int mt = 0; mt < 4; mt++) {
        int mbase = m0 + wm * 64 + mt * 16 + g;
        #pragma unroll
        for (int nt = 0; nt < 8; nt++) {
            int n = n0 + wn * 64 + nt * 8 + tq * 2;
            float2 v0 = make_float2(acc[mt][nt][0], acc[mt][nt][1]);
            float2 v1 = make_float2(acc[mt][nt][2], acc[mt][nt][3]);
            if (BIAS) {
                float2 bb = *(const float2*)(bias + n);
                v0.x += bb.x; v0.y += bb.y; v1.x += bb.x; v1.y += bb.y;
            }
            if (RELU) {
                v0.x = fmaxf(v0.x, 0.f); v0.y = fmaxf(v0.y, 0.f);
                v1.x = fmaxf(v1.x, 0.f); v1.y = fmaxf(v1.y, 0.f);
            }
            if (RES) {
                float2 q0 = *(const float2*)(Res + (size_t)mbase * N + n);
                float2 q1 = *(const float2*)(Res + (size_t)(mbase + 8) * N + n);
                v0.x += q0.x; v0.y += q0.y; v1.x += q1.x; v1.y += q1.y;
            }
            if (QKVOUT) {
                int which = n >> 10, nn = n & 1023;
                __half* dst = Ch + (size_t)which * (TOK * DM) + (size_t)mbase * DM + nn;
                *(uint32_t*)dst                    = packh2(v0.x, v0.y);
                *(uint32_t*)(dst + (size_t)8 * DM) = packh2(v1.x, v1.y);
            } else if (OUTH) {
                *(uint32_t*)(Ch + (size_t)mbase * N + n)       = packh2(v0.x, v0.y);
                *(uint32_t*)(Ch + (size_t)(mbase + 8) * N + n) = packh2(v1.x, v1.y);
            } else {
                *(float2*)(Cf + (size_t)mbase * N + n) = v0;
                *(float2*)(Cf + (size_t)(mbase + 8) * N + n) = v1;
            }
        }
    }
}

// ---------------- tensor-core flash attention (fp16, base-2 softmax) ----------
// 128 queries x (head, batch), 256 threads; 3 KV stages, ONE sync per tile.
#define ALD  144
#define ATB  (64 * ALD)
#define QTB  (128 * ALD)
#define ASTG (2 * ATB)              // K, V per stage
#define ATT_SMEM (QTB + 3 * ASTG)   // 73728

#define SC_LOG2E 0.1803368801111f   // 0.125 * log2(e)

__global__ void __launch_bounds__(256) attn_tc_kernel(
    const __half* __restrict__ Q, const __half* __restrict__ K,
    const __half* __restrict__ V, __half* __restrict__ O)
{
    extern __shared__ char smc[];
    const uint32_t sb = smem_u32(smc);
    int qt = (int)gridDim.x - 1 - (int)blockIdx.x;
    int h = blockIdx.y, b = blockIdx.z;
    int tid = threadIdx.x;
    int wm = tid >> 5, lane = tid & 31;

    auto load_kv = [&](int t, int st) {
        uint32_t base = sb + QTB + st * ASTG;
        #pragma unroll
        for (int i = 0; i < 2; i++) {
            int slot = tid * 2 + i;
            int r = slot >> 3, c = slot & 7;
            size_t gk = (size_t)(b * SEQL + t * 64 + r) * DM + h * DH + c * 8;
            uint32_t so = (uint32_t)(r * ALD + c * 16);
            cpa16(base + so,       K + gk);
            cpa16(base + ATB + so, V + gk);
        }
    };

    #pragma unroll
    for (int i = 0; i < 4; i++) {
        int slot = tid * 4 + i;
        int r = slot >> 3, c = slot & 7;
        size_t gq = (size_t)(b * SEQL + qt * 128 + r) * DM + h * DH + c * 8;
        cpa16(sb + (uint32_t)(r * ALD + c * 16), Q + gq);
    }
    load_kv(0, 0);
    CP_COMMIT();
    load_kv(1, 1);
    CP_COMMIT();

    float oacc[8][4];
    #pragma unroll
    for (int nt = 0; nt < 8; nt++)
        #pragma unroll
        for (int j = 0; j < 4; j++) oacc[nt][j] = 0.f;
    float mrow[2] = {-INFINITY, -INFINITY};
    float lrow[2] = {0.f, 0.f};

    uint32_t aOff = (uint32_t)((wm * 16 + (lane & 15)) * ALD + (lane >> 4) * 16);
    int bm = lane >> 3, brr = lane & 7;
    uint32_t bOff = (uint32_t)((((bm & 2) ? 8 : 0) + brr) * ALD + ((bm & 1) ? 16 : 0));
    uint32_t vtOff = (uint32_t)((lane & 15) * ALD + (lane >> 4) * 16);

    int ntile = 2 * qt + 2;
    for (int t = 0; t < ntile; t++) {
        int st = t % 3;
        CP_WAIT(1);
        __syncthreads();
        // prefetch after barrier: stage (t+2)%3 == (t-1)%3 already consumed.
        if (t + 2 < ntile) { load_kv(t + 2, (t + 2) % 3); CP_COMMIT(); }
        else               { CP_COMMIT(); }

        uint32_t kbase = sb + QTB + st * ASTG;
        uint32_t vbase = kbase + ATB;

        // ---- scores ----
        float sacc[8][4];
        #pragma unroll
        for (int nt = 0; nt < 8; nt++)
            #pragma unroll
            for (int j = 0; j < 4; j++) sacc[nt][j] = 0.f;

        #pragma unroll
        for (int kt = 0; kt < 4; kt++) {
            uint32_t kb = kt * 32;
            uint32_t a4[4];
            ldm_x4(a4, sb + aOff + kb);
            #pragma unroll
            for (int p = 0; p < 4; p++) {
                uint32_t t4[4];
                ldm_x4(t4, kbase + bOff + p * (16 * ALD) + kb);
                uint32_t b0[2] = {t4[0], t4[1]}, b1[2] = {t4[2], t4[3]};
                mma_f16(sacc[2*p],   a4, b0);
                mma_f16(sacc[2*p+1], a4, b1);
            }
        }

        // ---- base-2 scale + causal mask ----
        int g = lane >> 2, colb = (lane & 3) * 2;
        bool diag = (t >= 2 * qt);
        #pragma unroll
        for (int nt = 0; nt < 8; nt++)
            #pragma unroll
            for (int j = 0; j < 4; j++) {
                float s = sacc[nt][j] * SC_LOG2E;
                if (diag) {
                    int col = t * 64 + nt * 8 + colb + (j & 1);
                    int qr  = qt * 128 + wm * 16 + g + ((j >= 2) ? 8 : 0);
                    if (col > qr) s = -1e30f;
                }
                sacc[nt][j] = s;
            }

        // ---- online softmax (base 2) ----
        float mt0 = -INFINITY, mt1 = -INFINITY;
        #pragma unroll
        for (int nt = 0; nt < 8; nt++) {
            mt0 = fmaxf(mt0, fmaxf(sacc[nt][0], sacc[nt][1]));
            mt1 = fmaxf(mt1, fmaxf(sacc[nt][2], sacc[nt][3]));
        }
        mt0 = fmaxf(mt0, __shfl_xor_sync(0xffffffffu, mt0, 1));
        mt0 = fmaxf(mt0, __shfl_xor_sync(0xffffffffu, mt0, 2));
        mt1 = fmaxf(mt1, __shfl_xor_sync(0xffffffffu, mt1, 1));
        mt1 = fmaxf(mt1, __shfl_xor_sync(0xffffffffu, mt1, 2));
        float mn0 = fmaxf(mrow[0], mt0), mn1 = fmaxf(mrow[1], mt1);
        float sc0 = exp2f(mrow[0] - mn0), sc1 = exp2f(mrow[1] - mn1);
        float lt0 = 0.f, lt1 = 0.f;
        #pragma unroll
        for (int nt = 0; nt < 8; nt++) {
            float p0 = exp2f(sacc[nt][0] - mn0);
            float p1 = exp2f(sacc[nt][1] - mn0);
            float p2 = exp2f(sacc[nt][2] - mn1);
            float p3 = exp2f(sacc[nt][3] - mn1);
            sacc[nt][0] = p0; sacc[nt][1] = p1; sacc[nt][2] = p2; sacc[nt][3] = p3;
            lt0 += p0 + p1; lt1 += p2 + p3;
        }
        lt0 += __shfl_xor_sync(0xffffffffu, lt0, 1);
        lt0 += __shfl_xor_sync(0xffffffffu, lt0, 2);
        lt1 += __shfl_xor_sync(0xffffffffu, lt1, 1);
        lt1 += __shfl_xor_sync(0xffffffffu, lt1, 2);
        lrow[0] = lrow[0] * sc0 + lt0;
        lrow[1] = lrow[1] * sc1 + lt1;
        mrow[0] = mn0; mrow[1] = mn1;
        #pragma unroll
        for (int nt = 0; nt < 8; nt++) {
            oacc[nt][0] *= sc0; oacc[nt][1] *= sc0;
            oacc[nt][2] *= sc1; oacc[nt][3] *= sc1;
        }

        // ---- O += P @ V : V natural [key][d], B-frags via ldmatrix.trans ----
        #pragma unroll
        for (int kk = 0; kk < 4; kk++) {
            uint32_t pa[4];
            pa[0] = packh2(sacc[2*kk][0],   sacc[2*kk][1]);
            pa[1] = packh2(sacc[2*kk][2],   sacc[2*kk][3]);
            pa[2] = packh2(sacc[2*kk+1][0], sacc[2*kk+1][1]);
            pa[3] = packh2(sacc[2*kk+1][2], sacc[2*kk+1][3]);
            uint32_t rowb = vbase + vtOff + kk * (16 * ALD);
            #pragma unroll
            for (int p = 0; p < 4; p++) {
                uint32_t t4[4];
                ldm_x4_t(t4, rowb + p * 32);
                uint32_t b0[2] = {t4[0], t4[1]}, b1[2] = {t4[2], t4[3]};
                mma_f16(oacc[2*p],   pa, b0);
                mma_f16(oacc[2*p+1], pa, b1);
            }
        }
        // no tail sync: next iteration's barrier orders stage reuse
    }

    // ---- epilogue: fp16 out ----
    float inv0 = 1.0f / lrow[0], inv1 = 1.0f / lrow[1];
    int g = lane >> 2, tq = lane & 3;
    int row0 = qt * 128 + wm * 16 + g;
    #pragma unroll
    for (int nt = 0; nt < 8; nt++) {
        int d = h * DH + nt * 8 + tq * 2;
        *(uint32_t*)(O + (size_t)(b * SEQL + row0) * DM + d) =
            packh2(oacc[nt][0] * inv0, oacc[nt][1] * inv0);
        *(uint32_t*)(O + (size_t)(b * SEQL + row0 + 8) * DM + d) =
            packh2(oacc[nt][2] * inv1, oacc[nt][3] * inv1);
    }
}

// ---------------- launch ----------------
extern "C" void kernel_launch(void* const* d_in, const int* in_sizes, int n_in,
                              void* d_out, int out_size)
{
    const float* x   = (const float*)d_in[0];
    const float* wq  = (const float*)d_in[1];
    const float* wk  = (const float*)d_in[2];
    const float* wv  = (const float*)d_in[3];
    const float* wo  = (const float*)d_in[4];
    const float* w1  = (const float*)d_in[5];
    const float* b1  = (const float*)d_in[6];
    const float* w2  = (const float*)d_in[7];
    const float* b2  = (const float*)d_in[8];
    const float* g1  = (const float*)d_in[9];
    const float* be1 = (const float*)d_in[10];
    const float* g2  = (const float*)d_in[11];
    const float* be2 = (const float*)d_in[12];
    float* out = (float*)d_out;

    float* x1;
    cudaGetSymbolAddress((void**)&x1, g_x1);
    __half *xnh, *qkv16, *attn16, *hid16;
    __half *wqkv16, *wo16, *w116, *w216;
    cudaGetSymbolAddress((void**)&xnh,    g_xnh);
    cudaGetSymbolAddress((void**)&qkv16,  g_qkv16);
    cudaGetSymbolAddress((void**)&attn16, g_attn16);
    cudaGetSymbolAddress((void**)&hid16,  g_hid16);
    cudaGetSymbolAddress((void**)&wqkv16, g_wqkv16);
    cudaGetSymbolAddress((void**)&wo16,   g_wo16);
    cudaGetSymbolAddress((void**)&w116,   g_w116);
    cudaGetSymbolAddress((void**)&w216,   g_w216);
    __half* q16 = qkv16;
    __half* k16 = qkv16 + (size_t)TOK * DM;
    __half* v16 = qkv16 + 2 * (size_t)TOK * DM;

    cudaFuncSetAttribute(attn_tc_kernel, cudaFuncAttributeMaxDynamicSharedMemorySize,
                         ATT_SMEM);
    cudaFuncSetAttribute(tc_gemm_kernel<false, false, false, true, true>,
                         cudaFuncAttributeMaxDynamicSharedMemorySize, GEMM_SMEM);
    cudaFuncSetAttribute(tc_gemm_kernel<false, false, true, false, false>,
                         cudaFuncAttributeMaxDynamicSharedMemorySize, GEMM_SMEM);
    cudaFuncSetAttribute(tc_gemm_kernel<true, true, false, true, false>,
                         cudaFuncAttributeMaxDynamicSharedMemorySize, GEMM_SMEM);
    cudaFuncSetAttribute(tc_gemm_kernel<true, false, true, false, false>,
                         cudaFuncAttributeMaxDynamicSharedMemorySize, GEMM_SMEM);

    // fused weight prep (single launch)
    wprep_kernel<<<12288, dim3(32, 8)>>>(wq, wk, wv, wo, w1, w2,
                                         wqkv16, wo16, w116, w216);

    // LN1 -> fp16
    ln_kernel<<<TOK, 128>>>(x, g1, be1, xnh);

    // fused QKV projection (N=3072) -> q|k|v fp16
    tc_gemm_kernel<false, false, false, true, true>
        <<<dim3(3 * DM / 128, TOK / 256), 256, GEMM_SMEM>>>(
        xnh, wqkv16, nullptr, nullptr, nullptr, qkv16, TOK, 3 * DM, DM);

    // tensor-core attention -> fp16 (V consumed in natural layout)
    attn_tc_kernel<<<dim3(SEQL / 128, NH, NB), 256, ATT_SMEM>>>(q16, k16, v16, attn16);

    // O projection + residual(x) -> x1 (fp32)
    tc_gemm_kernel<false, false, true, false, false>
        <<<dim3(DM / 128, TOK / 256), 256, GEMM_SMEM>>>(
        attn16, wo16, nullptr, x, x1, nullptr, TOK, DM, DM);

    // LN2 -> fp16
    ln_kernel<<<TOK, 128>>>(x1, g2, be2, xnh);

    // FFN1: relu(xn @ w1 + b1) -> fp16 hid
    tc_gemm_kernel<true, true, false, true, false>
        <<<dim3(HID / 128, TOK / 256), 256, GEMM_SMEM>>>(
        xnh, w116, b1, nullptr, nullptr, hid16, TOK, HID, DM);

    // FFN2: hid @ w2 + b2 + x1 -> out (fp32)
    tc_gemm_kernel<true, false, true, false, false>
        <<<dim3(DM / 128, TOK / 256), 256, GEMM_SMEM>>>(
        hid16, w216, b2, x1, out, nullptr, TOK, DM, HID);
}